// round 1
// baseline (speedup 1.0000x reference)
#include <cuda_runtime.h>
#include <math.h>

// Problem constants (fixed shapes per reference setup_inputs)
#define T_LEN  2048
#define BSZ    2
#define E_DIM  1024
#define H_NUM  16
#define D_DIM  64
#define PLEN   32
#define BH     32          // BSZ*H_NUM
#define CHUNK  128
#define NCH    (T_LEN/CHUNK)   // 16
#define SCALING 0.125f         // D^-0.5
#define BETA    0.6931471805599453f  // ln 2

// ------------------------- scratch (no cudaMalloc allowed) -----------------
__device__ float g_pq   [BH*PLEN*D_DIM];       // (BH, plen, D)  scaled
__device__ float g_q    [BH*T_LEN*D_DIM];      // (BH, T, D)     scaled
__device__ float g_kp   [BH*T_LEN*D_DIM];      // (BH, T, D)
__device__ float g_kv   [BH*T_LEN*D_DIM];      // (BH, T, D)
__device__ float g_pattn[BH*T_LEN*PLEN];       // (BH, T, plen)
__device__ float g_attw [BH*T_LEN*PLEN];       // (BH, T, plen)
__device__ float g_S    [BH*NCH*D_DIM*PLEN];   // chunk states (exclusive prefix)
__device__ float g_attn [T_LEN*BSZ*E_DIM];     // pre-output-proj, (T,B,E) layout

// ------------------------- generic SGEMM: C = (A @ W^T + bias) * scale -----
// A: MxK row-major, W: NxK row-major (torch Linear weight), N == 1024.
// mode 0: C[m*N+n]   (plain row-major)
// mode 1: m=(t,b) interleaved rows of (T,B,E); n=(h,d);
//         C[((b*16+h)*Trows + t)*64 + d]
__global__ __launch_bounds__(256)
void sgemm_wt(const float* __restrict__ A, const float* __restrict__ W,
              const float* __restrict__ bias, float* __restrict__ C,
              int M, int K, float scale, int mode, int Trows)
{
    const int N = E_DIM;
    __shared__ float As[8][128];
    __shared__ float Bs[8][128];

    const int bm = blockIdx.y * 128;
    const int bn = blockIdx.x * 128;
    const int tid = threadIdx.x;
    const int tx = tid & 15;          // 0..15  (n)
    const int ty = tid >> 4;          // 0..15  (m)

    const int lrow  = tid >> 1;       // 0..127
    const int lcol4 = (tid & 1) * 4;  // 0 or 4

    float acc[8][8];
#pragma unroll
    for (int i = 0; i < 8; i++)
#pragma unroll
        for (int j = 0; j < 8; j++) acc[i][j] = 0.f;

    for (int k0 = 0; k0 < K; k0 += 8) {
        // load A tile (guard rows >= M)
        float4 av = make_float4(0.f, 0.f, 0.f, 0.f);
        if (bm + lrow < M)
            av = *(const float4*)&A[(size_t)(bm + lrow) * K + k0 + lcol4];
        As[lcol4 + 0][lrow] = av.x;
        As[lcol4 + 1][lrow] = av.y;
        As[lcol4 + 2][lrow] = av.z;
        As[lcol4 + 3][lrow] = av.w;
        // load W tile (N=1024 always covered)
        float4 bv = *(const float4*)&W[(size_t)(bn + lrow) * K + k0 + lcol4];
        Bs[lcol4 + 0][lrow] = bv.x;
        Bs[lcol4 + 1][lrow] = bv.y;
        Bs[lcol4 + 2][lrow] = bv.z;
        Bs[lcol4 + 3][lrow] = bv.w;
        __syncthreads();

#pragma unroll
        for (int kk = 0; kk < 8; kk++) {
            float a[8], b[8];
#pragma unroll
            for (int i = 0; i < 8; i++) a[i] = As[kk][ty * 8 + i];
#pragma unroll
            for (int j = 0; j < 8; j++) b[j] = Bs[kk][tx * 8 + j];
#pragma unroll
            for (int i = 0; i < 8; i++)
#pragma unroll
                for (int j = 0; j < 8; j++) acc[i][j] += a[i] * b[j];
        }
        __syncthreads();
    }

#pragma unroll
    for (int i = 0; i < 8; i++) {
        int m = bm + ty * 8 + i;
        if (m >= M) continue;
#pragma unroll
        for (int j = 0; j < 8; j++) {
            int n = bn + tx * 8 + j;
            float v = (acc[i][j] + bias[n]) * scale;
            if (mode == 0) {
                C[(size_t)m * N + n] = v;
            } else {
                int t = m >> 1, b = m & 1;
                int h = n >> 6, d = n & 63;
                C[(size_t)((b * 16 + h) * Trows + t) * 64 + d] = v;
            }
        }
    }
}

// ------------------------- pattn = softplus(beta * kp@pq^T)/beta -----------
__global__ __launch_bounds__(256)
void pattn_kernel()
{
    const int bh = blockIdx.y;
    const int t0 = blockIdx.x * 64;
    __shared__ float pqs[PLEN][D_DIM + 1];
    __shared__ float kps[64][D_DIM + 1];

    for (int i = threadIdx.x; i < PLEN * D_DIM; i += 256)
        pqs[i / D_DIM][i % D_DIM] = g_pq[(size_t)bh * PLEN * D_DIM + i];
    for (int i = threadIdx.x; i < 64 * D_DIM; i += 256) {
        int tt = i / D_DIM, d = i % D_DIM;
        kps[tt][d] = g_kp[((size_t)bh * T_LEN + t0 + tt) * D_DIM + d];
    }
    __syncthreads();

    const int t  = threadIdx.x >> 2;
    const int p0 = (threadIdx.x & 3) * 8;
#pragma unroll
    for (int pp = 0; pp < 8; pp++) {
        int p = p0 + pp;
        float acc = 0.f;
#pragma unroll
        for (int d = 0; d < 64; d++) acc += kps[t][d] * pqs[p][d];
        float z  = BETA * acc;
        float sp = fmaxf(z, 0.f) + log1pf(expf(-fabsf(z)));
        g_pattn[((size_t)bh * T_LEN + t0 + t) * PLEN + p] = sp * (1.0f / BETA);
    }
}

// ------------------- chunk-local state: L = KV^T @ P (64x32) ---------------
__global__ __launch_bounds__(256)
void local_sums()
{
    const int c = blockIdx.x, bh = blockIdx.y;
    extern __shared__ float sm[];
    float* kvs = sm;               // [128][64]
    float* ps  = sm + 128 * 64;    // [128][32]
    const size_t base = (size_t)bh * T_LEN + c * CHUNK;

    for (int i = threadIdx.x; i < 128 * 64; i += 256) kvs[i] = g_kv[base * 64 + i];
    for (int i = threadIdx.x; i < 128 * 32; i += 256) ps[i]  = g_pattn[base * 32 + i];
    __syncthreads();

    const int d  = threadIdx.x >> 2;
    const int j0 = (threadIdx.x & 3) * 8;
    float acc[8] = {0.f};
    for (int s = 0; s < 128; s++) {
        float a = kvs[s * 64 + d];
#pragma unroll
        for (int jj = 0; jj < 8; jj++) acc[jj] += a * ps[s * 32 + j0 + jj];
    }
    float* out = &g_S[((size_t)bh * NCH + c) * (64 * 32)];
#pragma unroll
    for (int jj = 0; jj < 8; jj++) out[d * 32 + j0 + jj] = acc[jj];
}

// ------------------- exclusive prefix scan over chunks ---------------------
__global__ void scan_states()
{
    const int bh = blockIdx.x;
    for (int r = 0; r < 4; r++) {
        int e = threadIdx.x + r * 512;
        float run = 0.f;
        for (int c = 0; c < NCH; c++) {
            float* p = &g_S[(((size_t)bh * NCH) + c) * 2048 + e];
            float v = *p;
            *p = run;
            run += v;
        }
    }
}

// ------------------- pass1: attn_weights = q@cumsum(kv⊗p)/(t+1) -----------
__global__ __launch_bounds__(256)
void pass1_kernel()
{
    const int c = blockIdx.x, bh = blockIdx.y;
    extern __shared__ float sm[];
    float* qs  = sm;                        // [128][65]
    float* kvs = qs + 128 * 65;             // [128][64]
    float* ps  = kvs + 128 * 64;            // [128][32]
    float* ss  = ps + 128 * 32;             // [64][32]
    const size_t base = (size_t)bh * T_LEN + c * CHUNK;

    for (int i = threadIdx.x; i < 128 * 64; i += 256) {
        int s = i >> 6, d = i & 63;
        float qv  = g_q[(base + s) * 64 + d];
        qs[s * 65 + d] = qv;
        kvs[i] = g_kv[(base + s) * 64 + d];
    }
    for (int i = threadIdx.x; i < 128 * 32; i += 256) ps[i] = g_pattn[base * 32 + i];
    for (int i = threadIdx.x; i < 64 * 32; i += 256)
        ss[i] = g_S[((size_t)bh * NCH + c) * 2048 + i];
    __syncthreads();

    const int t  = threadIdx.x >> 1;
    const int j0 = (threadIdx.x & 1) * 16;

    float qreg[64];
#pragma unroll
    for (int d = 0; d < 64; d++) qreg[d] = qs[t * 65 + d];

    float r[16] = {0.f};
    // inter-chunk: q[t] @ S_prefix
#pragma unroll 8
    for (int d = 0; d < 64; d++) {
        float a = qreg[d];
#pragma unroll
        for (int jj = 0; jj < 16; jj++) r[jj] += a * ss[d * 32 + j0 + jj];
    }
    // intra-chunk causal
    const int smax = t | 15;   // uniform within warp
    for (int s = 0; s <= smax; s++) {
        float a = 0.f;
#pragma unroll 16
        for (int d = 0; d < 64; d++) a += qreg[d] * kvs[s * 64 + d];
        if (s <= t) {
#pragma unroll
            for (int jj = 0; jj < 16; jj++) r[jj] += a * ps[s * 32 + j0 + jj];
        }
    }
    const int tg = c * CHUNK + t;
    const float inv = 1.0f / (float)(tg + 1);
#pragma unroll
    for (int jj = 0; jj < 16; jj++)
        g_attw[((size_t)bh * T_LEN + tg) * 32 + j0 + jj] = r[jj] * inv;
}

// ------------------- softmax over plen=32 ----------------------------------
__global__ __launch_bounds__(256)
void softmax32()
{
    const int row  = blockIdx.x * 8 + (threadIdx.x >> 5);
    const int lane = threadIdx.x & 31;
    float v = g_attw[(size_t)row * 32 + lane];
    float m = v;
#pragma unroll
    for (int o = 16; o; o >>= 1) m = fmaxf(m, __shfl_xor_sync(0xffffffffu, m, o));
    float e = expf(v - m);
    float s = e;
#pragma unroll
    for (int o = 16; o; o >>= 1) s += __shfl_xor_sync(0xffffffffu, s, o);
    g_attw[(size_t)row * 32 + lane] = e / s;
}

// ------------------- pass2: attn = w@cumsum(p⊗kv)/(t+1) -> (T,B,E) --------
// state for pass2 is the TRANSPOSE of pass1's state (same cumsum), reuse g_S.
__global__ __launch_bounds__(256)
void pass2_kernel()
{
    const int c = blockIdx.x, bh = blockIdx.y;
    extern __shared__ float sm[];
    float* ws  = sm;                        // [128][33]
    float* ps  = ws + 128 * 33;             // [128][33]
    float* kvs = ps + 128 * 33;             // [128][64]
    float* ss2 = kvs + 128 * 64;            // [32][65]  (transposed state)
    const size_t base = (size_t)bh * T_LEN + c * CHUNK;

    for (int i = threadIdx.x; i < 128 * 32; i += 256) {
        int s = i >> 5, j = i & 31;
        ws[s * 33 + j] = g_attw [base * 32 + i];
        ps[s * 33 + j] = g_pattn[base * 32 + i];
    }
    for (int i = threadIdx.x; i < 128 * 64; i += 256) kvs[i] = g_kv[base * 64 + i];
    for (int i = threadIdx.x; i < 64 * 32; i += 256) {
        int d = i >> 5, j = i & 31;
        ss2[j * 65 + d] = g_S[((size_t)bh * NCH + c) * 2048 + i];
    }
    __syncthreads();

    const int t  = threadIdx.x >> 1;
    const int d0 = (threadIdx.x & 1) * 32;

    float wreg[32];
#pragma unroll
    for (int j = 0; j < 32; j++) wreg[j] = ws[t * 33 + j];

    float r[32] = {0.f};
    // inter-chunk: w[t] @ S2_prefix  (S2 = S^T)
#pragma unroll 8
    for (int j = 0; j < 32; j++) {
        float a = wreg[j];
#pragma unroll
        for (int dd = 0; dd < 32; dd++) r[dd] += a * ss2[j * 65 + d0 + dd];
    }
    // intra-chunk causal
    const int smax = t | 15;
    for (int s = 0; s <= smax; s++) {
        float a = 0.f;
#pragma unroll
        for (int j = 0; j < 32; j++) a += wreg[j] * ps[s * 33 + j];
        if (s <= t) {
#pragma unroll
            for (int dd = 0; dd < 32; dd++) r[dd] += a * kvs[s * 64 + d0 + dd];
        }
    }
    const int tg  = c * CHUNK + t;
    const float inv = 1.0f / (float)(tg + 1);
    const int b = bh >> 4, h = bh & 15;
    float* out = &g_attn[((size_t)tg * 2 + b) * 1024 + h * 64 + d0];
#pragma unroll
    for (int dd = 0; dd < 32; dd++) out[dd] = r[dd] * inv;
}

// ---------------------------------------------------------------------------
extern "C" void kernel_launch(void* const* d_in, const int* in_sizes, int n_in,
                              void* d_out, int out_size)
{
    const float* query  = (const float*)d_in[0];
    const float* pquery = (const float*)d_in[1];
    const float* Wpq = (const float*)d_in[2];
    const float* bpq = (const float*)d_in[3];
    const float* Wq  = (const float*)d_in[4];
    const float* bq  = (const float*)d_in[5];
    const float* Wpc = (const float*)d_in[6];
    const float* bpc = (const float*)d_in[7];
    const float* Wc  = (const float*)d_in[8];
    const float* bc  = (const float*)d_in[9];
    const float* Wo  = (const float*)d_in[10];
    const float* bo  = (const float*)d_in[11];
    float* out = (float*)d_out;

    float *p_pq, *p_q, *p_kp, *p_kv, *p_attn;
    cudaGetSymbolAddress((void**)&p_pq,   g_pq);
    cudaGetSymbolAddress((void**)&p_q,    g_q);
    cudaGetSymbolAddress((void**)&p_kp,   g_kp);
    cudaGetSymbolAddress((void**)&p_kv,   g_kv);
    cudaGetSymbolAddress((void**)&p_attn, g_attn);

    const int LS_SMEM = (128 * 64 + 128 * 32) * 4;                        // 49152
    const int P1_SMEM = (128 * 65 + 128 * 64 + 128 * 32 + 64 * 32) * 4;  // 90624
    const int P2_SMEM = (128 * 33 * 2 + 128 * 64 + 32 * 65) * 4;         // 74944
    cudaFuncSetAttribute(local_sums,   cudaFuncAttributeMaxDynamicSharedMemorySize, LS_SMEM);
    cudaFuncSetAttribute(pass1_kernel, cudaFuncAttributeMaxDynamicSharedMemorySize, P1_SMEM);
    cudaFuncSetAttribute(pass2_kernel, cudaFuncAttributeMaxDynamicSharedMemorySize, P2_SMEM);

    // projections
    dim3 gP(8, 32);   // N/128, M/128  (M = T*B = 4096)
    sgemm_wt<<<gP, 256>>>(query,  Wq,  bq,  p_q,  T_LEN * BSZ, E_DIM, SCALING, 1, T_LEN);
    sgemm_wt<<<gP, 256>>>(query,  Wpc, bpc, p_kp, T_LEN * BSZ, E_DIM, 1.0f,    1, T_LEN);
    sgemm_wt<<<gP, 256>>>(query,  Wc,  bc,  p_kv, T_LEN * BSZ, E_DIM, 1.0f,    1, T_LEN);
    sgemm_wt<<<dim3(8, 1), 256>>>(pquery, Wpq, bpq, p_pq, PLEN * BSZ, E_DIM, SCALING, 1, PLEN);

    // pattn
    pattn_kernel<<<dim3(T_LEN / 64, BH), 256>>>();

    // shared chunk states + exclusive scan
    local_sums<<<dim3(NCH, BH), 256, LS_SMEM>>>();
    scan_states<<<BH, 512>>>();

    // pass 1 + softmax
    pass1_kernel<<<dim3(NCH, BH), 256, P1_SMEM>>>();
    softmax32<<<BH * T_LEN / 8, 256>>>();

    // pass 2 (state = transpose of pass1 state, reuses g_S)
    pass2_kernel<<<dim3(NCH, BH), 256, P2_SMEM>>>();

    // output projection
    sgemm_wt<<<gP, 256>>>(p_attn, Wo, bo, out, T_LEN * BSZ, E_DIM, 1.0f, 0, 0);
}

// round 3
// speedup vs baseline: 1.5633x; 1.5633x over previous
#include <cuda_runtime.h>
#include <cuda_bf16.h>
#include <math.h>
#include <stdint.h>

// Problem constants (fixed shapes per reference setup_inputs)
#define T_LEN  2048
#define BSZ    2
#define E_DIM  1024
#define H_NUM  16
#define D_DIM  64
#define PLEN   32
#define BH     32
#define CHUNK  128
#define NCH    (T_LEN/CHUNK)
#define SCALING 0.125f
#define BETA    0.6931471805599453f

#define MROWS  (T_LEN*BSZ)      // 4096

// ------------------------- scratch (no cudaMalloc allowed) -----------------
__device__ float g_pq   [BH*PLEN*D_DIM];
__device__ float g_q    [BH*T_LEN*D_DIM];
__device__ float g_kp   [BH*T_LEN*D_DIM];
__device__ float g_kv   [BH*T_LEN*D_DIM];
__device__ float g_pattn[BH*T_LEN*PLEN];
__device__ float g_attw [BH*T_LEN*PLEN];
__device__ float g_S    [BH*NCH*D_DIM*PLEN];

// bf16 hi/lo planes
__device__ __nv_bfloat16 g_Ahi [MROWS*E_DIM];
__device__ __nv_bfloat16 g_Alo [MROWS*E_DIM];
__device__ __nv_bfloat16 g_PQhi[64*E_DIM];
__device__ __nv_bfloat16 g_PQlo[64*E_DIM];
__device__ __nv_bfloat16 g_W3hi[3*E_DIM*E_DIM];   // Wq, Wpc, Wc stacked
__device__ __nv_bfloat16 g_W3lo[3*E_DIM*E_DIM];
__device__ __nv_bfloat16 g_WOhi[E_DIM*E_DIM];
__device__ __nv_bfloat16 g_WOlo[E_DIM*E_DIM];
__device__ __nv_bfloat16 g_WPQhi[E_DIM*E_DIM];
__device__ __nv_bfloat16 g_WPQlo[E_DIM*E_DIM];
__device__ __nv_bfloat16 g_AThi[MROWS*E_DIM];
__device__ __nv_bfloat16 g_ATlo[MROWS*E_DIM];

// ------------------------- helpers -----------------------------------------
__device__ __forceinline__ uint32_t smem_u32(const void* p) {
    uint32_t a;
    asm("{ .reg .u64 t; cvta.to.shared.u64 t, %1; cvt.u32.u64 %0, t; }"
        : "=r"(a) : "l"(p));
    return a;
}
__device__ __forceinline__ uint32_t sw128(uint32_t off) {
    return off ^ ((off >> 3) & 0x70);
}
__device__ __forceinline__ void ldsm_x4(uint32_t* r, uint32_t addr) {
    asm volatile("ldmatrix.sync.aligned.m8n8.x4.shared.b16 {%0,%1,%2,%3}, [%4];"
                 : "=r"(r[0]), "=r"(r[1]), "=r"(r[2]), "=r"(r[3]) : "r"(addr));
}
__device__ __forceinline__ void mma16816(float* c, const uint32_t* a, const uint32_t* b) {
    asm volatile("mma.sync.aligned.m16n8k16.row.col.f32.bf16.bf16.f32 "
                 "{%0,%1,%2,%3}, {%4,%5,%6,%7}, {%8,%9}, {%0,%1,%2,%3};"
                 : "+f"(c[0]), "+f"(c[1]), "+f"(c[2]), "+f"(c[3])
                 : "r"(a[0]), "r"(a[1]), "r"(a[2]), "r"(a[3]), "r"(b[0]), "r"(b[1]));
}

// ------------------------- fp32 -> bf16 hi/lo converter --------------------
__global__ __launch_bounds__(256)
void cvt_hilo(const float* __restrict__ src, __nv_bfloat16* __restrict__ hi,
              __nv_bfloat16* __restrict__ lo, int n)
{
    int i = blockIdx.x * 256 + threadIdx.x;
    int stride = gridDim.x * 256;
    for (; i < n; i += stride) {
        float v = src[i];
        __nv_bfloat16 h = __float2bfloat16(v);
        hi[i] = h;
        lo[i] = __float2bfloat16(v - __bfloat162float(h));
    }
}

// ------------------------- mma.sync split-bf16 GEMM -------------------------
// C_z = (A @ W_z^T + bias_z) * scale_z.  A: Mx1024 (hi/lo bf16), W_z: 1024x1024
// row-major (hi/lo), z = blockIdx.z selects weight/bias/out/scale.
// mode 0: out[m*1024+n]
// mode 1: m=(t,b), n=(h,d) -> out[((b*16+h)*Trows + t)*64 + d]
__global__ __launch_bounds__(256)
void gemm_mma(const __nv_bfloat16* __restrict__ Ahi, const __nv_bfloat16* __restrict__ Alo,
              const __nv_bfloat16* __restrict__ Whi, const __nv_bfloat16* __restrict__ Wlo,
              const float* b0, const float* b1, const float* b2,
              float* o0, float* o1, float* o2,
              float s0, float s1, float s2,
              int M, int mode, int Trows)
{
    extern __shared__ char smem[];
    const uint32_t sb = smem_u32(smem);
    const uint32_t AHI = 0, ALO = 16384, BHI = 32768, BLO = 49152;

    const int tid = threadIdx.x, wid = tid >> 5, lane = tid & 31;
    const int bm = blockIdx.y * 128, bn = blockIdx.x * 128;
    const int z = blockIdx.z;
    const __nv_bfloat16* wh = Whi + (size_t)z * E_DIM * E_DIM;
    const __nv_bfloat16* wl = Wlo + (size_t)z * E_DIM * E_DIM;
    const float* bias = (z == 0) ? b0 : ((z == 1) ? b1 : b2);
    float* out        = (z == 0) ? o0 : ((z == 1) ? o1 : o2);
    const float scale = (z == 0) ? s0 : ((z == 1) ? s1 : s2);

    const int warpM = (wid >> 2) * 64;   // 0 / 64
    const int warpN = (wid & 3) * 32;    // 0 / 32 / 64 / 96

    float acc[4][4][4];
#pragma unroll
    for (int i = 0; i < 4; i++)
#pragma unroll
        for (int j = 0; j < 4; j++)
#pragma unroll
            for (int k = 0; k < 4; k++) acc[i][j][k] = 0.f;

    const int li = lane >> 3, lr = lane & 7;
    const uint4 z4 = make_uint4(0u, 0u, 0u, 0u);

    for (int ks = 0; ks < 16; ks++) {
        const int k0g = ks * 64;
        // ---- load tiles: A hi/lo (128x64), B hi/lo (128x64), swizzled ----
        for (int i = tid; i < 1024; i += 256) {
            int r = i >> 3, c = i & 7;
            uint32_t so = sw128((uint32_t)(r * 128 + c * 16));
            int m = bm + r;
            uint4 vh = z4, vl = z4;
            if (m < M) {
                const size_t gA = (size_t)m * E_DIM + k0g + c * 8;
                vh = *(const uint4*)(Ahi + gA);
                vl = *(const uint4*)(Alo + gA);
            }
            *(uint4*)(smem + AHI + so) = vh;
            *(uint4*)(smem + ALO + so) = vl;
            const size_t gB = (size_t)(bn + r) * E_DIM + k0g + c * 8;
            *(uint4*)(smem + BHI + so) = *(const uint4*)(wh + gB);
            *(uint4*)(smem + BLO + so) = *(const uint4*)(wl + gB);
        }
        __syncthreads();

        // ---- 4 x k16 MMA steps ----
#pragma unroll
        for (int kk = 0; kk < 4; kk++) {
            const int k0 = kk * 16;
            uint32_t ah[4][4], al[4][4], bh[2][4], bl[2][4];
#pragma unroll
            for (int i = 0; i < 4; i++) {
                int row = warpM + i * 16 + (li & 1) * 8 + lr;
                int kc  = k0 + (li >> 1) * 8;
                uint32_t off = sw128((uint32_t)(row * 128 + kc * 2));
                ldsm_x4(ah[i], sb + AHI + off);
                ldsm_x4(al[i], sb + ALO + off);
            }
#pragma unroll
            for (int jn = 0; jn < 2; jn++) {
                int row = warpN + jn * 16 + (li >> 1) * 8 + lr;
                int kc  = k0 + (li & 1) * 8;
                uint32_t off = sw128((uint32_t)(row * 128 + kc * 2));
                ldsm_x4(bh[jn], sb + BHI + off);
                ldsm_x4(bl[jn], sb + BLO + off);
            }
#pragma unroll
            for (int i = 0; i < 4; i++)
#pragma unroll
                for (int j = 0; j < 4; j++) {
                    const uint32_t* Bh = &bh[j >> 1][(j & 1) * 2];
                    const uint32_t* Bl = &bl[j >> 1][(j & 1) * 2];
                    mma16816(acc[i][j], ah[i], Bh);   // hi*hi
                    mma16816(acc[i][j], ah[i], Bl);   // hi*lo
                    mma16816(acc[i][j], al[i], Bh);   // lo*hi
                }
        }
        __syncthreads();
    }

    // ---- epilogue ----
    const int g = lane >> 2, tg = lane & 3;
#pragma unroll
    for (int i = 0; i < 4; i++) {
#pragma unroll
        for (int j = 0; j < 4; j++) {
            int m0 = bm + warpM + i * 16 + g;
            int n0 = bn + warpN + j * 8 + tg * 2;
#pragma unroll
            for (int e = 0; e < 4; e++) {
                int m = m0 + (e >> 1) * 8;
                int n = n0 + (e & 1);
                if (m >= M) continue;
                float v = (acc[i][j][e] + bias[n]) * scale;
                if (mode == 0) {
                    out[(size_t)m * E_DIM + n] = v;
                } else {
                    int t = m >> 1, b = m & 1;
                    int h = n >> 6, d = n & 63;
                    out[(size_t)((b * 16 + h) * Trows + t) * 64 + d] = v;
                }
            }
        }
    }
}

// ------------------------- pattn = softplus(beta * kp@pq^T)/beta -----------
__global__ __launch_bounds__(256)
void pattn_kernel()
{
    const int bh = blockIdx.y;
    const int t0 = blockIdx.x * 64;
    __shared__ float pqs[PLEN][D_DIM + 1];
    __shared__ float kps[64][D_DIM + 1];

    for (int i = threadIdx.x; i < PLEN * D_DIM; i += 256)
        pqs[i / D_DIM][i % D_DIM] = g_pq[(size_t)bh * PLEN * D_DIM + i];
    for (int i = threadIdx.x; i < 64 * D_DIM; i += 256) {
        int tt = i / D_DIM, d = i % D_DIM;
        kps[tt][d] = g_kp[((size_t)bh * T_LEN + t0 + tt) * D_DIM + d];
    }
    __syncthreads();

    const int t  = threadIdx.x >> 2;
    const int p0 = (threadIdx.x & 3) * 8;
#pragma unroll
    for (int pp = 0; pp < 8; pp++) {
        int p = p0 + pp;
        float acc = 0.f;
#pragma unroll
        for (int d = 0; d < 64; d++) acc += kps[t][d] * pqs[p][d];
        float z  = BETA * acc;
        float sp = fmaxf(z, 0.f) + log1pf(expf(-fabsf(z)));
        g_pattn[((size_t)bh * T_LEN + t0 + t) * PLEN + p] = sp * (1.0f / BETA);
    }
}

// ------------------- chunk-local state: L = KV^T @ P (64x32) ---------------
__global__ __launch_bounds__(256)
void local_sums()
{
    const int c = blockIdx.x, bh = blockIdx.y;
    extern __shared__ float sm[];
    float* kvs = sm;
    float* ps  = sm + 128 * 64;
    const size_t base = (size_t)bh * T_LEN + c * CHUNK;

    for (int i = threadIdx.x; i < 128 * 64; i += 256) kvs[i] = g_kv[base * 64 + i];
    for (int i = threadIdx.x; i < 128 * 32; i += 256) ps[i]  = g_pattn[base * 32 + i];
    __syncthreads();

    const int d  = threadIdx.x >> 2;
    const int j0 = (threadIdx.x & 3) * 8;
    float acc[8] = {0.f};
    for (int s = 0; s < 128; s++) {
        float a = kvs[s * 64 + d];
#pragma unroll
        for (int jj = 0; jj < 8; jj++) acc[jj] += a * ps[s * 32 + j0 + jj];
    }
    float* out = &g_S[((size_t)bh * NCH + c) * (64 * 32)];
#pragma unroll
    for (int jj = 0; jj < 8; jj++) out[d * 32 + j0 + jj] = acc[jj];
}

// ------------------- exclusive prefix scan over chunks ---------------------
__global__ void scan_states()
{
    const int bh = blockIdx.x;
    for (int r = 0; r < 4; r++) {
        int e = threadIdx.x + r * 512;
        float run = 0.f;
        for (int c = 0; c < NCH; c++) {
            float* p = &g_S[(((size_t)bh * NCH) + c) * 2048 + e];
            float v = *p;
            *p = run;
            run += v;
        }
    }
}

// ------------------- pass1 ---------------------------------------------------
__global__ __launch_bounds__(256)
void pass1_kernel()
{
    const int c = blockIdx.x, bh = blockIdx.y;
    extern __shared__ float sm[];
    float* qs  = sm;
    float* kvs = qs + 128 * 65;
    float* ps  = kvs + 128 * 64;
    float* ss  = ps + 128 * 32;
    const size_t base = (size_t)bh * T_LEN + c * CHUNK;

    for (int i = threadIdx.x; i < 128 * 64; i += 256) {
        int s = i >> 6, d = i & 63;
        qs[s * 65 + d] = g_q[(base + s) * 64 + d];
        kvs[i] = g_kv[(base + s) * 64 + d];
    }
    for (int i = threadIdx.x; i < 128 * 32; i += 256) ps[i] = g_pattn[base * 32 + i];
    for (int i = threadIdx.x; i < 64 * 32; i += 256)
        ss[i] = g_S[((size_t)bh * NCH + c) * 2048 + i];
    __syncthreads();

    const int t  = threadIdx.x >> 1;
    const int j0 = (threadIdx.x & 1) * 16;

    float qreg[64];
#pragma unroll
    for (int d = 0; d < 64; d++) qreg[d] = qs[t * 65 + d];

    float r[16] = {0.f};
#pragma unroll 8
    for (int d = 0; d < 64; d++) {
        float a = qreg[d];
#pragma unroll
        for (int jj = 0; jj < 16; jj++) r[jj] += a * ss[d * 32 + j0 + jj];
    }
    const int smax = t | 15;
    for (int s = 0; s <= smax; s++) {
        float a = 0.f;
#pragma unroll 16
        for (int d = 0; d < 64; d++) a += qreg[d] * kvs[s * 64 + d];
        if (s <= t) {
#pragma unroll
            for (int jj = 0; jj < 16; jj++) r[jj] += a * ps[s * 32 + j0 + jj];
        }
    }
    const int tg = c * CHUNK + t;
    const float inv = 1.0f / (float)(tg + 1);
#pragma unroll
    for (int jj = 0; jj < 16; jj++)
        g_attw[((size_t)bh * T_LEN + tg) * 32 + j0 + jj] = r[jj] * inv;
}

// ------------------- softmax over plen=32 ----------------------------------
__global__ __launch_bounds__(256)
void softmax32()
{
    const int row  = blockIdx.x * 8 + (threadIdx.x >> 5);
    const int lane = threadIdx.x & 31;
    float v = g_attw[(size_t)row * 32 + lane];
    float m = v;
#pragma unroll
    for (int o = 16; o; o >>= 1) m = fmaxf(m, __shfl_xor_sync(0xffffffffu, m, o));
    float e = expf(v - m);
    float s = e;
#pragma unroll
    for (int o = 16; o; o >>= 1) s += __shfl_xor_sync(0xffffffffu, s, o);
    g_attw[(size_t)row * 32 + lane] = e / s;
}

// ------------------- pass2 (emits bf16 hi/lo for output projection) --------
__global__ __launch_bounds__(256)
void pass2_kernel()
{
    const int c = blockIdx.x, bh = blockIdx.y;
    extern __shared__ float sm[];
    float* ws  = sm;
    float* ps  = ws + 128 * 33;
    float* kvs = ps + 128 * 33;
    float* ss2 = kvs + 128 * 64;
    const size_t base = (size_t)bh * T_LEN + c * CHUNK;

    for (int i = threadIdx.x; i < 128 * 32; i += 256) {
        int s = i >> 5, j = i & 31;
        ws[s * 33 + j] = g_attw [base * 32 + i];
        ps[s * 33 + j] = g_pattn[base * 32 + i];
    }
    for (int i = threadIdx.x; i < 128 * 64; i += 256) kvs[i] = g_kv[base * 64 + i];
    for (int i = threadIdx.x; i < 64 * 32; i += 256) {
        int d = i >> 5, j = i & 31;
        ss2[j * 65 + d] = g_S[((size_t)bh * NCH + c) * 2048 + i];
    }
    __syncthreads();

    const int t  = threadIdx.x >> 1;
    const int d0 = (threadIdx.x & 1) * 32;

    float wreg[32];
#pragma unroll
    for (int j = 0; j < 32; j++) wreg[j] = ws[t * 33 + j];

    float r[32] = {0.f};
#pragma unroll 8
    for (int j = 0; j < 32; j++) {
        float a = wreg[j];
#pragma unroll
        for (int dd = 0; dd < 32; dd++) r[dd] += a * ss2[j * 65 + d0 + dd];
    }
    const int smax = t | 15;
    for (int s = 0; s <= smax; s++) {
        float a = 0.f;
#pragma unroll
        for (int j = 0; j < 32; j++) a += wreg[j] * ps[s * 33 + j];
        if (s <= t) {
#pragma unroll
            for (int dd = 0; dd < 32; dd++) r[dd] += a * kvs[s * 64 + d0 + dd];
        }
    }
    const int tg  = c * CHUNK + t;
    const float inv = 1.0f / (float)(tg + 1);
    const int b = bh >> 4, hh = bh & 15;
    const size_t ob = ((size_t)tg * 2 + b) * 1024 + hh * 64 + d0;
#pragma unroll
    for (int dd = 0; dd < 32; dd++) {
        float v = r[dd] * inv;
        __nv_bfloat16 h = __float2bfloat16(v);
        g_AThi[ob + dd] = h;
        g_ATlo[ob + dd] = __float2bfloat16(v - __bfloat162float(h));
    }
}

// ---------------------------------------------------------------------------
extern "C" void kernel_launch(void* const* d_in, const int* in_sizes, int n_in,
                              void* d_out, int out_size)
{
    const float* query  = (const float*)d_in[0];
    const float* pquery = (const float*)d_in[1];
    const float* Wpq = (const float*)d_in[2];
    const float* bpq = (const float*)d_in[3];
    const float* Wq  = (const float*)d_in[4];
    const float* bq  = (const float*)d_in[5];
    const float* Wpc = (const float*)d_in[6];
    const float* bpc = (const float*)d_in[7];
    const float* Wc  = (const float*)d_in[8];
    const float* bc  = (const float*)d_in[9];
    const float* Wo  = (const float*)d_in[10];
    const float* bo  = (const float*)d_in[11];
    float* out = (float*)d_out;

    float *p_pq, *p_q, *p_kp, *p_kv;
    __nv_bfloat16 *p_Ahi, *p_Alo, *p_PQhi, *p_PQlo, *p_W3hi, *p_W3lo;
    __nv_bfloat16 *p_WOhi, *p_WOlo, *p_WPQhi, *p_WPQlo, *p_AThi, *p_ATlo;
    cudaGetSymbolAddress((void**)&p_pq,   g_pq);
    cudaGetSymbolAddress((void**)&p_q,    g_q);
    cudaGetSymbolAddress((void**)&p_kp,   g_kp);
    cudaGetSymbolAddress((void**)&p_kv,   g_kv);
    cudaGetSymbolAddress((void**)&p_Ahi,  g_Ahi);
    cudaGetSymbolAddress((void**)&p_Alo,  g_Alo);
    cudaGetSymbolAddress((void**)&p_PQhi, g_PQhi);
    cudaGetSymbolAddress((void**)&p_PQlo, g_PQlo);
    cudaGetSymbolAddress((void**)&p_W3hi, g_W3hi);
    cudaGetSymbolAddress((void**)&p_W3lo, g_W3lo);
    cudaGetSymbolAddress((void**)&p_WOhi, g_WOhi);
    cudaGetSymbolAddress((void**)&p_WOlo, g_WOlo);
    cudaGetSymbolAddress((void**)&p_WPQhi,g_WPQhi);
    cudaGetSymbolAddress((void**)&p_WPQlo,g_WPQlo);
    cudaGetSymbolAddress((void**)&p_AThi, g_AThi);
    cudaGetSymbolAddress((void**)&p_ATlo, g_ATlo);

    const int GEMM_SMEM = 65536;
    const int LS_SMEM = (128 * 64 + 128 * 32) * 4;
    const int P1_SMEM = (128 * 65 + 128 * 64 + 128 * 32 + 64 * 32) * 4;
    const int P2_SMEM = (128 * 33 * 2 + 128 * 64 + 32 * 65) * 4;
    cudaFuncSetAttribute(gemm_mma,     cudaFuncAttributeMaxDynamicSharedMemorySize, GEMM_SMEM);
    cudaFuncSetAttribute(local_sums,   cudaFuncAttributeMaxDynamicSharedMemorySize, LS_SMEM);
    cudaFuncSetAttribute(pass1_kernel, cudaFuncAttributeMaxDynamicSharedMemorySize, P1_SMEM);
    cudaFuncSetAttribute(pass2_kernel, cudaFuncAttributeMaxDynamicSharedMemorySize, P2_SMEM);

    const int NE = E_DIM * E_DIM;

    // fp32 -> bf16 hi/lo conversions
    cvt_hilo<<<512, 256>>>(query,  p_Ahi,  p_Alo,  MROWS * E_DIM);
    cvt_hilo<<<64,  256>>>(pquery, p_PQhi, p_PQlo, 64 * E_DIM);
    cvt_hilo<<<256, 256>>>(Wq,  p_W3hi,          p_W3lo,          NE);
    cvt_hilo<<<256, 256>>>(Wpc, p_W3hi + NE,     p_W3lo + NE,     NE);
    cvt_hilo<<<256, 256>>>(Wc,  p_W3hi + 2 * NE, p_W3lo + 2 * NE, NE);
    cvt_hilo<<<256, 256>>>(Wo,  p_WOhi,  p_WOlo,  NE);
    cvt_hilo<<<256, 256>>>(Wpq, p_WPQhi, p_WPQlo, NE);

    // fused q/kp/kv projections: gridDim.z selects the weight
    gemm_mma<<<dim3(8, 32, 3), 256, GEMM_SMEM>>>(
        p_Ahi, p_Alo, p_W3hi, p_W3lo,
        bq, bpc, bc, p_q, p_kp, p_kv,
        SCALING, 1.0f, 1.0f, MROWS, 1, T_LEN);

    // pq projection (M=64, padded to one 128-row block)
    gemm_mma<<<dim3(8, 1, 1), 256, GEMM_SMEM>>>(
        p_PQhi, p_PQlo, p_WPQhi, p_WPQlo,
        bpq, bpq, bpq, p_pq, p_pq, p_pq,
        SCALING, SCALING, SCALING, 64, 1, PLEN);

    // pattn
    pattn_kernel<<<dim3(T_LEN / 64, BH), 256>>>();

    // chunk states + scan
    local_sums<<<dim3(NCH, BH), 256, LS_SMEM>>>();
    scan_states<<<BH, 512>>>();

    // pass 1 + softmax
    pass1_kernel<<<dim3(NCH, BH), 256, P1_SMEM>>>();
    softmax32<<<BH * T_LEN / 8, 256>>>();

    // pass 2 (emits bf16 hi/lo)
    pass2_kernel<<<dim3(NCH, BH), 256, P2_SMEM>>>();

    // output projection -> d_out
    gemm_mma<<<dim3(8, 32, 1), 256, GEMM_SMEM>>>(
        p_AThi, p_ATlo, p_WOhi, p_WOlo,
        bo, bo, bo, out, out, out,
        1.0f, 1.0f, 1.0f, MROWS, 0, 0);
}

// round 4
// speedup vs baseline: 2.2082x; 1.4125x over previous
#include <cuda_runtime.h>
#include <cuda_bf16.h>
#include <math.h>
#include <stdint.h>

// Problem constants (fixed shapes per reference setup_inputs)
#define T_LEN  2048
#define BSZ    2
#define E_DIM  1024
#define H_NUM  16
#define D_DIM  64
#define PLEN   32
#define BH     32
#define CHUNK  128
#define NCH    (T_LEN/CHUNK)
#define SCALING 0.125f
#define BETA    0.6931471805599453f

#define MROWS  (T_LEN*BSZ)      // 4096

// ------------------------- scratch (no cudaMalloc allowed) -----------------
__device__ float g_pq   [BH*PLEN*D_DIM];
__device__ float g_q    [BH*T_LEN*D_DIM];
__device__ float g_kp   [BH*T_LEN*D_DIM];
__device__ float g_kv   [BH*T_LEN*D_DIM];
__device__ float g_pattn[BH*T_LEN*PLEN];
__device__ float g_S    [BH*NCH*D_DIM*PLEN];

// bf16 hi/lo planes
__device__ __nv_bfloat16 g_Ahi [MROWS*E_DIM];
__device__ __nv_bfloat16 g_Alo [MROWS*E_DIM];
__device__ __nv_bfloat16 g_PQhi[64*E_DIM];
__device__ __nv_bfloat16 g_PQlo[64*E_DIM];
__device__ __nv_bfloat16 g_W3hi[3*E_DIM*E_DIM];   // Wq, Wpc, Wc stacked
__device__ __nv_bfloat16 g_W3lo[3*E_DIM*E_DIM];
__device__ __nv_bfloat16 g_WOhi[E_DIM*E_DIM];
__device__ __nv_bfloat16 g_WOlo[E_DIM*E_DIM];
__device__ __nv_bfloat16 g_WPQhi[E_DIM*E_DIM];
__device__ __nv_bfloat16 g_WPQlo[E_DIM*E_DIM];
__device__ __nv_bfloat16 g_AThi[MROWS*E_DIM];
__device__ __nv_bfloat16 g_ATlo[MROWS*E_DIM];

// ------------------------- helpers -----------------------------------------
__device__ __forceinline__ uint32_t smem_u32(const void* p) {
    uint32_t a;
    asm("{ .reg .u64 t; cvta.to.shared.u64 t, %1; cvt.u32.u64 %0, t; }"
        : "=r"(a) : "l"(p));
    return a;
}
__device__ __forceinline__ uint32_t sw128(uint32_t off) {
    return off ^ ((off >> 3) & 0x70);
}
__device__ __forceinline__ void ldsm_x4(uint32_t* r, uint32_t addr) {
    asm volatile("ldmatrix.sync.aligned.m8n8.x4.shared.b16 {%0,%1,%2,%3}, [%4];"
                 : "=r"(r[0]), "=r"(r[1]), "=r"(r[2]), "=r"(r[3]) : "r"(addr));
}
__device__ __forceinline__ void mma16816(float* c, const uint32_t* a, const uint32_t* b) {
    asm volatile("mma.sync.aligned.m16n8k16.row.col.f32.bf16.bf16.f32 "
                 "{%0,%1,%2,%3}, {%4,%5,%6,%7}, {%8,%9}, {%0,%1,%2,%3};"
                 : "+f"(c[0]), "+f"(c[1]), "+f"(c[2]), "+f"(c[3])
                 : "r"(a[0]), "r"(a[1]), "r"(a[2]), "r"(a[3]), "r"(b[0]), "r"(b[1]));
}
__device__ __forceinline__ void cp16(uint32_t dst, const void* src, int sz) {
    asm volatile("cp.async.cg.shared.global [%0], [%1], 16, %2;"
                 :: "r"(dst), "l"(src), "r"(sz));
}
__device__ __forceinline__ void cp_commit() {
    asm volatile("cp.async.commit_group;" ::: "memory");
}
__device__ __forceinline__ void cp_wait1() {
    asm volatile("cp.async.wait_group 1;" ::: "memory");
}
__device__ __forceinline__ void cp_wait0() {
    asm volatile("cp.async.wait_group 0;" ::: "memory");
}

// ------------------------- fp32 -> bf16 hi/lo converter (vectorized) -------
__global__ __launch_bounds__(256)
void cvt_hilo4(const float4* __restrict__ src, __nv_bfloat162* __restrict__ hi,
               __nv_bfloat162* __restrict__ lo, int n4)
{
    int i = blockIdx.x * 256 + threadIdx.x;
    if (i >= n4) return;
    float4 v = src[i];
    __nv_bfloat16 h0 = __float2bfloat16(v.x);
    __nv_bfloat16 h1 = __float2bfloat16(v.y);
    __nv_bfloat16 h2 = __float2bfloat16(v.z);
    __nv_bfloat16 h3 = __float2bfloat16(v.w);
    __nv_bfloat16 l0 = __float2bfloat16(v.x - __bfloat162float(h0));
    __nv_bfloat16 l1 = __float2bfloat16(v.y - __bfloat162float(h1));
    __nv_bfloat16 l2 = __float2bfloat16(v.z - __bfloat162float(h2));
    __nv_bfloat16 l3 = __float2bfloat16(v.w - __bfloat162float(h3));
    hi[2 * i]     = __nv_bfloat162(h0, h1);
    hi[2 * i + 1] = __nv_bfloat162(h2, h3);
    lo[2 * i]     = __nv_bfloat162(l0, l1);
    lo[2 * i + 1] = __nv_bfloat162(l2, l3);
}

// ------------------------- pipelined split-bf16 GEMM ------------------------
// C_z = (A @ W_z^T + bias_z) * scale_z.  A: Mx1024 (hi/lo), W_z: 1024x1024 (hi/lo).
// k-tile 32; smem row = 128B: [hi 64B | lo 64B]; 2-stage cp.async pipeline.
// mode 0: out[m*1024+n]
// mode 1: m=(t,b), n=(h,d) -> out[((b*16+h)*Trows + t)*64 + d]
__device__ __forceinline__ void g_load_stage(
    uint32_t sb, int st,
    const __nv_bfloat16* Ahi, const __nv_bfloat16* Alo,
    const __nv_bfloat16* Bhi, const __nv_bfloat16* Blo,
    int bm, int bn, int kb, int M, int tid)
{
    const uint32_t abase = sb + st * 32768;
    const uint32_t bbase = abase + 16384;
#pragma unroll
    for (int ii = 0; ii < 4; ii++) {
        int i = tid + ii * 256;
        int r = i >> 3, c = i & 7;
        uint32_t so = sw128((uint32_t)(r * 128 + c * 16));
        // A
        int m = bm + r;
        int mc = (m < M) ? m : (M - 1);
        const __nv_bfloat16* asrc = ((c & 4) ? Alo : Ahi)
            + (size_t)mc * E_DIM + kb + (c & 3) * 8;
        cp16(abase + so, asrc, (m < M) ? 16 : 0);
        // B
        const __nv_bfloat16* bsrc = ((c & 4) ? Blo : Bhi)
            + (size_t)(bn + r) * E_DIM + kb + (c & 3) * 8;
        cp16(bbase + so, bsrc, 16);
    }
}

__global__ __launch_bounds__(256)
void gemm_mma(const __nv_bfloat16* __restrict__ Ahi, const __nv_bfloat16* __restrict__ Alo,
              const __nv_bfloat16* __restrict__ Whi, const __nv_bfloat16* __restrict__ Wlo,
              const float* b0, const float* b1, const float* b2,
              float* o0, float* o1, float* o2,
              float s0, float s1, float s2,
              int M, int mode, int Trows)
{
    extern __shared__ char smem[];
    const uint32_t sb = smem_u32(smem);

    const int tid = threadIdx.x, wid = tid >> 5, lane = tid & 31;
    const int bm = blockIdx.y * 128, bn = blockIdx.x * 128;
    const int z = blockIdx.z;
    const __nv_bfloat16* wh = Whi + (size_t)z * E_DIM * E_DIM;
    const __nv_bfloat16* wl = Wlo + (size_t)z * E_DIM * E_DIM;
    const float* bias = (z == 0) ? b0 : ((z == 1) ? b1 : b2);
    float* out        = (z == 0) ? o0 : ((z == 1) ? o1 : o2);
    const float scale = (z == 0) ? s0 : ((z == 1) ? s1 : s2);

    const int warpM = (wid >> 2) * 64;   // 0 / 64
    const int warpN = (wid & 3) * 32;    // 0 / 32 / 64 / 96
    const int li = lane >> 3, lr = lane & 7;

    float acc[4][4][4];
#pragma unroll
    for (int i = 0; i < 4; i++)
#pragma unroll
        for (int j = 0; j < 4; j++)
#pragma unroll
            for (int k = 0; k < 4; k++) acc[i][j][k] = 0.f;

    const int NK = E_DIM / 32;  // 32 stages
    g_load_stage(sb, 0, Ahi, Alo, wh, wl, bm, bn, 0, M, tid);
    cp_commit();

    for (int ks = 0; ks < NK; ks++) {
        if (ks + 1 < NK) {
            g_load_stage(sb, (ks + 1) & 1, Ahi, Alo, wh, wl, bm, bn, (ks + 1) * 32, M, tid);
            cp_commit();
            cp_wait1();
        } else {
            cp_wait0();
        }
        __syncthreads();

        const uint32_t abase = sb + (ks & 1) * 32768;
        const uint32_t bbase = abase + 16384;
#pragma unroll
        for (int kk = 0; kk < 2; kk++) {
            uint32_t ah[4][4], al[4][4], bh[2][4], bl[2][4];
            const uint32_t ka = (uint32_t)(kk * 32 + (li >> 1) * 16);
#pragma unroll
            for (int i = 0; i < 4; i++) {
                uint32_t off = (uint32_t)((warpM + i * 16 + (li & 1) * 8 + lr) * 128) + ka;
                ldsm_x4(ah[i], abase + sw128(off));
                ldsm_x4(al[i], abase + sw128(off + 64));
            }
            const uint32_t kb2 = (uint32_t)(kk * 32 + (li & 1) * 16);
#pragma unroll
            for (int jn = 0; jn < 2; jn++) {
                uint32_t off = (uint32_t)((warpN + jn * 16 + (li >> 1) * 8 + lr) * 128) + kb2;
                ldsm_x4(bh[jn], bbase + sw128(off));
                ldsm_x4(bl[jn], bbase + sw128(off + 64));
            }
#pragma unroll
            for (int i = 0; i < 4; i++)
#pragma unroll
                for (int j = 0; j < 4; j++) {
                    const uint32_t* Bh = &bh[j >> 1][(j & 1) * 2];
                    const uint32_t* Bl = &bl[j >> 1][(j & 1) * 2];
                    mma16816(acc[i][j], ah[i], Bh);
                    mma16816(acc[i][j], ah[i], Bl);
                    mma16816(acc[i][j], al[i], Bh);
                }
        }
        __syncthreads();
    }

    // ---- epilogue ----
    const int g = lane >> 2, tg = lane & 3;
#pragma unroll
    for (int i = 0; i < 4; i++) {
#pragma unroll
        for (int j = 0; j < 4; j++) {
            int m0 = bm + warpM + i * 16 + g;
            int n0 = bn + warpN + j * 8 + tg * 2;
#pragma unroll
            for (int e = 0; e < 4; e++) {
                int m = m0 + (e >> 1) * 8;
                int n = n0 + (e & 1);
                if (m >= M) continue;
                float v = (acc[i][j][e] + bias[n]) * scale;
                if (mode == 0) {
                    out[(size_t)m * E_DIM + n] = v;
                } else {
                    int t = m >> 1, b = m & 1;
                    int h = n >> 6, d = n & 63;
                    out[(size_t)((b * 16 + h) * Trows + t) * 64 + d] = v;
                }
            }
        }
    }
}

// ------------------------- pattn = softplus(beta * kp@pq^T)/beta -----------
__global__ __launch_bounds__(256)
void pattn_kernel()
{
    const int bh = blockIdx.y;
    const int t0 = blockIdx.x * 64;
    __shared__ float pqs[PLEN][D_DIM + 1];
    __shared__ float kps[64][D_DIM + 1];

    for (int i = threadIdx.x; i < PLEN * D_DIM; i += 256)
        pqs[i / D_DIM][i % D_DIM] = g_pq[(size_t)bh * PLEN * D_DIM + i];
    for (int i = threadIdx.x; i < 64 * D_DIM; i += 256) {
        int tt = i / D_DIM, d = i % D_DIM;
        kps[tt][d] = g_kp[((size_t)bh * T_LEN + t0 + tt) * D_DIM + d];
    }
    __syncthreads();

    const int t  = threadIdx.x >> 2;
    const int p0 = (threadIdx.x & 3) * 8;
#pragma unroll
    for (int pp = 0; pp < 8; pp++) {
        int p = p0 + pp;
        float a0 = 0.f, a1 = 0.f, a2 = 0.f, a3 = 0.f;
#pragma unroll
        for (int d = 0; d < 64; d += 4) {
            a0 += kps[t][d]     * pqs[p][d];
            a1 += kps[t][d + 1] * pqs[p][d + 1];
            a2 += kps[t][d + 2] * pqs[p][d + 2];
            a3 += kps[t][d + 3] * pqs[p][d + 3];
        }
        float accv = (a0 + a1) + (a2 + a3);
        float zz = BETA * accv;
        float sp = fmaxf(zz, 0.f) + log1pf(expf(-fabsf(zz)));
        g_pattn[((size_t)bh * T_LEN + t0 + t) * PLEN + p] = sp * (1.0f / BETA);
    }
}

// ------------------- chunk-local state: L = KV^T @ P (64x32) ---------------
__global__ __launch_bounds__(256)
void local_sums()
{
    const int c = blockIdx.x, bh = blockIdx.y;
    extern __shared__ float sm[];
    float* kvs = sm;
    float* ps  = sm + 128 * 64;
    const size_t base = (size_t)bh * T_LEN + c * CHUNK;

    for (int i = threadIdx.x; i < 128 * 64; i += 256) kvs[i] = g_kv[base * 64 + i];
    for (int i = threadIdx.x; i < 128 * 32; i += 256) ps[i]  = g_pattn[base * 32 + i];
    __syncthreads();

    const int d  = threadIdx.x >> 2;
    const int j0 = (threadIdx.x & 3) * 8;
    float acc[8] = {0.f};
    for (int s = 0; s < 128; s++) {
        float a = kvs[s * 64 + d];
#pragma unroll
        for (int jj = 0; jj < 8; jj++) acc[jj] += a * ps[s * 32 + j0 + jj];
    }
    float* out = &g_S[((size_t)bh * NCH + c) * (64 * 32)];
#pragma unroll
    for (int jj = 0; jj < 8; jj++) out[d * 32 + j0 + jj] = acc[jj];
}

// ------------------- exclusive prefix scan over chunks ---------------------
__global__ void scan_states()
{
    const int bh = blockIdx.x;
    for (int r = 0; r < 4; r++) {
        int e = threadIdx.x + r * 512;
        float run = 0.f;
        for (int c = 0; c < NCH; c++) {
            float* p = &g_S[(((size_t)bh * NCH) + c) * 2048 + e];
            float v = *p;
            *p = run;
            run += v;
        }
    }
}

// ------------------- fused pass1 + softmax + pass2 --------------------------
// Per (chunk, bh): computes attn_weights rows (pass1), row-softmax, then
// attn output (pass2) directly to bf16 hi/lo. No g_attw global traffic.
__global__ __launch_bounds__(256)
void fused_pass()
{
    const int c = blockIdx.x, bh = blockIdx.y;
    extern __shared__ float sm[];
    float* qs  = sm;                 // 128 x 65
    float* kvs = qs  + 128 * 65;     // 128 x 64
    float* ps  = kvs + 128 * 64;     // 128 x 33
    float* ss  = ps  + 128 * 33;     // 64 x 33   (pass1: [d][j])
    float* ssT = ss  + 64 * 33;      // 32 x 65   (pass2: [j][d])
    float* ws  = ssT + 32 * 65;      // 128 x 33
    const size_t base = (size_t)bh * T_LEN + c * CHUNK;
    const int tid = threadIdx.x;

    for (int i = tid; i < 128 * 64; i += 256) {
        int s = i >> 6, d = i & 63;
        kvs[i] = g_kv[(base + s) * 64 + d];
        qs[s * 65 + d] = g_q[(base + s) * 64 + d];
    }
    for (int i = tid; i < 128 * 32; i += 256) {
        int s = i >> 5, j = i & 31;
        ps[s * 33 + j] = g_pattn[base * 32 + i];
    }
    for (int i = tid; i < 64 * 32; i += 256) {
        int d = i >> 5, j = i & 31;
        float v = g_S[((size_t)bh * NCH + c) * 2048 + i];
        ss[d * 33 + j]  = v;
        ssT[j * 65 + d] = v;
    }
    __syncthreads();

    const int t   = tid >> 1;
    const int tgl = c * CHUNK + t;
    const float inv = 1.0f / (float)(tgl + 1);
    const int smax = t | 15;   // uniform within warp

    // ---------------- pass 1 ----------------
    {
        const int j0 = (tid & 1) * 16;
        float qreg[64];
#pragma unroll
        for (int d = 0; d < 64; d++) qreg[d] = qs[t * 65 + d];

        float r[16];
#pragma unroll
        for (int jj = 0; jj < 16; jj++) r[jj] = 0.f;

        // inter-chunk: q[t] @ S_prefix
#pragma unroll 8
        for (int d = 0; d < 64; d++) {
            float a = qreg[d];
#pragma unroll
            for (int jj = 0; jj < 16; jj++) r[jj] += a * ss[d * 33 + j0 + jj];
        }
        // intra-chunk causal
        for (int s = 0; s <= smax; s++) {
            const float* kr = &kvs[s * 64];
            float a0 = 0.f, a1 = 0.f, a2 = 0.f, a3 = 0.f;
#pragma unroll
            for (int d = 0; d < 64; d += 4) {
                a0 += qreg[d]     * kr[d];
                a1 += qreg[d + 1] * kr[d + 1];
                a2 += qreg[d + 2] * kr[d + 2];
                a3 += qreg[d + 3] * kr[d + 3];
            }
            float a = (a0 + a1) + (a2 + a3);
            if (s <= t) {
                const float* pr = &ps[s * 33 + j0];
#pragma unroll
                for (int jj = 0; jj < 16; jj++) r[jj] += a * pr[jj];
            }
        }
        // scale by 1/(t+1), softmax with partner lane (lane^1)
        float mx = -1e30f;
#pragma unroll
        for (int jj = 0; jj < 16; jj++) { r[jj] *= inv; mx = fmaxf(mx, r[jj]); }
        mx = fmaxf(mx, __shfl_xor_sync(0xffffffffu, mx, 1));
        float sum = 0.f;
#pragma unroll
        for (int jj = 0; jj < 16; jj++) { r[jj] = expf(r[jj] - mx); sum += r[jj]; }
        sum += __shfl_xor_sync(0xffffffffu, sum, 1);
        float rs = 1.0f / sum;
#pragma unroll
        for (int jj = 0; jj < 16; jj++) ws[t * 33 + j0 + jj] = r[jj] * rs;
    }
    __syncwarp();

    // ---------------- pass 2 ----------------
    {
        const int d0 = (tid & 1) * 32;
        float wreg[32];
#pragma unroll
        for (int j = 0; j < 32; j++) wreg[j] = ws[t * 33 + j];

        float r[32];
#pragma unroll
        for (int dd = 0; dd < 32; dd++) r[dd] = 0.f;

        // inter-chunk: w[t] @ S^T_prefix
#pragma unroll 8
        for (int j = 0; j < 32; j++) {
            float a = wreg[j];
            const float* sr = &ssT[j * 65 + d0];
#pragma unroll
            for (int dd = 0; dd < 32; dd++) r[dd] += a * sr[dd];
        }
        // intra-chunk causal
        for (int s = 0; s <= smax; s++) {
            const float* pr = &ps[s * 33];
            float a0 = 0.f, a1 = 0.f, a2 = 0.f, a3 = 0.f;
#pragma unroll
            for (int j = 0; j < 32; j += 4) {
                a0 += wreg[j]     * pr[j];
                a1 += wreg[j + 1] * pr[j + 1];
                a2 += wreg[j + 2] * pr[j + 2];
                a3 += wreg[j + 3] * pr[j + 3];
            }
            float a = (a0 + a1) + (a2 + a3);
            if (s <= t) {
                const float* kr = &kvs[s * 64 + d0];
#pragma unroll
                for (int dd = 0; dd < 32; dd++) r[dd] += a * kr[dd];
            }
        }
        const int b = bh >> 4, hh = bh & 15;
        const size_t ob = ((size_t)tgl * 2 + b) * 1024 + hh * 64 + d0;
#pragma unroll
        for (int dd = 0; dd < 32; dd++) {
            float v = r[dd] * inv;
            __nv_bfloat16 h = __float2bfloat16(v);
            g_AThi[ob + dd] = h;
            g_ATlo[ob + dd] = __float2bfloat16(v - __bfloat162float(h));
        }
    }
}

// ---------------------------------------------------------------------------
extern "C" void kernel_launch(void* const* d_in, const int* in_sizes, int n_in,
                              void* d_out, int out_size)
{
    const float* query  = (const float*)d_in[0];
    const float* pquery = (const float*)d_in[1];
    const float* Wpq = (const float*)d_in[2];
    const float* bpq = (const float*)d_in[3];
    const float* Wq  = (const float*)d_in[4];
    const float* bq  = (const float*)d_in[5];
    const float* Wpc = (const float*)d_in[6];
    const float* bpc = (const float*)d_in[7];
    const float* Wc  = (const float*)d_in[8];
    const float* bc  = (const float*)d_in[9];
    const float* Wo  = (const float*)d_in[10];
    const float* bo  = (const float*)d_in[11];
    float* out = (float*)d_out;

    float *p_pq, *p_q, *p_kp, *p_kv;
    __nv_bfloat16 *p_Ahi, *p_Alo, *p_PQhi, *p_PQlo, *p_W3hi, *p_W3lo;
    __nv_bfloat16 *p_WOhi, *p_WOlo, *p_WPQhi, *p_WPQlo, *p_AThi, *p_ATlo;
    cudaGetSymbolAddress((void**)&p_pq,   g_pq);
    cudaGetSymbolAddress((void**)&p_q,    g_q);
    cudaGetSymbolAddress((void**)&p_kp,   g_kp);
    cudaGetSymbolAddress((void**)&p_kv,   g_kv);
    cudaGetSymbolAddress((void**)&p_Ahi,  g_Ahi);
    cudaGetSymbolAddress((void**)&p_Alo,  g_Alo);
    cudaGetSymbolAddress((void**)&p_PQhi, g_PQhi);
    cudaGetSymbolAddress((void**)&p_PQlo, g_PQlo);
    cudaGetSymbolAddress((void**)&p_W3hi, g_W3hi);
    cudaGetSymbolAddress((void**)&p_W3lo, g_W3lo);
    cudaGetSymbolAddress((void**)&p_WOhi, g_WOhi);
    cudaGetSymbolAddress((void**)&p_WOlo, g_WOlo);
    cudaGetSymbolAddress((void**)&p_WPQhi,g_WPQhi);
    cudaGetSymbolAddress((void**)&p_WPQlo,g_WPQlo);
    cudaGetSymbolAddress((void**)&p_AThi, g_AThi);
    cudaGetSymbolAddress((void**)&p_ATlo, g_ATlo);

    const int GEMM_SMEM = 65536;
    const int LS_SMEM = (128 * 64 + 128 * 32) * 4;
    const int FP_SMEM = (128 * 65 + 128 * 64 + 128 * 33 + 64 * 33 + 32 * 65 + 128 * 33) * 4;
    cudaFuncSetAttribute(gemm_mma,   cudaFuncAttributeMaxDynamicSharedMemorySize, GEMM_SMEM);
    cudaFuncSetAttribute(local_sums, cudaFuncAttributeMaxDynamicSharedMemorySize, LS_SMEM);
    cudaFuncSetAttribute(fused_pass, cudaFuncAttributeMaxDynamicSharedMemorySize, FP_SMEM);

    const int NE = E_DIM * E_DIM;

    // fp32 -> bf16 hi/lo conversions (vectorized, exact grids)
    cvt_hilo4<<<(MROWS * E_DIM / 4 + 255) / 256, 256>>>(
        (const float4*)query, (__nv_bfloat162*)p_Ahi, (__nv_bfloat162*)p_Alo, MROWS * E_DIM / 4);
    cvt_hilo4<<<(64 * E_DIM / 4 + 255) / 256, 256>>>(
        (const float4*)pquery, (__nv_bfloat162*)p_PQhi, (__nv_bfloat162*)p_PQlo, 64 * E_DIM / 4);
    cvt_hilo4<<<(NE / 4 + 255) / 256, 256>>>(
        (const float4*)Wq, (__nv_bfloat162*)p_W3hi, (__nv_bfloat162*)p_W3lo, NE / 4);
    cvt_hilo4<<<(NE / 4 + 255) / 256, 256>>>(
        (const float4*)Wpc, (__nv_bfloat162*)(p_W3hi + NE), (__nv_bfloat162*)(p_W3lo + NE), NE / 4);
    cvt_hilo4<<<(NE / 4 + 255) / 256, 256>>>(
        (const float4*)Wc, (__nv_bfloat162*)(p_W3hi + 2 * NE), (__nv_bfloat162*)(p_W3lo + 2 * NE), NE / 4);
    cvt_hilo4<<<(NE / 4 + 255) / 256, 256>>>(
        (const float4*)Wo, (__nv_bfloat162*)p_WOhi, (__nv_bfloat162*)p_WOlo, NE / 4);
    cvt_hilo4<<<(NE / 4 + 255) / 256, 256>>>(
        (const float4*)Wpq, (__nv_bfloat162*)p_WPQhi, (__nv_bfloat162*)p_WPQlo, NE / 4);

    // fused q/kp/kv projections: gridDim.z selects the weight
    gemm_mma<<<dim3(8, 32, 3), 256, GEMM_SMEM>>>(
        p_Ahi, p_Alo, p_W3hi, p_W3lo,
        bq, bpc, bc, p_q, p_kp, p_kv,
        SCALING, 1.0f, 1.0f, MROWS, 1, T_LEN);

    // pq projection (M=64, padded to one 128-row block)
    gemm_mma<<<dim3(8, 1, 1), 256, GEMM_SMEM>>>(
        p_PQhi, p_PQlo, p_WPQhi, p_WPQlo,
        bpq, bpq, bpq, p_pq, p_pq, p_pq,
        SCALING, SCALING, SCALING, 64, 1, PLEN);

    // pattn
    pattn_kernel<<<dim3(T_LEN / 64, BH), 256>>>();

    // chunk states + scan
    local_sums<<<dim3(NCH, BH), 256, LS_SMEM>>>();
    scan_states<<<BH, 512>>>();

    // fused pass1 + softmax + pass2
    fused_pass<<<dim3(NCH, BH), 256, FP_SMEM>>>();

    // output projection -> d_out
    gemm_mma<<<dim3(8, 32, 1), 256, GEMM_SMEM>>>(
        p_AThi, p_ATlo, p_WOhi, p_WOlo,
        bo, bo, bo, out, out, out,
        1.0f, 1.0f, 1.0f, MROWS, 0, 0);
}

// round 5
// speedup vs baseline: 2.3893x; 1.0820x over previous
#include <cuda_runtime.h>
#include <cuda_bf16.h>
#include <math.h>
#include <stdint.h>

// Problem constants (fixed shapes per reference setup_inputs)
#define T_LEN  2048
#define BSZ    2
#define E_DIM  1024
#define H_NUM  16
#define D_DIM  64
#define PLEN   32
#define BH     32
#define CHUNK  128
#define NCH    (T_LEN/CHUNK)
#define SCALING 0.125f
#define BETA    0.6931471805599453f

#define MROWS  (T_LEN*BSZ)      // 4096

// ------------------------- scratch (no cudaMalloc allowed) -----------------
__device__ float g_pq   [BH*PLEN*D_DIM];
__device__ float g_q    [BH*T_LEN*D_DIM];
__device__ float g_kp   [BH*T_LEN*D_DIM];
__device__ float g_kv   [BH*T_LEN*D_DIM];
__device__ float g_pattn[BH*T_LEN*PLEN];
__device__ float g_S    [BH*NCH*D_DIM*PLEN];

// bf16 hi/lo planes
__device__ __nv_bfloat16 g_Ahi [MROWS*E_DIM];
__device__ __nv_bfloat16 g_Alo [MROWS*E_DIM];
__device__ __nv_bfloat16 g_PQhi[64*E_DIM];
__device__ __nv_bfloat16 g_PQlo[64*E_DIM];
__device__ __nv_bfloat16 g_W3hi[3*E_DIM*E_DIM];   // Wq, Wpc, Wc stacked
__device__ __nv_bfloat16 g_W3lo[3*E_DIM*E_DIM];
__device__ __nv_bfloat16 g_WOhi[E_DIM*E_DIM];
__device__ __nv_bfloat16 g_WOlo[E_DIM*E_DIM];
__device__ __nv_bfloat16 g_WPQhi[E_DIM*E_DIM];
__device__ __nv_bfloat16 g_WPQlo[E_DIM*E_DIM];
__device__ __nv_bfloat16 g_AThi[MROWS*E_DIM];
__device__ __nv_bfloat16 g_ATlo[MROWS*E_DIM];

// ------------------------- helpers -----------------------------------------
__device__ __forceinline__ uint32_t smem_u32(const void* p) {
    uint32_t a;
    asm("{ .reg .u64 t; cvta.to.shared.u64 t, %1; cvt.u32.u64 %0, t; }"
        : "=r"(a) : "l"(p));
    return a;
}
__device__ __forceinline__ uint32_t sw128(uint32_t off) {
    return off ^ ((off >> 3) & 0x70);
}
__device__ __forceinline__ void ldsm_x4(uint32_t* r, uint32_t addr) {
    asm volatile("ldmatrix.sync.aligned.m8n8.x4.shared.b16 {%0,%1,%2,%3}, [%4];"
                 : "=r"(r[0]), "=r"(r[1]), "=r"(r[2]), "=r"(r[3]) : "r"(addr));
}
__device__ __forceinline__ void mma16816(float* c, const uint32_t* a, const uint32_t* b) {
    asm volatile("mma.sync.aligned.m16n8k16.row.col.f32.bf16.bf16.f32 "
                 "{%0,%1,%2,%3}, {%4,%5,%6,%7}, {%8,%9}, {%0,%1,%2,%3};"
                 : "+f"(c[0]), "+f"(c[1]), "+f"(c[2]), "+f"(c[3])
                 : "r"(a[0]), "r"(a[1]), "r"(a[2]), "r"(a[3]), "r"(b[0]), "r"(b[1]));
}
__device__ __forceinline__ void cp16(uint32_t dst, const void* src, int sz) {
    asm volatile("cp.async.cg.shared.global [%0], [%1], 16, %2;"
                 :: "r"(dst), "l"(src), "r"(sz));
}
__device__ __forceinline__ void cp_commit() {
    asm volatile("cp.async.commit_group;" ::: "memory");
}
__device__ __forceinline__ void cp_wait1() {
    asm volatile("cp.async.wait_group 1;" ::: "memory");
}
__device__ __forceinline__ void cp_wait0() {
    asm volatile("cp.async.wait_group 0;" ::: "memory");
}

// ------------------------- fp32 -> bf16 hi/lo converter (vectorized) -------
__global__ __launch_bounds__(256)
void cvt_hilo4(const float4* __restrict__ src, __nv_bfloat162* __restrict__ hi,
               __nv_bfloat162* __restrict__ lo, int n4)
{
    int i = blockIdx.x * 256 + threadIdx.x;
    if (i >= n4) return;
    float4 v = src[i];
    __nv_bfloat16 h0 = __float2bfloat16(v.x);
    __nv_bfloat16 h1 = __float2bfloat16(v.y);
    __nv_bfloat16 h2 = __float2bfloat16(v.z);
    __nv_bfloat16 h3 = __float2bfloat16(v.w);
    __nv_bfloat16 l0 = __float2bfloat16(v.x - __bfloat162float(h0));
    __nv_bfloat16 l1 = __float2bfloat16(v.y - __bfloat162float(h1));
    __nv_bfloat16 l2 = __float2bfloat16(v.z - __bfloat162float(h2));
    __nv_bfloat16 l3 = __float2bfloat16(v.w - __bfloat162float(h3));
    hi[2 * i]     = __nv_bfloat162(h0, h1);
    hi[2 * i + 1] = __nv_bfloat162(h2, h3);
    lo[2 * i]     = __nv_bfloat162(l0, l1);
    lo[2 * i + 1] = __nv_bfloat162(l2, l3);
}

// ------------------------- pipelined split-bf16 GEMM ------------------------
// C_z = (A @ W_z^T + bias_z) * scale_z.  A: Mx1024 (hi/lo), W_z: 1024x1024 (hi/lo).
// k-tile 32; smem row = 128B: [hi 64B | lo 64B]; 3-stage cp.async pipeline,
// single __syncthreads per k-iter.
// mode 0: out[m*1024+n]
// mode 1: m=(t,b), n=(h,d) -> out[((b*16+h)*Trows + t)*64 + d]
__device__ __forceinline__ void g_load_stage(
    uint32_t sb, int slot,
    const __nv_bfloat16* Ahi, const __nv_bfloat16* Alo,
    const __nv_bfloat16* Bhi, const __nv_bfloat16* Blo,
    int bm, int bn, int kb, int M, int tid)
{
    const uint32_t abase = sb + slot * 32768;
    const uint32_t bbase = abase + 16384;
    const int c  = tid & 7;           // 16B column within 128B row
    const int r0 = tid >> 3;          // base row (0..31), step 32
    const int kc = kb + (c & 3) * 8;  // element column
    const __nv_bfloat16* ap = (c & 4) ? Alo : Ahi;
    const __nv_bfloat16* bp = (c & 4) ? Blo : Bhi;
#pragma unroll
    for (int ii = 0; ii < 4; ii++) {
        int r = r0 + ii * 32;
        uint32_t so = sw128((uint32_t)(r * 128 + c * 16));
        int m = bm + r;
        int mc = (m < M) ? m : (M - 1);
        cp16(abase + so, ap + (size_t)mc * E_DIM + kc, (m < M) ? 16 : 0);
        cp16(bbase + so, bp + (size_t)(bn + r) * E_DIM + kc, 16);
    }
}

__global__ __launch_bounds__(256, 2)
void gemm_mma(const __nv_bfloat16* __restrict__ Ahi, const __nv_bfloat16* __restrict__ Alo,
              const __nv_bfloat16* __restrict__ Whi, const __nv_bfloat16* __restrict__ Wlo,
              const float* b0, const float* b1, const float* b2,
              float* o0, float* o1, float* o2,
              float s0, float s1, float s2,
              int M, int mode, int Trows)
{
    extern __shared__ char smem[];
    const uint32_t sb = smem_u32(smem);

    const int tid = threadIdx.x, wid = tid >> 5, lane = tid & 31;
    const int bm = blockIdx.y * 128, bn = blockIdx.x * 128;
    const int z = blockIdx.z;
    const __nv_bfloat16* wh = Whi + (size_t)z * E_DIM * E_DIM;
    const __nv_bfloat16* wl = Wlo + (size_t)z * E_DIM * E_DIM;
    const float* bias = (z == 0) ? b0 : ((z == 1) ? b1 : b2);
    float* out        = (z == 0) ? o0 : ((z == 1) ? o1 : o2);
    const float scale = (z == 0) ? s0 : ((z == 1) ? s1 : s2);

    const int warpM = (wid >> 2) * 64;   // 0 / 64
    const int warpN = (wid & 3) * 32;    // 0 / 32 / 64 / 96
    const int li = lane >> 3, lr = lane & 7;

    float acc[4][4][4];
#pragma unroll
    for (int i = 0; i < 4; i++)
#pragma unroll
        for (int j = 0; j < 4; j++)
#pragma unroll
            for (int k = 0; k < 4; k++) acc[i][j][k] = 0.f;

    const int NK = E_DIM / 32;  // 32 k-iters
    g_load_stage(sb, 0, Ahi, Alo, wh, wl, bm, bn, 0, M, tid);
    cp_commit();
    g_load_stage(sb, 1, Ahi, Alo, wh, wl, bm, bn, 32, M, tid);
    cp_commit();

    int slot = 0, next = 2;
    for (int ks = 0; ks < NK; ks++) {
        if (ks + 1 < NK) cp_wait1(); else cp_wait0();
        __syncthreads();
        if (ks + 2 < NK) {
            g_load_stage(sb, next, Ahi, Alo, wh, wl, bm, bn, (ks + 2) * 32, M, tid);
            cp_commit();
            if (++next == 3) next = 0;
        }

        const uint32_t abase = sb + slot * 32768;
        const uint32_t bbase = abase + 16384;
        if (++slot == 3) slot = 0;
#pragma unroll
        for (int kk = 0; kk < 2; kk++) {
            uint32_t bh[2][4], bl[2][4];
            const uint32_t kb2 = (uint32_t)(kk * 32 + (li & 1) * 16);
#pragma unroll
            for (int jn = 0; jn < 2; jn++) {
                uint32_t off = (uint32_t)((warpN + jn * 16 + (li >> 1) * 8 + lr) * 128) + kb2;
                ldsm_x4(bh[jn], bbase + sw128(off));
                ldsm_x4(bl[jn], bbase + sw128(off + 64));
            }
            const uint32_t ka = (uint32_t)(kk * 32 + (li >> 1) * 16);
#pragma unroll
            for (int i = 0; i < 4; i++) {
                uint32_t ah[4], al[4];
                uint32_t off = (uint32_t)((warpM + i * 16 + (li & 1) * 8 + lr) * 128) + ka;
                ldsm_x4(ah, abase + sw128(off));
                ldsm_x4(al, abase + sw128(off + 64));
#pragma unroll
                for (int j = 0; j < 4; j++) {
                    const uint32_t* Bh = &bh[j >> 1][(j & 1) * 2];
                    const uint32_t* Bl = &bl[j >> 1][(j & 1) * 2];
                    mma16816(acc[i][j], ah, Bh);
                    mma16816(acc[i][j], ah, Bl);
                    mma16816(acc[i][j], al, Bh);
                }
            }
        }
    }

    // ---- epilogue (float2 stores) ----
    const int g = lane >> 2, tg = lane & 3;
#pragma unroll
    for (int i = 0; i < 4; i++) {
#pragma unroll
        for (int j = 0; j < 4; j++) {
            int n0 = bn + warpN + j * 8 + tg * 2;
            float bx = bias[n0], by = bias[n0 + 1];
#pragma unroll
            for (int half = 0; half < 2; half++) {
                int m = bm + warpM + i * 16 + g + half * 8;
                if (m >= M) continue;
                float2 v;
                v.x = (acc[i][j][half * 2 + 0] + bx) * scale;
                v.y = (acc[i][j][half * 2 + 1] + by) * scale;
                if (mode == 0) {
                    *(float2*)&out[(size_t)m * E_DIM + n0] = v;
                } else {
                    int t = m >> 1, b = m & 1;
                    int h = n0 >> 6, d = n0 & 63;
                    *(float2*)&out[(size_t)((b * 16 + h) * Trows + t) * 64 + d] = v;
                }
            }
        }
    }
}

// ------------------------- pattn = softplus(beta * kp@pq^T)/beta -----------
__global__ __launch_bounds__(256)
void pattn_kernel()
{
    const int bh = blockIdx.y;
    const int t0 = blockIdx.x * 64;
    __shared__ float pqs[PLEN][D_DIM + 1];
    __shared__ float kps[64][D_DIM + 1];

    for (int i = threadIdx.x; i < PLEN * D_DIM; i += 256)
        pqs[i / D_DIM][i % D_DIM] = g_pq[(size_t)bh * PLEN * D_DIM + i];
    for (int i = threadIdx.x; i < 64 * D_DIM; i += 256) {
        int tt = i / D_DIM, d = i % D_DIM;
        kps[tt][d] = g_kp[((size_t)bh * T_LEN + t0 + tt) * D_DIM + d];
    }
    __syncthreads();

    const int t  = threadIdx.x >> 2;
    const int p0 = (threadIdx.x & 3) * 8;
#pragma unroll
    for (int pp = 0; pp < 8; pp++) {
        int p = p0 + pp;
        float a0 = 0.f, a1 = 0.f, a2 = 0.f, a3 = 0.f;
#pragma unroll
        for (int d = 0; d < 64; d += 4) {
            a0 += kps[t][d]     * pqs[p][d];
            a1 += kps[t][d + 1] * pqs[p][d + 1];
            a2 += kps[t][d + 2] * pqs[p][d + 2];
            a3 += kps[t][d + 3] * pqs[p][d + 3];
        }
        float accv = (a0 + a1) + (a2 + a3);
        float zz = BETA * accv;
        float sp = fmaxf(zz, 0.f) + log1pf(expf(-fabsf(zz)));
        g_pattn[((size_t)bh * T_LEN + t0 + t) * PLEN + p] = sp * (1.0f / BETA);
    }
}

// ------------------- chunk-local state: L = KV^T @ P (64x32) ---------------
__global__ __launch_bounds__(256)
void local_sums()
{
    const int c = blockIdx.x, bh = blockIdx.y;
    extern __shared__ float sm[];
    float* kvs = sm;
    float* ps  = sm + 128 * 64;
    const size_t base = (size_t)bh * T_LEN + c * CHUNK;

    for (int i = threadIdx.x; i < 128 * 64; i += 256) kvs[i] = g_kv[base * 64 + i];
    for (int i = threadIdx.x; i < 128 * 32; i += 256) ps[i]  = g_pattn[base * 32 + i];
    __syncthreads();

    const int d  = threadIdx.x >> 2;
    const int j0 = (threadIdx.x & 3) * 8;
    float acc[8] = {0.f};
    for (int s = 0; s < 128; s++) {
        float a = kvs[s * 64 + d];
#pragma unroll
        for (int jj = 0; jj < 8; jj++) acc[jj] += a * ps[s * 32 + j0 + jj];
    }
    float* out = &g_S[((size_t)bh * NCH + c) * (64 * 32)];
#pragma unroll
    for (int jj = 0; jj < 8; jj++) out[d * 32 + j0 + jj] = acc[jj];
}

// ------------------- exclusive prefix scan over chunks ---------------------
__global__ void scan_states()
{
    const int bh = blockIdx.x;
    for (int r = 0; r < 4; r++) {
        int e = threadIdx.x + r * 512;
        float run = 0.f;
        for (int c = 0; c < NCH; c++) {
            float* p = &g_S[(((size_t)bh * NCH) + c) * 2048 + e];
            float v = *p;
            *p = run;
            run += v;
        }
    }
}

// ------------------- fused pass1 + softmax + pass2 --------------------------
__global__ __launch_bounds__(256)
void fused_pass()
{
    const int c = blockIdx.x, bh = blockIdx.y;
    extern __shared__ float sm[];
    float* qs  = sm;                 // 128 x 65
    float* kvs = qs  + 128 * 65;     // 128 x 64
    float* ps  = kvs + 128 * 64;     // 128 x 33
    float* ss  = ps  + 128 * 33;     // 64 x 33   (pass1: [d][j])
    float* ssT = ss  + 64 * 33;      // 32 x 65   (pass2: [j][d])
    float* ws  = ssT + 32 * 65;      // 128 x 33
    const size_t base = (size_t)bh * T_LEN + c * CHUNK;
    const int tid = threadIdx.x;

    for (int i = tid; i < 128 * 64; i += 256) {
        int s = i >> 6, d = i & 63;
        kvs[i] = g_kv[(base + s) * 64 + d];
        qs[s * 65 + d] = g_q[(base + s) * 64 + d];
    }
    for (int i = tid; i < 128 * 32; i += 256) {
        int s = i >> 5, j = i & 31;
        ps[s * 33 + j] = g_pattn[base * 32 + i];
    }
    for (int i = tid; i < 64 * 32; i += 256) {
        int d = i >> 5, j = i & 31;
        float v = g_S[((size_t)bh * NCH + c) * 2048 + i];
        ss[d * 33 + j]  = v;
        ssT[j * 65 + d] = v;
    }
    __syncthreads();

    const int t   = tid >> 1;
    const int tgl = c * CHUNK + t;
    const float inv = 1.0f / (float)(tgl + 1);
    const int smax = t | 15;   // uniform within warp

    // ---------------- pass 1 ----------------
    {
        const int j0 = (tid & 1) * 16;
        float qreg[64];
#pragma unroll
        for (int d = 0; d < 64; d++) qreg[d] = qs[t * 65 + d];

        float r[16];
#pragma unroll
        for (int jj = 0; jj < 16; jj++) r[jj] = 0.f;

#pragma unroll 8
        for (int d = 0; d < 64; d++) {
            float a = qreg[d];
#pragma unroll
            for (int jj = 0; jj < 16; jj++) r[jj] += a * ss[d * 33 + j0 + jj];
        }
        for (int s = 0; s <= smax; s++) {
            const float* kr = &kvs[s * 64];
            float a0 = 0.f, a1 = 0.f, a2 = 0.f, a3 = 0.f;
#pragma unroll
            for (int d = 0; d < 64; d += 4) {
                a0 += qreg[d]     * kr[d];
                a1 += qreg[d + 1] * kr[d + 1];
                a2 += qreg[d + 2] * kr[d + 2];
                a3 += qreg[d + 3] * kr[d + 3];
            }
            float a = (a0 + a1) + (a2 + a3);
            if (s <= t) {
                const float* pr = &ps[s * 33 + j0];
#pragma unroll
                for (int jj = 0; jj < 16; jj++) r[jj] += a * pr[jj];
            }
        }
        float mx = -1e30f;
#pragma unroll
        for (int jj = 0; jj < 16; jj++) { r[jj] *= inv; mx = fmaxf(mx, r[jj]); }
        mx = fmaxf(mx, __shfl_xor_sync(0xffffffffu, mx, 1));
        float sum = 0.f;
#pragma unroll
        for (int jj = 0; jj < 16; jj++) { r[jj] = expf(r[jj] - mx); sum += r[jj]; }
        sum += __shfl_xor_sync(0xffffffffu, sum, 1);
        float rs = 1.0f / sum;
#pragma unroll
        for (int jj = 0; jj < 16; jj++) ws[t * 33 + j0 + jj] = r[jj] * rs;
    }
    __syncwarp();

    // ---------------- pass 2 ----------------
    {
        const int d0 = (tid & 1) * 32;
        float wreg[32];
#pragma unroll
        for (int j = 0; j < 32; j++) wreg[j] = ws[t * 33 + j];

        float r[32];
#pragma unroll
        for (int dd = 0; dd < 32; dd++) r[dd] = 0.f;

#pragma unroll 8
        for (int j = 0; j < 32; j++) {
            float a = wreg[j];
            const float* sr = &ssT[j * 65 + d0];
#pragma unroll
            for (int dd = 0; dd < 32; dd++) r[dd] += a * sr[dd];
        }
        for (int s = 0; s <= smax; s++) {
            const float* pr = &ps[s * 33];
            float a0 = 0.f, a1 = 0.f, a2 = 0.f, a3 = 0.f;
#pragma unroll
            for (int j = 0; j < 32; j += 4) {
                a0 += wreg[j]     * pr[j];
                a1 += wreg[j + 1] * pr[j + 1];
                a2 += wreg[j + 2] * pr[j + 2];
                a3 += wreg[j + 3] * pr[j + 3];
            }
            float a = (a0 + a1) + (a2 + a3);
            if (s <= t) {
                const float* kr = &kvs[s * 64 + d0];
#pragma unroll
                for (int dd = 0; dd < 32; dd++) r[dd] += a * kr[dd];
            }
        }
        const int b = bh >> 4, hh = bh & 15;
        const size_t ob = ((size_t)tgl * 2 + b) * 1024 + hh * 64 + d0;
#pragma unroll
        for (int dd = 0; dd < 32; dd++) {
            float v = r[dd] * inv;
            __nv_bfloat16 h = __float2bfloat16(v);
            g_AThi[ob + dd] = h;
            g_ATlo[ob + dd] = __float2bfloat16(v - __bfloat162float(h));
        }
    }
}

// ---------------------------------------------------------------------------
extern "C" void kernel_launch(void* const* d_in, const int* in_sizes, int n_in,
                              void* d_out, int out_size)
{
    const float* query  = (const float*)d_in[0];
    const float* pquery = (const float*)d_in[1];
    const float* Wpq = (const float*)d_in[2];
    const float* bpq = (const float*)d_in[3];
    const float* Wq  = (const float*)d_in[4];
    const float* bq  = (const float*)d_in[5];
    const float* Wpc = (const float*)d_in[6];
    const float* bpc = (const float*)d_in[7];
    const float* Wc  = (const float*)d_in[8];
    const float* bc  = (const float*)d_in[9];
    const float* Wo  = (const float*)d_in[10];
    const float* bo  = (const float*)d_in[11];
    float* out = (float*)d_out;

    float *p_pq, *p_q, *p_kp, *p_kv;
    __nv_bfloat16 *p_Ahi, *p_Alo, *p_PQhi, *p_PQlo, *p_W3hi, *p_W3lo;
    __nv_bfloat16 *p_WOhi, *p_WOlo, *p_WPQhi, *p_WPQlo, *p_AThi, *p_ATlo;
    cudaGetSymbolAddress((void**)&p_pq,   g_pq);
    cudaGetSymbolAddress((void**)&p_q,    g_q);
    cudaGetSymbolAddress((void**)&p_kp,   g_kp);
    cudaGetSymbolAddress((void**)&p_kv,   g_kv);
    cudaGetSymbolAddress((void**)&p_Ahi,  g_Ahi);
    cudaGetSymbolAddress((void**)&p_Alo,  g_Alo);
    cudaGetSymbolAddress((void**)&p_PQhi, g_PQhi);
    cudaGetSymbolAddress((void**)&p_PQlo, g_PQlo);
    cudaGetSymbolAddress((void**)&p_W3hi, g_W3hi);
    cudaGetSymbolAddress((void**)&p_W3lo, g_W3lo);
    cudaGetSymbolAddress((void**)&p_WOhi, g_WOhi);
    cudaGetSymbolAddress((void**)&p_WOlo, g_WOlo);
    cudaGetSymbolAddress((void**)&p_WPQhi,g_WPQhi);
    cudaGetSymbolAddress((void**)&p_WPQlo,g_WPQlo);
    cudaGetSymbolAddress((void**)&p_AThi, g_AThi);
    cudaGetSymbolAddress((void**)&p_ATlo, g_ATlo);

    const int GEMM_SMEM = 3 * 32768;   // 98304
    const int LS_SMEM = (128 * 64 + 128 * 32) * 4;
    const int FP_SMEM = (128 * 65 + 128 * 64 + 128 * 33 + 64 * 33 + 32 * 65 + 128 * 33) * 4;
    cudaFuncSetAttribute(gemm_mma,   cudaFuncAttributeMaxDynamicSharedMemorySize, GEMM_SMEM);
    cudaFuncSetAttribute(local_sums, cudaFuncAttributeMaxDynamicSharedMemorySize, LS_SMEM);
    cudaFuncSetAttribute(fused_pass, cudaFuncAttributeMaxDynamicSharedMemorySize, FP_SMEM);

    const int NE = E_DIM * E_DIM;

    // fp32 -> bf16 hi/lo conversions (vectorized, exact grids)
    cvt_hilo4<<<(MROWS * E_DIM / 4 + 255) / 256, 256>>>(
        (const float4*)query, (__nv_bfloat162*)p_Ahi, (__nv_bfloat162*)p_Alo, MROWS * E_DIM / 4);
    cvt_hilo4<<<(64 * E_DIM / 4 + 255) / 256, 256>>>(
        (const float4*)pquery, (__nv_bfloat162*)p_PQhi, (__nv_bfloat162*)p_PQlo, 64 * E_DIM / 4);
    cvt_hilo4<<<(NE / 4 + 255) / 256, 256>>>(
        (const float4*)Wq, (__nv_bfloat162*)p_W3hi, (__nv_bfloat162*)p_W3lo, NE / 4);
    cvt_hilo4<<<(NE / 4 + 255) / 256, 256>>>(
        (const float4*)Wpc, (__nv_bfloat162*)(p_W3hi + NE), (__nv_bfloat162*)(p_W3lo + NE), NE / 4);
    cvt_hilo4<<<(NE / 4 + 255) / 256, 256>>>(
        (const float4*)Wc, (__nv_bfloat162*)(p_W3hi + 2 * NE), (__nv_bfloat162*)(p_W3lo + 2 * NE), NE / 4);
    cvt_hilo4<<<(NE / 4 + 255) / 256, 256>>>(
        (const float4*)Wo, (__nv_bfloat162*)p_WOhi, (__nv_bfloat162*)p_WOlo, NE / 4);
    cvt_hilo4<<<(NE / 4 + 255) / 256, 256>>>(
        (const float4*)Wpq, (__nv_bfloat162*)p_WPQhi, (__nv_bfloat162*)p_WPQlo, NE / 4);

    // fused q/kp/kv projections: gridDim.z selects the weight
    gemm_mma<<<dim3(8, 32, 3), 256, GEMM_SMEM>>>(
        p_Ahi, p_Alo, p_W3hi, p_W3lo,
        bq, bpc, bc, p_q, p_kp, p_kv,
        SCALING, 1.0f, 1.0f, MROWS, 1, T_LEN);

    // pq projection (M=64, padded to one 128-row block)
    gemm_mma<<<dim3(8, 1, 1), 256, GEMM_SMEM>>>(
        p_PQhi, p_PQlo, p_WPQhi, p_WPQlo,
        bpq, bpq, bpq, p_pq, p_pq, p_pq,
        SCALING, SCALING, SCALING, 64, 1, PLEN);

    // pattn
    pattn_kernel<<<dim3(T_LEN / 64, BH), 256>>>();

    // chunk states + scan
    local_sums<<<dim3(NCH, BH), 256, LS_SMEM>>>();
    scan_states<<<BH, 512>>>();

    // fused pass1 + softmax + pass2
    fused_pass<<<dim3(NCH, BH), 256, FP_SMEM>>>();

    // output projection -> d_out
    gemm_mma<<<dim3(8, 32, 1), 256, GEMM_SMEM>>>(
        p_AThi, p_ATlo, p_WOhi, p_WOlo,
        bo, bo, bo, out, out, out,
        1.0f, 1.0f, 1.0f, MROWS, 0, 0);
}

// round 6
// speedup vs baseline: 2.5741x; 1.0773x over previous
#include <cuda_runtime.h>
#include <cuda_bf16.h>
#include <math.h>
#include <stdint.h>

// Problem constants (fixed shapes per reference setup_inputs)
#define T_LEN  2048
#define BSZ    2
#define E_DIM  1024
#define H_NUM  16
#define D_DIM  64
#define PLEN   32
#define BH     32
#define CHUNK  64
#define NCH    (T_LEN/CHUNK)   // 32
#define SCALING 0.125f
#define BETA    0.6931471805599453f

#define MROWS  (T_LEN*BSZ)      // 4096

// ------------------------- scratch (no cudaMalloc allowed) -----------------
__device__ float g_pq   [BH*PLEN*D_DIM];
__device__ float g_q    [BH*T_LEN*D_DIM];
__device__ float g_kp   [BH*T_LEN*D_DIM];
__device__ float g_kv   [BH*T_LEN*D_DIM];
__device__ float g_pattn[BH*T_LEN*PLEN];
__device__ float g_S    [BH*NCH*D_DIM*PLEN];

// bf16 hi/lo planes
__device__ __nv_bfloat16 g_Ahi [MROWS*E_DIM];
__device__ __nv_bfloat16 g_Alo [MROWS*E_DIM];
__device__ __nv_bfloat16 g_PQhi[64*E_DIM];
__device__ __nv_bfloat16 g_PQlo[64*E_DIM];
__device__ __nv_bfloat16 g_W3hi[3*E_DIM*E_DIM];   // Wq, Wpc, Wc stacked
__device__ __nv_bfloat16 g_W3lo[3*E_DIM*E_DIM];
__device__ __nv_bfloat16 g_WOhi[E_DIM*E_DIM];
__device__ __nv_bfloat16 g_WOlo[E_DIM*E_DIM];
__device__ __nv_bfloat16 g_WPQhi[E_DIM*E_DIM];
__device__ __nv_bfloat16 g_WPQlo[E_DIM*E_DIM];
__device__ __nv_bfloat16 g_AThi[MROWS*E_DIM];
__device__ __nv_bfloat16 g_ATlo[MROWS*E_DIM];

// ------------------------- helpers -----------------------------------------
__device__ __forceinline__ uint32_t smem_u32(const void* p) {
    uint32_t a;
    asm("{ .reg .u64 t; cvta.to.shared.u64 t, %1; cvt.u32.u64 %0, t; }"
        : "=r"(a) : "l"(p));
    return a;
}
__device__ __forceinline__ uint32_t sw128(uint32_t off) {
    return off ^ ((off >> 3) & 0x70);
}
__device__ __forceinline__ void ldsm_x4(uint32_t* r, uint32_t addr) {
    asm volatile("ldmatrix.sync.aligned.m8n8.x4.shared.b16 {%0,%1,%2,%3}, [%4];"
                 : "=r"(r[0]), "=r"(r[1]), "=r"(r[2]), "=r"(r[3]) : "r"(addr));
}
__device__ __forceinline__ void mma16816(float* c, const uint32_t* a, const uint32_t* b) {
    asm volatile("mma.sync.aligned.m16n8k16.row.col.f32.bf16.bf16.f32 "
                 "{%0,%1,%2,%3}, {%4,%5,%6,%7}, {%8,%9}, {%0,%1,%2,%3};"
                 : "+f"(c[0]), "+f"(c[1]), "+f"(c[2]), "+f"(c[3])
                 : "r"(a[0]), "r"(a[1]), "r"(a[2]), "r"(a[3]), "r"(b[0]), "r"(b[1]));
}
__device__ __forceinline__ void cp16(uint32_t dst, const void* src, int sz) {
    asm volatile("cp.async.cg.shared.global [%0], [%1], 16, %2;"
                 :: "r"(dst), "l"(src), "r"(sz));
}
__device__ __forceinline__ void cp_commit() {
    asm volatile("cp.async.commit_group;" ::: "memory");
}
__device__ __forceinline__ void cp_wait1() {
    asm volatile("cp.async.wait_group 1;" ::: "memory");
}
__device__ __forceinline__ void cp_wait0() {
    asm volatile("cp.async.wait_group 0;" ::: "memory");
}

// ------------------------- fp32 -> bf16 hi/lo converter (vectorized) -------
__global__ __launch_bounds__(256)
void cvt_hilo4(const float4* __restrict__ src, __nv_bfloat162* __restrict__ hi,
               __nv_bfloat162* __restrict__ lo, int n4)
{
    int i = blockIdx.x * 256 + threadIdx.x;
    if (i >= n4) return;
    float4 v = src[i];
    __nv_bfloat16 h0 = __float2bfloat16(v.x);
    __nv_bfloat16 h1 = __float2bfloat16(v.y);
    __nv_bfloat16 h2 = __float2bfloat16(v.z);
    __nv_bfloat16 h3 = __float2bfloat16(v.w);
    __nv_bfloat16 l0 = __float2bfloat16(v.x - __bfloat162float(h0));
    __nv_bfloat16 l1 = __float2bfloat16(v.y - __bfloat162float(h1));
    __nv_bfloat16 l2 = __float2bfloat16(v.z - __bfloat162float(h2));
    __nv_bfloat16 l3 = __float2bfloat16(v.w - __bfloat162float(h3));
    hi[2 * i]     = __nv_bfloat162(h0, h1);
    hi[2 * i + 1] = __nv_bfloat162(h2, h3);
    lo[2 * i]     = __nv_bfloat162(l0, l1);
    lo[2 * i + 1] = __nv_bfloat162(l2, l3);
}

// ------------------------- pipelined split-bf16 GEMM ------------------------
__device__ __forceinline__ void g_load_stage(
    uint32_t sb, int slot,
    const __nv_bfloat16* Ahi, const __nv_bfloat16* Alo,
    const __nv_bfloat16* Bhi, const __nv_bfloat16* Blo,
    int bm, int bn, int kb, int M, int tid)
{
    const uint32_t abase = sb + slot * 32768;
    const uint32_t bbase = abase + 16384;
    const int c  = tid & 7;
    const int r0 = tid >> 3;
    const int kc = kb + (c & 3) * 8;
    const __nv_bfloat16* ap = (c & 4) ? Alo : Ahi;
    const __nv_bfloat16* bp = (c & 4) ? Blo : Bhi;
#pragma unroll
    for (int ii = 0; ii < 4; ii++) {
        int r = r0 + ii * 32;
        uint32_t so = sw128((uint32_t)(r * 128 + c * 16));
        int m = bm + r;
        int mc = (m < M) ? m : (M - 1);
        cp16(abase + so, ap + (size_t)mc * E_DIM + kc, (m < M) ? 16 : 0);
        cp16(bbase + so, bp + (size_t)(bn + r) * E_DIM + kc, 16);
    }
}

__global__ __launch_bounds__(256, 2)
void gemm_mma(const __nv_bfloat16* __restrict__ Ahi, const __nv_bfloat16* __restrict__ Alo,
              const __nv_bfloat16* __restrict__ Whi, const __nv_bfloat16* __restrict__ Wlo,
              const float* b0, const float* b1, const float* b2,
              float* o0, float* o1, float* o2,
              float s0, float s1, float s2,
              int M, int mode, int Trows)
{
    extern __shared__ char smem[];
    const uint32_t sb = smem_u32(smem);

    const int tid = threadIdx.x, wid = tid >> 5, lane = tid & 31;
    const int bm = blockIdx.y * 128, bn = blockIdx.x * 128;
    const int z = blockIdx.z;
    const __nv_bfloat16* wh = Whi + (size_t)z * E_DIM * E_DIM;
    const __nv_bfloat16* wl = Wlo + (size_t)z * E_DIM * E_DIM;
    const float* bias = (z == 0) ? b0 : ((z == 1) ? b1 : b2);
    float* out        = (z == 0) ? o0 : ((z == 1) ? o1 : o2);
    const float scale = (z == 0) ? s0 : ((z == 1) ? s1 : s2);

    const int warpM = (wid >> 2) * 64;
    const int warpN = (wid & 3) * 32;
    const int li = lane >> 3, lr = lane & 7;

    float acc[4][4][4];
#pragma unroll
    for (int i = 0; i < 4; i++)
#pragma unroll
        for (int j = 0; j < 4; j++)
#pragma unroll
            for (int k = 0; k < 4; k++) acc[i][j][k] = 0.f;

    const int NK = E_DIM / 32;
    g_load_stage(sb, 0, Ahi, Alo, wh, wl, bm, bn, 0, M, tid);
    cp_commit();
    g_load_stage(sb, 1, Ahi, Alo, wh, wl, bm, bn, 32, M, tid);
    cp_commit();

    int slot = 0, next = 2;
    for (int ks = 0; ks < NK; ks++) {
        if (ks + 1 < NK) cp_wait1(); else cp_wait0();
        __syncthreads();
        if (ks + 2 < NK) {
            g_load_stage(sb, next, Ahi, Alo, wh, wl, bm, bn, (ks + 2) * 32, M, tid);
            cp_commit();
            if (++next == 3) next = 0;
        }

        const uint32_t abase = sb + slot * 32768;
        const uint32_t bbase = abase + 16384;
        if (++slot == 3) slot = 0;
#pragma unroll
        for (int kk = 0; kk < 2; kk++) {
            uint32_t bh[2][4], bl[2][4];
            const uint32_t kb2 = (uint32_t)(kk * 32 + (li & 1) * 16);
#pragma unroll
            for (int jn = 0; jn < 2; jn++) {
                uint32_t off = (uint32_t)((warpN + jn * 16 + (li >> 1) * 8 + lr) * 128) + kb2;
                ldsm_x4(bh[jn], bbase + sw128(off));
                ldsm_x4(bl[jn], bbase + sw128(off + 64));
            }
            const uint32_t ka = (uint32_t)(kk * 32 + (li >> 1) * 16);
#pragma unroll
            for (int i = 0; i < 4; i++) {
                uint32_t ah[4], al[4];
                uint32_t off = (uint32_t)((warpM + i * 16 + (li & 1) * 8 + lr) * 128) + ka;
                ldsm_x4(ah, abase + sw128(off));
                ldsm_x4(al, abase + sw128(off + 64));
#pragma unroll
                for (int j = 0; j < 4; j++) {
                    const uint32_t* Bh = &bh[j >> 1][(j & 1) * 2];
                    const uint32_t* Bl = &bl[j >> 1][(j & 1) * 2];
                    mma16816(acc[i][j], ah, Bh);
                    mma16816(acc[i][j], ah, Bl);
                    mma16816(acc[i][j], al, Bh);
                }
            }
        }
    }

    // ---- epilogue (float2 stores) ----
    const int g = lane >> 2, tg = lane & 3;
#pragma unroll
    for (int i = 0; i < 4; i++) {
#pragma unroll
        for (int j = 0; j < 4; j++) {
            int n0 = bn + warpN + j * 8 + tg * 2;
            float bx = bias[n0], by = bias[n0 + 1];
#pragma unroll
            for (int half = 0; half < 2; half++) {
                int m = bm + warpM + i * 16 + g + half * 8;
                if (m >= M) continue;
                float2 v;
                v.x = (acc[i][j][half * 2 + 0] + bx) * scale;
                v.y = (acc[i][j][half * 2 + 1] + by) * scale;
                if (mode == 0) {
                    *(float2*)&out[(size_t)m * E_DIM + n0] = v;
                } else {
                    int t = m >> 1, b = m & 1;
                    int h = n0 >> 6, d = n0 & 63;
                    *(float2*)&out[(size_t)((b * 16 + h) * Trows + t) * 64 + d] = v;
                }
            }
        }
    }
}

// ------------------------- pattn = softplus(beta * kp@pq^T)/beta -----------
__global__ __launch_bounds__(256)
void pattn_kernel()
{
    const int bh = blockIdx.y;
    const int t0 = blockIdx.x * 64;
    __shared__ float pqs[PLEN][D_DIM + 1];
    __shared__ float kps[64][D_DIM + 1];

    for (int i = threadIdx.x; i < PLEN * D_DIM; i += 256)
        pqs[i / D_DIM][i % D_DIM] = g_pq[(size_t)bh * PLEN * D_DIM + i];
    for (int i = threadIdx.x; i < 64 * D_DIM; i += 256) {
        int tt = i / D_DIM, d = i % D_DIM;
        kps[tt][d] = g_kp[((size_t)bh * T_LEN + t0 + tt) * D_DIM + d];
    }
    __syncthreads();

    const int t  = threadIdx.x >> 2;
    const int p0 = (threadIdx.x & 3) * 8;
#pragma unroll
    for (int pp = 0; pp < 8; pp++) {
        int p = p0 + pp;
        float a0 = 0.f, a1 = 0.f, a2 = 0.f, a3 = 0.f;
#pragma unroll
        for (int d = 0; d < 64; d += 4) {
            a0 += kps[t][d]     * pqs[p][d];
            a1 += kps[t][d + 1] * pqs[p][d + 1];
            a2 += kps[t][d + 2] * pqs[p][d + 2];
            a3 += kps[t][d + 3] * pqs[p][d + 3];
        }
        float accv = (a0 + a1) + (a2 + a3);
        float zz = BETA * accv;
        float sp = fmaxf(zz, 0.f) + log1pf(expf(-fabsf(zz)));
        g_pattn[((size_t)bh * T_LEN + t0 + t) * PLEN + p] = sp * (1.0f / BETA);
    }
}

// ------------------- chunk-local state: L = KV^T @ P (64x32), CHUNK=64 -----
__global__ __launch_bounds__(256)
void local_sums()
{
    const int c = blockIdx.x, bh = blockIdx.y;
    extern __shared__ float sm[];
    float* kvs = sm;               // 64 x 64
    float* ps  = sm + CHUNK * 64;  // 64 x 32
    const size_t base = (size_t)bh * T_LEN + c * CHUNK;

    for (int i = threadIdx.x; i < CHUNK * 64; i += 256) kvs[i] = g_kv[base * 64 + i];
    for (int i = threadIdx.x; i < CHUNK * 32; i += 256) ps[i]  = g_pattn[base * 32 + i];
    __syncthreads();

    const int d  = threadIdx.x >> 2;
    const int j0 = (threadIdx.x & 3) * 8;
    float acc[8] = {0.f};
    for (int s = 0; s < CHUNK; s++) {
        float a = kvs[s * 64 + d];
#pragma unroll
        for (int jj = 0; jj < 8; jj++) acc[jj] += a * ps[s * 32 + j0 + jj];
    }
    float* out = &g_S[((size_t)bh * NCH + c) * (64 * 32)];
#pragma unroll
    for (int jj = 0; jj < 8; jj++) out[d * 32 + j0 + jj] = acc[jj];
}

// ------------------- exclusive prefix scan over chunks ---------------------
__global__ void scan_states()
{
    const int bh = blockIdx.x;
    for (int r = 0; r < 4; r++) {
        int e = threadIdx.x + r * 512;
        float run = 0.f;
        for (int c = 0; c < NCH; c++) {
            float* p = &g_S[(((size_t)bh * NCH) + c) * 2048 + e];
            float v = *p;
            *p = run;
            run += v;
        }
    }
}

// ------------------- fused pass1 + softmax + pass2 (CHUNK=64) ---------------
// 4 threads per row, 64 rows per block.
__global__ __launch_bounds__(256, 2)
void fused_pass()
{
    const int c = blockIdx.x, bh = blockIdx.y;
    extern __shared__ float sm[];
    float* qs  = sm;                 // 64 x 65
    float* kvs = qs  + 64 * 65;      // 64 x 64
    float* ps  = kvs + 64 * 64;      // 64 x 33
    float* ss  = ps  + 64 * 33;      // 64 x 33   (pass1: [d][j])
    float* ssT = ss  + 64 * 33;      // 32 x 65   (pass2: [j][d])
    float* ws  = ssT + 32 * 65;      // 64 x 33
    const size_t base = (size_t)bh * T_LEN + c * CHUNK;
    const int tid = threadIdx.x;

    for (int i = tid; i < CHUNK * 64; i += 256) {
        int s = i >> 6, d = i & 63;
        kvs[i] = g_kv[(base + s) * 64 + d];
        qs[s * 65 + d] = g_q[(base + s) * 64 + d];
    }
    for (int i = tid; i < CHUNK * 32; i += 256) {
        int s = i >> 5, j = i & 31;
        ps[s * 33 + j] = g_pattn[base * 32 + i];
    }
    for (int i = tid; i < 64 * 32; i += 256) {
        int d = i >> 5, j = i & 31;
        float v = g_S[((size_t)bh * NCH + c) * 2048 + i];
        ss[d * 33 + j]  = v;
        ssT[j * 65 + d] = v;
    }
    __syncthreads();

    const int t   = tid >> 2;            // 0..63
    const int sub = tid & 3;
    const int tgl = c * CHUNK + t;
    const float inv = 1.0f / (float)(tgl + 1);
    const int smax = t | 7;              // uniform within warp (8 rows/warp)

    // ---------------- pass 1 ----------------
    {
        const int j0 = sub * 8;
        float qreg[64];
#pragma unroll
        for (int d = 0; d < 64; d++) qreg[d] = qs[t * 65 + d];

        float r[8];
#pragma unroll
        for (int jj = 0; jj < 8; jj++) r[jj] = 0.f;

        // inter-chunk: q[t] @ S_prefix
#pragma unroll 8
        for (int d = 0; d < 64; d++) {
            float a = qreg[d];
#pragma unroll
            for (int jj = 0; jj < 8; jj++) r[jj] += a * ss[d * 33 + j0 + jj];
        }
        // intra-chunk causal
        for (int s = 0; s <= smax; s++) {
            const float* kr = &kvs[s * 64];
            float a0 = 0.f, a1 = 0.f, a2 = 0.f, a3 = 0.f;
#pragma unroll
            for (int d = 0; d < 64; d += 4) {
                a0 += qreg[d]     * kr[d];
                a1 += qreg[d + 1] * kr[d + 1];
                a2 += qreg[d + 2] * kr[d + 2];
                a3 += qreg[d + 3] * kr[d + 3];
            }
            float a = (a0 + a1) + (a2 + a3);
            if (s <= t) {
                const float* pr = &ps[s * 33 + j0];
#pragma unroll
                for (int jj = 0; jj < 8; jj++) r[jj] += a * pr[jj];
            }
        }
        // softmax across the 4 sub-lanes of this row
        float mx = -1e30f;
#pragma unroll
        for (int jj = 0; jj < 8; jj++) { r[jj] *= inv; mx = fmaxf(mx, r[jj]); }
        mx = fmaxf(mx, __shfl_xor_sync(0xffffffffu, mx, 1));
        mx = fmaxf(mx, __shfl_xor_sync(0xffffffffu, mx, 2));
        float sum = 0.f;
#pragma unroll
        for (int jj = 0; jj < 8; jj++) { r[jj] = expf(r[jj] - mx); sum += r[jj]; }
        sum += __shfl_xor_sync(0xffffffffu, sum, 1);
        sum += __shfl_xor_sync(0xffffffffu, sum, 2);
        float rs = 1.0f / sum;
#pragma unroll
        for (int jj = 0; jj < 8; jj++) ws[t * 33 + j0 + jj] = r[jj] * rs;
    }
    __syncwarp();

    // ---------------- pass 2 ----------------
    {
        const int d0 = sub * 16;
        float wreg[32];
#pragma unroll
        for (int j = 0; j < 32; j++) wreg[j] = ws[t * 33 + j];

        float r[16];
#pragma unroll
        for (int dd = 0; dd < 16; dd++) r[dd] = 0.f;

        // inter-chunk: w[t] @ S^T_prefix
#pragma unroll 8
        for (int j = 0; j < 32; j++) {
            float a = wreg[j];
            const float* sr = &ssT[j * 65 + d0];
#pragma unroll
            for (int dd = 0; dd < 16; dd++) r[dd] += a * sr[dd];
        }
        // intra-chunk causal
        for (int s = 0; s <= smax; s++) {
            const float* pr = &ps[s * 33];
            float a0 = 0.f, a1 = 0.f, a2 = 0.f, a3 = 0.f;
#pragma unroll
            for (int j = 0; j < 32; j += 4) {
                a0 += wreg[j]     * pr[j];
                a1 += wreg[j + 1] * pr[j + 1];
                a2 += wreg[j + 2] * pr[j + 2];
                a3 += wreg[j + 3] * pr[j + 3];
            }
            float a = (a0 + a1) + (a2 + a3);
            if (s <= t) {
                const float* kr = &kvs[s * 64 + d0];
#pragma unroll
                for (int dd = 0; dd < 16; dd++) r[dd] += a * kr[dd];
            }
        }
        const int b = bh >> 4, hh = bh & 15;
        const size_t ob = ((size_t)tgl * 2 + b) * 1024 + hh * 64 + d0;
#pragma unroll
        for (int dd = 0; dd < 16; dd++) {
            float v = r[dd] * inv;
            __nv_bfloat16 h = __float2bfloat16(v);
            g_AThi[ob + dd] = h;
            g_ATlo[ob + dd] = __float2bfloat16(v - __bfloat162float(h));
        }
    }
}

// ---------------------------------------------------------------------------
extern "C" void kernel_launch(void* const* d_in, const int* in_sizes, int n_in,
                              void* d_out, int out_size)
{
    const float* query  = (const float*)d_in[0];
    const float* pquery = (const float*)d_in[1];
    const float* Wpq = (const float*)d_in[2];
    const float* bpq = (const float*)d_in[3];
    const float* Wq  = (const float*)d_in[4];
    const float* bq  = (const float*)d_in[5];
    const float* Wpc = (const float*)d_in[6];
    const float* bpc = (const float*)d_in[7];
    const float* Wc  = (const float*)d_in[8];
    const float* bc  = (const float*)d_in[9];
    const float* Wo  = (const float*)d_in[10];
    const float* bo  = (const float*)d_in[11];
    float* out = (float*)d_out;

    float *p_pq, *p_q, *p_kp, *p_kv;
    __nv_bfloat16 *p_Ahi, *p_Alo, *p_PQhi, *p_PQlo, *p_W3hi, *p_W3lo;
    __nv_bfloat16 *p_WOhi, *p_WOlo, *p_WPQhi, *p_WPQlo, *p_AThi, *p_ATlo;
    cudaGetSymbolAddress((void**)&p_pq,   g_pq);
    cudaGetSymbolAddress((void**)&p_q,    g_q);
    cudaGetSymbolAddress((void**)&p_kp,   g_kp);
    cudaGetSymbolAddress((void**)&p_kv,   g_kv);
    cudaGetSymbolAddress((void**)&p_Ahi,  g_Ahi);
    cudaGetSymbolAddress((void**)&p_Alo,  g_Alo);
    cudaGetSymbolAddress((void**)&p_PQhi, g_PQhi);
    cudaGetSymbolAddress((void**)&p_PQlo, g_PQlo);
    cudaGetSymbolAddress((void**)&p_W3hi, g_W3hi);
    cudaGetSymbolAddress((void**)&p_W3lo, g_W3lo);
    cudaGetSymbolAddress((void**)&p_WOhi, g_WOhi);
    cudaGetSymbolAddress((void**)&p_WOlo, g_WOlo);
    cudaGetSymbolAddress((void**)&p_WPQhi,g_WPQhi);
    cudaGetSymbolAddress((void**)&p_WPQlo,g_WPQlo);
    cudaGetSymbolAddress((void**)&p_AThi, g_AThi);
    cudaGetSymbolAddress((void**)&p_ATlo, g_ATlo);

    const int GEMM_SMEM = 3 * 32768;   // 98304
    const int LS_SMEM = (CHUNK * 64 + CHUNK * 32) * 4;
    const int FP_SMEM = (64 * 65 + 64 * 64 + 64 * 33 + 64 * 33 + 32 * 65 + 64 * 33) * 4;
    cudaFuncSetAttribute(gemm_mma,   cudaFuncAttributeMaxDynamicSharedMemorySize, GEMM_SMEM);
    cudaFuncSetAttribute(local_sums, cudaFuncAttributeMaxDynamicSharedMemorySize, LS_SMEM);
    cudaFuncSetAttribute(fused_pass, cudaFuncAttributeMaxDynamicSharedMemorySize, FP_SMEM);

    const int NE = E_DIM * E_DIM;

    // launches 0-4: conversions needed by the big GEMM (GEMM3 lands at index 5
    // so ncu -s 5 -c 1 profiles it)
    cvt_hilo4<<<(MROWS * E_DIM / 4 + 255) / 256, 256>>>(
        (const float4*)query, (__nv_bfloat162*)p_Ahi, (__nv_bfloat162*)p_Alo, MROWS * E_DIM / 4);
    cvt_hilo4<<<(64 * E_DIM / 4 + 255) / 256, 256>>>(
        (const float4*)pquery, (__nv_bfloat162*)p_PQhi, (__nv_bfloat162*)p_PQlo, 64 * E_DIM / 4);
    cvt_hilo4<<<(NE / 4 + 255) / 256, 256>>>(
        (const float4*)Wq, (__nv_bfloat162*)p_W3hi, (__nv_bfloat162*)p_W3lo, NE / 4);
    cvt_hilo4<<<(NE / 4 + 255) / 256, 256>>>(
        (const float4*)Wpc, (__nv_bfloat162*)(p_W3hi + NE), (__nv_bfloat162*)(p_W3lo + NE), NE / 4);
    cvt_hilo4<<<(NE / 4 + 255) / 256, 256>>>(
        (const float4*)Wc, (__nv_bfloat162*)(p_W3hi + 2 * NE), (__nv_bfloat162*)(p_W3lo + 2 * NE), NE / 4);

    // launch 5: fused q/kp/kv projections
    gemm_mma<<<dim3(8, 32, 3), 256, GEMM_SMEM>>>(
        p_Ahi, p_Alo, p_W3hi, p_W3lo,
        bq, bpc, bc, p_q, p_kp, p_kv,
        SCALING, 1.0f, 1.0f, MROWS, 1, T_LEN);

    // remaining conversions
    cvt_hilo4<<<(NE / 4 + 255) / 256, 256>>>(
        (const float4*)Wo, (__nv_bfloat162*)p_WOhi, (__nv_bfloat162*)p_WOlo, NE / 4);
    cvt_hilo4<<<(NE / 4 + 255) / 256, 256>>>(
        (const float4*)Wpq, (__nv_bfloat162*)p_WPQhi, (__nv_bfloat162*)p_WPQlo, NE / 4);

    // pq projection (M=64, padded to one 128-row block)
    gemm_mma<<<dim3(8, 1, 1), 256, GEMM_SMEM>>>(
        p_PQhi, p_PQlo, p_WPQhi, p_WPQlo,
        bpq, bpq, bpq, p_pq, p_pq, p_pq,
        SCALING, SCALING, SCALING, 64, 1, PLEN);

    // pattn
    pattn_kernel<<<dim3(T_LEN / 64, BH), 256>>>();

    // chunk states + scan
    local_sums<<<dim3(NCH, BH), 256, LS_SMEM>>>();
    scan_states<<<BH, 512>>>();

    // fused pass1 + softmax + pass2
    fused_pass<<<dim3(NCH, BH), 256, FP_SMEM>>>();

    // output projection -> d_out
    gemm_mma<<<dim3(8, 32, 1), 256, GEMM_SMEM>>>(
        p_AThi, p_ATlo, p_WOhi, p_WOlo,
        bo, bo, bo, out, out, out,
        1.0f, 1.0f, 1.0f, MROWS, 0, 0);
}

// round 7
// speedup vs baseline: 2.8508x; 1.1075x over previous
#include <cuda_runtime.h>
#include <cuda_bf16.h>
#include <math.h>
#include <stdint.h>

#define T_LEN  2048
#define BSZ    2
#define E_DIM  1024
#define H_NUM  16
#define D_DIM  64
#define PLEN   32
#define BH     32
#define CHUNK  64
#define NCH    (T_LEN/CHUNK)   // 32
#define SCALING 0.125f
#define BETA    0.6931471805599453f

#define MROWS  (T_LEN*BSZ)      // 4096
#define NE     (E_DIM*E_DIM)

// ------------------------- scratch -----------------------------------------
__device__ float g_pq   [BH*PLEN*D_DIM];
__device__ float g_q    [BH*T_LEN*D_DIM];
__device__ float g_kp   [BH*T_LEN*D_DIM];
__device__ float g_kv   [BH*T_LEN*D_DIM];
__device__ float g_pattn[BH*T_LEN*PLEN];
__device__ float g_S    [BH*NCH*D_DIM*PLEN];

__device__ __nv_bfloat16 g_Ahi [MROWS*E_DIM];
__device__ __nv_bfloat16 g_Alo [MROWS*E_DIM];
__device__ __nv_bfloat16 g_PQhi[64*E_DIM];
__device__ __nv_bfloat16 g_PQlo[64*E_DIM];
__device__ __nv_bfloat16 g_W4hi[4*NE];   // Wq, Wpc, Wc, Wpq stacked
__device__ __nv_bfloat16 g_W4lo[4*NE];
__device__ __nv_bfloat16 g_WOhi[NE];
__device__ __nv_bfloat16 g_WOlo[NE];
__device__ __nv_bfloat16 g_AThi[MROWS*E_DIM];
__device__ __nv_bfloat16 g_ATlo[MROWS*E_DIM];

// ------------------------- helpers -----------------------------------------
__device__ __forceinline__ uint32_t smem_u32(const void* p) {
    uint32_t a;
    asm("{ .reg .u64 t; cvta.to.shared.u64 t, %1; cvt.u32.u64 %0, t; }"
        : "=r"(a) : "l"(p));
    return a;
}
__device__ __forceinline__ uint32_t sw128(uint32_t off) {
    return off ^ ((off >> 3) & 0x70);
}
__device__ __forceinline__ void ldsm_x4(uint32_t* r, uint32_t addr) {
    asm volatile("ldmatrix.sync.aligned.m8n8.x4.shared.b16 {%0,%1,%2,%3}, [%4];"
                 : "=r"(r[0]), "=r"(r[1]), "=r"(r[2]), "=r"(r[3]) : "r"(addr));
}
__device__ __forceinline__ void mma16816(float* c, const uint32_t* a, const uint32_t* b) {
    asm volatile("mma.sync.aligned.m16n8k16.row.col.f32.bf16.bf16.f32 "
                 "{%0,%1,%2,%3}, {%4,%5,%6,%7}, {%8,%9}, {%0,%1,%2,%3};"
                 : "+f"(c[0]), "+f"(c[1]), "+f"(c[2]), "+f"(c[3])
                 : "r"(a[0]), "r"(a[1]), "r"(a[2]), "r"(a[3]), "r"(b[0]), "r"(b[1]));
}
__device__ __forceinline__ void cp16(uint32_t dst, const void* src, int sz) {
    asm volatile("cp.async.cg.shared.global [%0], [%1], 16, %2;"
                 :: "r"(dst), "l"(src), "r"(sz));
}
__device__ __forceinline__ void cp_commit() {
    asm volatile("cp.async.commit_group;" ::: "memory");
}
__device__ __forceinline__ void cp_wait1() {
    asm volatile("cp.async.wait_group 1;" ::: "memory");
}
__device__ __forceinline__ void cp_wait0() {
    asm volatile("cp.async.wait_group 0;" ::: "memory");
}

// ------------------------- merged fp32 -> bf16 hi/lo converter -------------
#define NCVT 7
struct CvtArgs {
    const float4*    s[NCVT];
    __nv_bfloat162*  h[NCVT];
    __nv_bfloat162*  l[NCVT];
    int              end[NCVT];   // cumulative n4
};

__global__ __launch_bounds__(256)
void cvt_all(CvtArgs A)
{
    int gi = blockIdx.x * 256 + threadIdx.x;
    int seg = 0;
    while (seg < NCVT && gi >= A.end[seg]) seg++;
    if (seg >= NCVT) return;
    int i = gi - (seg ? A.end[seg - 1] : 0);

    float4 v = A.s[seg][i];
    __nv_bfloat16 h0 = __float2bfloat16(v.x);
    __nv_bfloat16 h1 = __float2bfloat16(v.y);
    __nv_bfloat16 h2 = __float2bfloat16(v.z);
    __nv_bfloat16 h3 = __float2bfloat16(v.w);
    __nv_bfloat16 l0 = __float2bfloat16(v.x - __bfloat162float(h0));
    __nv_bfloat16 l1 = __float2bfloat16(v.y - __bfloat162float(h1));
    __nv_bfloat16 l2 = __float2bfloat16(v.z - __bfloat162float(h2));
    __nv_bfloat16 l3 = __float2bfloat16(v.w - __bfloat162float(h3));
    A.h[seg][2 * i]     = __nv_bfloat162(h0, h1);
    A.h[seg][2 * i + 1] = __nv_bfloat162(h2, h3);
    A.l[seg][2 * i]     = __nv_bfloat162(l0, l1);
    A.l[seg][2 * i + 1] = __nv_bfloat162(l2, l3);
}

// ------------------------- pipelined split-bf16 GEMM ------------------------
__device__ __forceinline__ void g_load_stage(
    uint32_t sb, int slot,
    const __nv_bfloat16* Ahi, const __nv_bfloat16* Alo,
    const __nv_bfloat16* Bhi, const __nv_bfloat16* Blo,
    int bm, int bn, int kb, int M, int tid)
{
    const uint32_t abase = sb + slot * 32768;
    const uint32_t bbase = abase + 16384;
    const int c  = tid & 7;
    const int r0 = tid >> 3;
    const int kc = kb + (c & 3) * 8;
    const __nv_bfloat16* ap = (c & 4) ? Alo : Ahi;
    const __nv_bfloat16* bp = (c & 4) ? Blo : Bhi;
#pragma unroll
    for (int ii = 0; ii < 4; ii++) {
        int r = r0 + ii * 32;
        uint32_t so = sw128((uint32_t)(r * 128 + c * 16));
        int m = bm + r;
        int mc = (m < M) ? m : (M - 1);
        cp16(abase + so, ap + (size_t)mc * E_DIM + kc, (m < M) ? 16 : 0);
        cp16(bbase + so, bp + (size_t)(bn + r) * E_DIM + kc, 16);
    }
}

// z = blockIdx.z selects weight slice z and output z; z==3 uses alternate A.
__global__ __launch_bounds__(256, 2)
void gemm_mma(const __nv_bfloat16* __restrict__ A0hi, const __nv_bfloat16* __restrict__ A0lo,
              const __nv_bfloat16* __restrict__ A3hi, const __nv_bfloat16* __restrict__ A3lo,
              const __nv_bfloat16* __restrict__ Whi, const __nv_bfloat16* __restrict__ Wlo,
              const float* b0, const float* b1, const float* b2, const float* b3,
              float* o0, float* o1, float* o2, float* o3,
              float s0, float s1, float s2, float s3,
              int M0, int M3, int mode, int Trows0, int Trows3)
{
    extern __shared__ char smem[];
    const uint32_t sb = smem_u32(smem);

    const int tid = threadIdx.x, wid = tid >> 5, lane = tid & 31;
    const int bm = blockIdx.y * 128, bn = blockIdx.x * 128;
    const int z = blockIdx.z;
    const int M     = (z == 3) ? M3 : M0;
    const int Trows = (z == 3) ? Trows3 : Trows0;
    if (bm >= M) return;
    const __nv_bfloat16* Ahi = (z == 3) ? A3hi : A0hi;
    const __nv_bfloat16* Alo = (z == 3) ? A3lo : A0lo;
    const __nv_bfloat16* wh = Whi + (size_t)z * NE;
    const __nv_bfloat16* wl = Wlo + (size_t)z * NE;
    const float* bias = (z == 0) ? b0 : ((z == 1) ? b1 : ((z == 2) ? b2 : b3));
    float* out        = (z == 0) ? o0 : ((z == 1) ? o1 : ((z == 2) ? o2 : o3));
    const float scale = (z == 0) ? s0 : ((z == 1) ? s1 : ((z == 2) ? s2 : s3));

    const int warpM = (wid >> 2) * 64;
    const int warpN = (wid & 3) * 32;
    const int li = lane >> 3, lr = lane & 7;

    float acc[4][4][4];
#pragma unroll
    for (int i = 0; i < 4; i++)
#pragma unroll
        for (int j = 0; j < 4; j++)
#pragma unroll
            for (int k = 0; k < 4; k++) acc[i][j][k] = 0.f;

    const int NK = E_DIM / 32;
    g_load_stage(sb, 0, Ahi, Alo, wh, wl, bm, bn, 0, M, tid);
    cp_commit();
    g_load_stage(sb, 1, Ahi, Alo, wh, wl, bm, bn, 32, M, tid);
    cp_commit();

    int slot = 0, next = 2;
    for (int ks = 0; ks < NK; ks++) {
        if (ks + 1 < NK) cp_wait1(); else cp_wait0();
        __syncthreads();
        if (ks + 2 < NK) {
            g_load_stage(sb, next, Ahi, Alo, wh, wl, bm, bn, (ks + 2) * 32, M, tid);
            cp_commit();
            if (++next == 3) next = 0;
        }

        const uint32_t abase = sb + slot * 32768;
        const uint32_t bbase = abase + 16384;
        if (++slot == 3) slot = 0;
#pragma unroll
        for (int kk = 0; kk < 2; kk++) {
            uint32_t bh[2][4], bl[2][4];
            const uint32_t kb2 = (uint32_t)(kk * 32 + (li & 1) * 16);
#pragma unroll
            for (int jn = 0; jn < 2; jn++) {
                uint32_t off = (uint32_t)((warpN + jn * 16 + (li >> 1) * 8 + lr) * 128) + kb2;
                ldsm_x4(bh[jn], bbase + sw128(off));
                ldsm_x4(bl[jn], bbase + sw128(off + 64));
            }
            const uint32_t ka = (uint32_t)(kk * 32 + (li >> 1) * 16);
#pragma unroll
            for (int i = 0; i < 4; i++) {
                uint32_t ah[4], al[4];
                uint32_t off = (uint32_t)((warpM + i * 16 + (li & 1) * 8 + lr) * 128) + ka;
                ldsm_x4(ah, abase + sw128(off));
                ldsm_x4(al, abase + sw128(off + 64));
#pragma unroll
                for (int j = 0; j < 4; j++) {
                    const uint32_t* Bh = &bh[j >> 1][(j & 1) * 2];
                    const uint32_t* Bl = &bl[j >> 1][(j & 1) * 2];
                    mma16816(acc[i][j], ah, Bh);
                    mma16816(acc[i][j], ah, Bl);
                    mma16816(acc[i][j], al, Bh);
                }
            }
        }
    }

    // ---- epilogue (float2 stores) ----
    const int g = lane >> 2, tg = lane & 3;
#pragma unroll
    for (int i = 0; i < 4; i++) {
#pragma unroll
        for (int j = 0; j < 4; j++) {
            int n0 = bn + warpN + j * 8 + tg * 2;
            float bx = bias[n0], by = bias[n0 + 1];
#pragma unroll
            for (int half = 0; half < 2; half++) {
                int m = bm + warpM + i * 16 + g + half * 8;
                if (m >= M) continue;
                float2 v;
                v.x = (acc[i][j][half * 2 + 0] + bx) * scale;
                v.y = (acc[i][j][half * 2 + 1] + by) * scale;
                if (mode == 0) {
                    *(float2*)&out[(size_t)m * E_DIM + n0] = v;
                } else {
                    int t = m >> 1, b = m & 1;
                    int h = n0 >> 6, d = n0 & 63;
                    *(float2*)&out[(size_t)((b * 16 + h) * Trows + t) * 64 + d] = v;
                }
            }
        }
    }
}

// ------------- merged pattn (softplus) + chunk-local state -----------------
// grid (NCH, BH). Computes pattn for this chunk, writes g_pattn, then the
// chunk-local 64x32 state KV^T @ P -> g_S.
__global__ __launch_bounds__(256, 2)
void pattn_local()
{
    const int c = blockIdx.x, bh = blockIdx.y;
    extern __shared__ float sm[];
    float* kps = sm;                   // 64 x 65
    float* pqs = kps + 64 * 65;        // 32 x 65
    float* kvs = pqs + 32 * 65;        // 64 x 64
    float* ps  = kvs + 64 * 64;        // 64 x 32
    const size_t base = (size_t)bh * T_LEN + c * CHUNK;
    const int tid = threadIdx.x;

    for (int i = tid; i < CHUNK * 64; i += 256) {
        int s = i >> 6, d = i & 63;
        kps[s * 65 + d] = g_kp[(base + s) * 64 + d];
        kvs[i] = g_kv[(base + s) * 64 + d];
    }
    for (int i = tid; i < PLEN * 64; i += 256) {
        int p = i >> 6, d = i & 63;
        pqs[p * 65 + d] = g_pq[(size_t)bh * PLEN * D_DIM + i];
    }
    __syncthreads();

    // pattn: row t (64 rows), 8 p's per thread
    {
        const int t  = tid >> 2;
        const int p0 = (tid & 3) * 8;
#pragma unroll
        for (int pp = 0; pp < 8; pp++) {
            int p = p0 + pp;
            float a0 = 0.f, a1 = 0.f, a2 = 0.f, a3 = 0.f;
#pragma unroll
            for (int d = 0; d < 64; d += 4) {
                a0 += kps[t * 65 + d]     * pqs[p * 65 + d];
                a1 += kps[t * 65 + d + 1] * pqs[p * 65 + d + 1];
                a2 += kps[t * 65 + d + 2] * pqs[p * 65 + d + 2];
                a3 += kps[t * 65 + d + 3] * pqs[p * 65 + d + 3];
            }
            float accv = (a0 + a1) + (a2 + a3);
            float zz = BETA * accv;
            float sp = (fmaxf(zz, 0.f) + log1pf(expf(-fabsf(zz)))) * (1.0f / BETA);
            ps[t * 32 + p] = sp;
            g_pattn[(base + t) * PLEN + p] = sp;
        }
    }
    __syncthreads();

    // local state: S_c[d][j] = sum_s kv[s][d] * p[s][j]
    {
        const int d  = tid >> 2;
        const int j0 = (tid & 3) * 8;
        float acc[8] = {0.f};
        for (int s = 0; s < CHUNK; s++) {
            float a = kvs[s * 64 + d];
#pragma unroll
            for (int jj = 0; jj < 8; jj++) acc[jj] += a * ps[s * 32 + j0 + jj];
        }
        float* out = &g_S[((size_t)bh * NCH + c) * (64 * 32)];
#pragma unroll
        for (int jj = 0; jj < 8; jj++) out[d * 32 + j0 + jj] = acc[jj];
    }
}

// ------------------- exclusive prefix scan over chunks ---------------------
__global__ void scan_states()
{
    const int bh = blockIdx.x;
    for (int r = 0; r < 4; r++) {
        int e = threadIdx.x + r * 512;
        float run = 0.f;
        for (int c = 0; c < NCH; c++) {
            float* p = &g_S[(((size_t)bh * NCH) + c) * 2048 + e];
            float v = *p;
            *p = run;
            run += v;
        }
    }
}

// ------------------- fused pass1 + softmax + pass2 (CHUNK=64) ---------------
// 4 threads/row; intra-chunk dots split across sub-lanes + butterfly reduce.
__global__ __launch_bounds__(256, 2)
void fused_pass()
{
    const int c = blockIdx.x, bh = blockIdx.y;
    extern __shared__ float sm[];
    float* qs  = sm;                 // 64 x 65
    float* kvs = qs  + 64 * 65;      // 64 x 64
    float* ps  = kvs + 64 * 64;      // 64 x 33
    float* ss  = ps  + 64 * 33;      // 64 x 33   (pass1: [d][j])
    float* ssT = ss  + 64 * 33;      // 32 x 65   (pass2: [j][d])
    float* ws  = ssT + 32 * 65;      // 64 x 33
    const size_t base = (size_t)bh * T_LEN + c * CHUNK;
    const int tid = threadIdx.x;

    for (int i = tid; i < CHUNK * 64; i += 256) {
        int s = i >> 6, d = i & 63;
        kvs[i] = g_kv[(base + s) * 64 + d];
        qs[s * 65 + d] = g_q[(base + s) * 64 + d];
    }
    for (int i = tid; i < CHUNK * 32; i += 256) {
        int s = i >> 5, j = i & 31;
        ps[s * 33 + j] = g_pattn[base * 32 + i];
    }
    for (int i = tid; i < 64 * 32; i += 256) {
        int d = i >> 5, j = i & 31;
        float v = g_S[((size_t)bh * NCH + c) * 2048 + i];
        ss[d * 33 + j]  = v;
        ssT[j * 65 + d] = v;
    }
    __syncthreads();

    const int t   = tid >> 2;            // 0..63
    const int sub = tid & 3;
    const int tgl = c * CHUNK + t;
    const float inv = 1.0f / (float)(tgl + 1);
    const int smax = t | 7;              // uniform within warp

    // ---------------- pass 1 ----------------
    {
        const int j0  = sub * 8;
        const int dq0 = sub * 16;
        float qreg[16];
#pragma unroll
        for (int d = 0; d < 16; d++) qreg[d] = qs[t * 65 + dq0 + d];

        float r[8];
#pragma unroll
        for (int jj = 0; jj < 8; jj++) r[jj] = 0.f;

        // inter-chunk: q[t] @ S_prefix (full q row read from smem)
        const float* qrow = &qs[t * 65];
#pragma unroll 8
        for (int d = 0; d < 64; d++) {
            float a = qrow[d];
#pragma unroll
            for (int jj = 0; jj < 8; jj++) r[jj] += a * ss[d * 33 + j0 + jj];
        }
        // intra-chunk causal: split dot across sub-lanes
        for (int s = 0; s <= smax; s++) {
            const float* kr = &kvs[s * 64 + dq0];
            float a0 = 0.f, a1 = 0.f, a2 = 0.f, a3 = 0.f;
#pragma unroll
            for (int d = 0; d < 16; d += 4) {
                a0 += qreg[d]     * kr[d];
                a1 += qreg[d + 1] * kr[d + 1];
                a2 += qreg[d + 2] * kr[d + 2];
                a3 += qreg[d + 3] * kr[d + 3];
            }
            float a = (a0 + a1) + (a2 + a3);
            a += __shfl_xor_sync(0xffffffffu, a, 1);
            a += __shfl_xor_sync(0xffffffffu, a, 2);
            if (s <= t) {
                const float* pr = &ps[s * 33 + j0];
#pragma unroll
                for (int jj = 0; jj < 8; jj++) r[jj] += a * pr[jj];
            }
        }
        // softmax across the 4 sub-lanes of this row
        float mx = -1e30f;
#pragma unroll
        for (int jj = 0; jj < 8; jj++) { r[jj] *= inv; mx = fmaxf(mx, r[jj]); }
        mx = fmaxf(mx, __shfl_xor_sync(0xffffffffu, mx, 1));
        mx = fmaxf(mx, __shfl_xor_sync(0xffffffffu, mx, 2));
        float sum = 0.f;
#pragma unroll
        for (int jj = 0; jj < 8; jj++) { r[jj] = expf(r[jj] - mx); sum += r[jj]; }
        sum += __shfl_xor_sync(0xffffffffu, sum, 1);
        sum += __shfl_xor_sync(0xffffffffu, sum, 2);
        float rs = 1.0f / sum;
#pragma unroll
        for (int jj = 0; jj < 8; jj++) ws[t * 33 + j0 + jj] = r[jj] * rs;
    }
    __syncwarp();

    // ---------------- pass 2 ----------------
    {
        const int d0 = sub * 16;
        const int jw0 = sub * 8;
        float wreg[32];
#pragma unroll
        for (int j = 0; j < 32; j++) wreg[j] = ws[t * 33 + j];

        float r[16];
#pragma unroll
        for (int dd = 0; dd < 16; dd++) r[dd] = 0.f;

        // inter-chunk: w[t] @ S^T_prefix
#pragma unroll 8
        for (int j = 0; j < 32; j++) {
            float a = wreg[j];
            const float* sr = &ssT[j * 65 + d0];
#pragma unroll
            for (int dd = 0; dd < 16; dd++) r[dd] += a * sr[dd];
        }
        // intra-chunk causal: split dot across sub-lanes
        for (int s = 0; s <= smax; s++) {
            const float* pr = &ps[s * 33 + jw0];
            float a0 = 0.f, a1 = 0.f;
#pragma unroll
            for (int j = 0; j < 8; j += 2) {
                a0 += wreg[jw0 + j]     * pr[j];
                a1 += wreg[jw0 + j + 1] * pr[j + 1];
            }
            float a = a0 + a1;
            a += __shfl_xor_sync(0xffffffffu, a, 1);
            a += __shfl_xor_sync(0xffffffffu, a, 2);
            if (s <= t) {
                const float* kr = &kvs[s * 64 + d0];
#pragma unroll
                for (int dd = 0; dd < 16; dd++) r[dd] += a * kr[dd];
            }
        }
        const int b = bh >> 4, hh = bh & 15;
        const size_t ob = ((size_t)tgl * 2 + b) * 1024 + hh * 64 + d0;
#pragma unroll
        for (int dd = 0; dd < 16; dd++) {
            float v = r[dd] * inv;
            __nv_bfloat16 h = __float2bfloat16(v);
            g_AThi[ob + dd] = h;
            g_ATlo[ob + dd] = __float2bfloat16(v - __bfloat162float(h));
        }
    }
}

// ---------------------------------------------------------------------------
extern "C" void kernel_launch(void* const* d_in, const int* in_sizes, int n_in,
                              void* d_out, int out_size)
{
    const float* query  = (const float*)d_in[0];
    const float* pquery = (const float*)d_in[1];
    const float* Wpq = (const float*)d_in[2];
    const float* bpq = (const float*)d_in[3];
    const float* Wq  = (const float*)d_in[4];
    const float* bq  = (const float*)d_in[5];
    const float* Wpc = (const float*)d_in[6];
    const float* bpc = (const float*)d_in[7];
    const float* Wc  = (const float*)d_in[8];
    const float* bc  = (const float*)d_in[9];
    const float* Wo  = (const float*)d_in[10];
    const float* bo  = (const float*)d_in[11];
    float* out = (float*)d_out;

    float *p_pq, *p_q, *p_kp, *p_kv;
    __nv_bfloat16 *p_Ahi, *p_Alo, *p_PQhi, *p_PQlo, *p_W4hi, *p_W4lo;
    __nv_bfloat16 *p_WOhi, *p_WOlo, *p_AThi, *p_ATlo;
    cudaGetSymbolAddress((void**)&p_pq,   g_pq);
    cudaGetSymbolAddress((void**)&p_q,    g_q);
    cudaGetSymbolAddress((void**)&p_kp,   g_kp);
    cudaGetSymbolAddress((void**)&p_kv,   g_kv);
    cudaGetSymbolAddress((void**)&p_Ahi,  g_Ahi);
    cudaGetSymbolAddress((void**)&p_Alo,  g_Alo);
    cudaGetSymbolAddress((void**)&p_PQhi, g_PQhi);
    cudaGetSymbolAddress((void**)&p_PQlo, g_PQlo);
    cudaGetSymbolAddress((void**)&p_W4hi, g_W4hi);
    cudaGetSymbolAddress((void**)&p_W4lo, g_W4lo);
    cudaGetSymbolAddress((void**)&p_WOhi, g_WOhi);
    cudaGetSymbolAddress((void**)&p_WOlo, g_WOlo);
    cudaGetSymbolAddress((void**)&p_AThi, g_AThi);
    cudaGetSymbolAddress((void**)&p_ATlo, g_ATlo);

    const int GEMM_SMEM = 3 * 32768;   // 98304
    const int PL_SMEM = (64 * 65 + 32 * 65 + 64 * 64 + 64 * 32) * 4;
    const int FP_SMEM = (64 * 65 + 64 * 64 + 64 * 33 + 64 * 33 + 32 * 65 + 64 * 33) * 4;
    cudaFuncSetAttribute(gemm_mma,    cudaFuncAttributeMaxDynamicSharedMemorySize, GEMM_SMEM);
    cudaFuncSetAttribute(pattn_local, cudaFuncAttributeMaxDynamicSharedMemorySize, PL_SMEM);
    cudaFuncSetAttribute(fused_pass,  cudaFuncAttributeMaxDynamicSharedMemorySize, FP_SMEM);

    // ---- launch 0: ALL conversions in one kernel ----
    CvtArgs ca;
    int acc = 0, n4;
    // 0: query
    n4 = MROWS * E_DIM / 4;
    ca.s[0] = (const float4*)query;  ca.h[0] = (__nv_bfloat162*)p_Ahi;  ca.l[0] = (__nv_bfloat162*)p_Alo;  acc += n4; ca.end[0] = acc;
    // 1: pquery (32 rows + 32 pad rows handled by M guard; convert only real 32 rows,
    //    pad region is never read because gemm clamps to M-1... M3=64 though. Convert 64 rows worth? 
    //    g_PQhi is 64 rows; rows 32..63 are garbage-read-guarded by M3=64? No: M3 must be 64 to cover
    //    pad; instead set M3=64 and ensure rows 32..63 defined: convert full 64-row buffer using
    //    pquery repeated? Simplest: M3 = 2*PLEN = 64 actual rows of pquery = plen*bsz = 64 rows. OK.)
    n4 = 64 * E_DIM / 4;
    ca.s[1] = (const float4*)pquery; ca.h[1] = (__nv_bfloat162*)p_PQhi; ca.l[1] = (__nv_bfloat162*)p_PQlo; acc += n4; ca.end[1] = acc;
    // 2-5: Wq, Wpc, Wc, Wpq into the 4-slot stack
    n4 = NE / 4;
    ca.s[2] = (const float4*)Wq;  ca.h[2] = (__nv_bfloat162*)p_W4hi;            ca.l[2] = (__nv_bfloat162*)p_W4lo;            acc += n4; ca.end[2] = acc;
    ca.s[3] = (const float4*)Wpc; ca.h[3] = (__nv_bfloat162*)(p_W4hi + NE);     ca.l[3] = (__nv_bfloat162*)(p_W4lo + NE);     acc += n4; ca.end[3] = acc;
    ca.s[4] = (const float4*)Wc;  ca.h[4] = (__nv_bfloat162*)(p_W4hi + 2 * NE); ca.l[4] = (__nv_bfloat162*)(p_W4lo + 2 * NE); acc += n4; ca.end[4] = acc;
    ca.s[5] = (const float4*)Wpq; ca.h[5] = (__nv_bfloat162*)(p_W4hi + 3 * NE); ca.l[5] = (__nv_bfloat162*)(p_W4lo + 3 * NE); acc += n4; ca.end[5] = acc;
    // 6: Wo
    ca.s[6] = (const float4*)Wo;  ca.h[6] = (__nv_bfloat162*)p_WOhi;            ca.l[6] = (__nv_bfloat162*)p_WOlo;            acc += n4; ca.end[6] = acc;
    cvt_all<<<(acc + 255) / 256, 256>>>(ca);

    // ---- launch 1: q/kp/kv/pq projections (z = 0..3) ----
    gemm_mma<<<dim3(8, 32, 4), 256, GEMM_SMEM>>>(
        p_Ahi, p_Alo, p_PQhi, p_PQlo, p_W4hi, p_W4lo,
        bq, bpc, bc, bpq,
        p_q, p_kp, p_kv, p_pq,
        SCALING, 1.0f, 1.0f, SCALING,
        MROWS, 64, 1, T_LEN, PLEN);

    // ---- launch 2: pattn + chunk-local states ----
    pattn_local<<<dim3(NCH, BH), 256, PL_SMEM>>>();

    // ---- launch 3: exclusive scan of chunk states ----
    scan_states<<<BH, 512>>>();

    // ---- launch 4: fused pass1 + softmax + pass2 ----
    fused_pass<<<dim3(NCH, BH), 256, FP_SMEM>>>();

    // ---- launch 5: output projection -> d_out ----
    gemm_mma<<<dim3(8, 32, 1), 256, GEMM_SMEM>>>(
        p_AThi, p_ATlo, p_AThi, p_ATlo, p_WOhi, p_WOlo,
        bo, bo, bo, bo,
        out, out, out, out,
        1.0f, 1.0f, 1.0f, 1.0f,
        MROWS, MROWS, 0, 0, 0);
}

// round 8
// speedup vs baseline: 3.2326x; 1.1339x over previous
#include <cuda_runtime.h>
#include <cuda_fp16.h>
#include <math.h>
#include <stdint.h>

#define T_LEN  2048
#define BSZ    2
#define E_DIM  1024
#define H_NUM  16
#define D_DIM  64
#define PLEN   32
#define BH     32
#define CHUNK  64
#define NCH    (T_LEN/CHUNK)   // 32
#define SCALING 0.125f
#define BETA    0.6931471805599453f

#define MROWS  (T_LEN*BSZ)      // 4096
#define NE     (E_DIM*E_DIM)

// ------------------------- scratch -----------------------------------------
__device__ float g_pq   [BH*PLEN*D_DIM];
__device__ float g_q    [BH*T_LEN*D_DIM];
__device__ float g_kp   [BH*T_LEN*D_DIM];
__device__ float g_kv   [BH*T_LEN*D_DIM];
__device__ float g_pattn[BH*T_LEN*PLEN];
__device__ float g_S    [BH*NCH*D_DIM*PLEN];

__device__ __half g_Ahi [MROWS*E_DIM];
__device__ __half g_Alo [MROWS*E_DIM];
__device__ __half g_PQhi[64*E_DIM];
__device__ __half g_PQlo[64*E_DIM];
__device__ __half g_W4h [4*NE];          // Wq, Wpc, Wc, Wpq (hi plane only)
__device__ __half g_WOhi[NE];
__device__ __half g_WOlo[NE];
__device__ __half g_AThi[MROWS*E_DIM];
__device__ __half g_ATlo[MROWS*E_DIM];

// ------------------------- helpers -----------------------------------------
__device__ __forceinline__ uint32_t smem_u32(const void* p) {
    uint32_t a;
    asm("{ .reg .u64 t; cvta.to.shared.u64 t, %1; cvt.u32.u64 %0, t; }"
        : "=r"(a) : "l"(p));
    return a;
}
__device__ __forceinline__ uint32_t sw128(uint32_t off) {
    return off ^ ((off >> 3) & 0x70);
}
__device__ __forceinline__ void ldsm_x4(uint32_t* r, uint32_t addr) {
    asm volatile("ldmatrix.sync.aligned.m8n8.x4.shared.b16 {%0,%1,%2,%3}, [%4];"
                 : "=r"(r[0]), "=r"(r[1]), "=r"(r[2]), "=r"(r[3]) : "r"(addr));
}
__device__ __forceinline__ void mma16816(float* c, const uint32_t* a, const uint32_t* b) {
    asm volatile("mma.sync.aligned.m16n8k16.row.col.f32.f16.f16.f32 "
                 "{%0,%1,%2,%3}, {%4,%5,%6,%7}, {%8,%9}, {%0,%1,%2,%3};"
                 : "+f"(c[0]), "+f"(c[1]), "+f"(c[2]), "+f"(c[3])
                 : "r"(a[0]), "r"(a[1]), "r"(a[2]), "r"(a[3]), "r"(b[0]), "r"(b[1]));
}
__device__ __forceinline__ void cp16(uint32_t dst, const void* src, int sz) {
    asm volatile("cp.async.cg.shared.global [%0], [%1], 16, %2;"
                 :: "r"(dst), "l"(src), "r"(sz));
}
__device__ __forceinline__ void cp_commit() {
    asm volatile("cp.async.commit_group;" ::: "memory");
}
__device__ __forceinline__ void cp_wait1() {
    asm volatile("cp.async.wait_group 1;" ::: "memory");
}
__device__ __forceinline__ void cp_wait0() {
    asm volatile("cp.async.wait_group 0;" ::: "memory");
}

// ------------------------- merged fp32 -> fp16 converter -------------------
#define NCVT 7
struct CvtArgs {
    const float4* s[NCVT];
    __half2*      h[NCVT];
    __half2*      l[NCVT];     // may be unused (mode 1)
    int           end[NCVT];   // cumulative n4
    int           mode[NCVT];  // 0 = hi+lo exact split, 1 = hi only
};

__global__ __launch_bounds__(256)
void cvt_all(CvtArgs A)
{
    int gi = blockIdx.x * 256 + threadIdx.x;
    int seg = 0;
    while (seg < NCVT && gi >= A.end[seg]) seg++;
    if (seg >= NCVT) return;
    int i = gi - (seg ? A.end[seg - 1] : 0);

    float4 v = A.s[seg][i];
    __half h0 = __float2half_rn(v.x);
    __half h1 = __float2half_rn(v.y);
    __half h2 = __float2half_rn(v.z);
    __half h3 = __float2half_rn(v.w);
    A.h[seg][2 * i]     = __half2(h0, h1);
    A.h[seg][2 * i + 1] = __half2(h2, h3);
    if (A.mode[seg] == 0) {
        __half l0 = __float2half_rn(v.x - __half2float(h0));
        __half l1 = __float2half_rn(v.y - __half2float(h1));
        __half l2 = __float2half_rn(v.z - __half2float(h2));
        __half l3 = __float2half_rn(v.w - __half2float(h3));
        A.l[seg][2 * i]     = __half2(l0, l1);
        A.l[seg][2 * i + 1] = __half2(l2, l3);
    }
}

// ------------------------- pipelined split-fp16 GEMM ------------------------
// NTERM=2: C = (Ahi+Alo) @ Whi^T    (A exact split, W rounded; Wlo unused)
// NTERM=3: C = Ahi@Whi + Ahi@Wlo + Alo@Whi (both split)
// smem row = 128B: [hi 64B | lo 64B]; B-lo half only loaded for NTERM=3.
template<int NTERM>
__device__ __forceinline__ void g_load_stage(
    uint32_t sb, int slot,
    const __half* Ahi, const __half* Alo,
    const __half* Bhi, const __half* Blo,
    int bm, int bn, int kb, int M, int tid)
{
    const uint32_t abase = sb + slot * 32768;
    const uint32_t bbase = abase + 16384;
    const int c  = tid & 7;
    const int r0 = tid >> 3;
    const int kc = kb + (c & 3) * 8;
    const __half* ap = (c & 4) ? Alo : Ahi;
    const bool blo = (c & 4);
    const __half* bp = blo ? Blo : Bhi;
#pragma unroll
    for (int ii = 0; ii < 4; ii++) {
        int r = r0 + ii * 32;
        uint32_t so = sw128((uint32_t)(r * 128 + c * 16));
        int m = bm + r;
        int mc = (m < M) ? m : (M - 1);
        cp16(abase + so, ap + (size_t)mc * E_DIM + kc, (m < M) ? 16 : 0);
        if (NTERM == 3 || !blo)
            cp16(bbase + so, bp + (size_t)(bn + r) * E_DIM + kc, 16);
    }
}

template<int NTERM>
__global__ __launch_bounds__(256, 2)
void gemm_mma(const __half* __restrict__ A0hi, const __half* __restrict__ A0lo,
              const __half* __restrict__ A3hi, const __half* __restrict__ A3lo,
              const __half* __restrict__ Whi, const __half* __restrict__ Wlo,
              const float* b0, const float* b1, const float* b2, const float* b3,
              float* o0, float* o1, float* o2, float* o3,
              float s0, float s1, float s2, float s3,
              int M0, int M3, int mode, int Trows0, int Trows3)
{
    extern __shared__ char smem[];
    const uint32_t sb = smem_u32(smem);

    const int tid = threadIdx.x, wid = tid >> 5, lane = tid & 31;
    const int bm = blockIdx.y * 128, bn = blockIdx.x * 128;
    const int z = blockIdx.z;
    const int M     = (z == 3) ? M3 : M0;
    const int Trows = (z == 3) ? Trows3 : Trows0;
    if (bm >= M) return;
    const __half* Ahi = (z == 3) ? A3hi : A0hi;
    const __half* Alo = (z == 3) ? A3lo : A0lo;
    const __half* wh = Whi + (size_t)z * NE;
    const __half* wl = (NTERM == 3) ? (Wlo + (size_t)z * NE) : Whi;
    const float* bias = (z == 0) ? b0 : ((z == 1) ? b1 : ((z == 2) ? b2 : b3));
    float* out        = (z == 0) ? o0 : ((z == 1) ? o1 : ((z == 2) ? o2 : o3));
    const float scale = (z == 0) ? s0 : ((z == 1) ? s1 : ((z == 2) ? s2 : s3));

    const int warpM = (wid >> 2) * 64;
    const int warpN = (wid & 3) * 32;
    const int li = lane >> 3, lr = lane & 7;

    float acc[4][4][4];
#pragma unroll
    for (int i = 0; i < 4; i++)
#pragma unroll
        for (int j = 0; j < 4; j++)
#pragma unroll
            for (int k = 0; k < 4; k++) acc[i][j][k] = 0.f;

    const int NK = E_DIM / 32;
    g_load_stage<NTERM>(sb, 0, Ahi, Alo, wh, wl, bm, bn, 0, M, tid);
    cp_commit();
    g_load_stage<NTERM>(sb, 1, Ahi, Alo, wh, wl, bm, bn, 32, M, tid);
    cp_commit();

    int slot = 0, next = 2;
    for (int ks = 0; ks < NK; ks++) {
        if (ks + 1 < NK) cp_wait1(); else cp_wait0();
        __syncthreads();
        if (ks + 2 < NK) {
            g_load_stage<NTERM>(sb, next, Ahi, Alo, wh, wl, bm, bn, (ks + 2) * 32, M, tid);
            cp_commit();
            if (++next == 3) next = 0;
        }

        const uint32_t abase = sb + slot * 32768;
        const uint32_t bbase = abase + 16384;
        if (++slot == 3) slot = 0;
#pragma unroll
        for (int kk = 0; kk < 2; kk++) {
            uint32_t bh[2][4], bl[2][4];
            const uint32_t kb2 = (uint32_t)(kk * 32 + (li & 1) * 16);
#pragma unroll
            for (int jn = 0; jn < 2; jn++) {
                uint32_t off = (uint32_t)((warpN + jn * 16 + (li >> 1) * 8 + lr) * 128) + kb2;
                ldsm_x4(bh[jn], bbase + sw128(off));
                if (NTERM == 3) ldsm_x4(bl[jn], bbase + sw128(off + 64));
            }
            const uint32_t ka = (uint32_t)(kk * 32 + (li >> 1) * 16);
#pragma unroll
            for (int i = 0; i < 4; i++) {
                uint32_t ah[4], al[4];
                uint32_t off = (uint32_t)((warpM + i * 16 + (li & 1) * 8 + lr) * 128) + ka;
                ldsm_x4(ah, abase + sw128(off));
                ldsm_x4(al, abase + sw128(off + 64));
#pragma unroll
                for (int j = 0; j < 4; j++) {
                    const uint32_t* Bh = &bh[j >> 1][(j & 1) * 2];
                    mma16816(acc[i][j], ah, Bh);
                    mma16816(acc[i][j], al, Bh);
                    if (NTERM == 3) {
                        const uint32_t* Bl = &bl[j >> 1][(j & 1) * 2];
                        mma16816(acc[i][j], ah, Bl);
                    }
                }
            }
        }
    }

    // ---- epilogue (float2 stores) ----
    const int g = lane >> 2, tg = lane & 3;
#pragma unroll
    for (int i = 0; i < 4; i++) {
#pragma unroll
        for (int j = 0; j < 4; j++) {
            int n0 = bn + warpN + j * 8 + tg * 2;
            float bx = bias[n0], by = bias[n0 + 1];
#pragma unroll
            for (int half = 0; half < 2; half++) {
                int m = bm + warpM + i * 16 + g + half * 8;
                if (m >= M) continue;
                float2 v;
                v.x = (acc[i][j][half * 2 + 0] + bx) * scale;
                v.y = (acc[i][j][half * 2 + 1] + by) * scale;
                if (mode == 0) {
                    *(float2*)&out[(size_t)m * E_DIM + n0] = v;
                } else {
                    int t = m >> 1, b = m & 1;
                    int h = n0 >> 6, d = n0 & 63;
                    *(float2*)&out[(size_t)((b * 16 + h) * Trows + t) * 64 + d] = v;
                }
            }
        }
    }
}

// ------------- merged pattn (softplus) + chunk-local state -----------------
__global__ __launch_bounds__(256, 2)
void pattn_local()
{
    const int c = blockIdx.x, bh = blockIdx.y;
    extern __shared__ float sm[];
    float* kps = sm;                   // 64 x 65
    float* pqs = kps + 64 * 65;        // 32 x 65
    float* kvs = pqs + 32 * 65;        // 64 x 64
    float* ps  = kvs + 64 * 64;        // 64 x 32
    const size_t base = (size_t)bh * T_LEN + c * CHUNK;
    const int tid = threadIdx.x;

    for (int i = tid; i < CHUNK * 64; i += 256) {
        int s = i >> 6, d = i & 63;
        kps[s * 65 + d] = g_kp[(base + s) * 64 + d];
        kvs[i] = g_kv[(base + s) * 64 + d];
    }
    for (int i = tid; i < PLEN * 64; i += 256) {
        int p = i >> 6, d = i & 63;
        pqs[p * 65 + d] = g_pq[(size_t)bh * PLEN * D_DIM + i];
    }
    __syncthreads();

    {
        const int t  = tid >> 2;
        const int p0 = (tid & 3) * 8;
#pragma unroll
        for (int pp = 0; pp < 8; pp++) {
            int p = p0 + pp;
            float a0 = 0.f, a1 = 0.f, a2 = 0.f, a3 = 0.f;
#pragma unroll
            for (int d = 0; d < 64; d += 4) {
                a0 += kps[t * 65 + d]     * pqs[p * 65 + d];
                a1 += kps[t * 65 + d + 1] * pqs[p * 65 + d + 1];
                a2 += kps[t * 65 + d + 2] * pqs[p * 65 + d + 2];
                a3 += kps[t * 65 + d + 3] * pqs[p * 65 + d + 3];
            }
            float accv = (a0 + a1) + (a2 + a3);
            float zz = BETA * accv;
            float sp = (fmaxf(zz, 0.f) + log1pf(expf(-fabsf(zz)))) * (1.0f / BETA);
            ps[t * 32 + p] = sp;
            g_pattn[(base + t) * PLEN + p] = sp;
        }
    }
    __syncthreads();

    {
        const int d  = tid >> 2;
        const int j0 = (tid & 3) * 8;
        float acc[8] = {0.f};
        for (int s = 0; s < CHUNK; s++) {
            float a = kvs[s * 64 + d];
#pragma unroll
            for (int jj = 0; jj < 8; jj++) acc[jj] += a * ps[s * 32 + j0 + jj];
        }
        float* out = &g_S[((size_t)bh * NCH + c) * (64 * 32)];
#pragma unroll
        for (int jj = 0; jj < 8; jj++) out[d * 32 + j0 + jj] = acc[jj];
    }
}

// ------------------- exclusive prefix scan over chunks (flat) --------------
__global__ __launch_bounds__(256)
void scan_states()
{
    const int gi = blockIdx.x * 256 + threadIdx.x;   // (bh, e): 32 * 2048
    const int bh = gi >> 11;
    const int e  = gi & 2047;
    float run = 0.f;
    float* p = &g_S[(size_t)bh * NCH * 2048 + e];
    for (int c = 0; c < NCH; c++) {
        float v = p[c * 2048];
        p[c * 2048] = run;
        run += v;
    }
}

// ------------------- fused pass1 + softmax + pass2 (CHUNK=64) ---------------
__global__ __launch_bounds__(256, 2)
void fused_pass()
{
    const int c = blockIdx.x, bh = blockIdx.y;
    extern __shared__ float sm[];
    float* qs  = sm;                 // 64 x 65
    float* kvs = qs  + 64 * 65;      // 64 x 64
    float* ps  = kvs + 64 * 64;      // 64 x 33
    float* ss  = ps  + 64 * 33;      // 64 x 33
    float* ssT = ss  + 64 * 33;      // 32 x 65
    float* ws  = ssT + 32 * 65;      // 64 x 33
    const size_t base = (size_t)bh * T_LEN + c * CHUNK;
    const int tid = threadIdx.x;

    for (int i = tid; i < CHUNK * 64; i += 256) {
        int s = i >> 6, d = i & 63;
        kvs[i] = g_kv[(base + s) * 64 + d];
        qs[s * 65 + d] = g_q[(base + s) * 64 + d];
    }
    for (int i = tid; i < CHUNK * 32; i += 256) {
        int s = i >> 5, j = i & 31;
        ps[s * 33 + j] = g_pattn[base * 32 + i];
    }
    for (int i = tid; i < 64 * 32; i += 256) {
        int d = i >> 5, j = i & 31;
        float v = g_S[((size_t)bh * NCH + c) * 2048 + i];
        ss[d * 33 + j]  = v;
        ssT[j * 65 + d] = v;
    }
    __syncthreads();

    const int t   = tid >> 2;
    const int sub = tid & 3;
    const int tgl = c * CHUNK + t;
    const float inv = 1.0f / (float)(tgl + 1);
    const int smax = t | 7;

    // ---------------- pass 1 ----------------
    {
        const int j0  = sub * 8;
        const int dq0 = sub * 16;
        float qreg[16];
#pragma unroll
        for (int d = 0; d < 16; d++) qreg[d] = qs[t * 65 + dq0 + d];

        float r[8];
#pragma unroll
        for (int jj = 0; jj < 8; jj++) r[jj] = 0.f;

        const float* qrow = &qs[t * 65];
#pragma unroll 8
        for (int d = 0; d < 64; d++) {
            float a = qrow[d];
#pragma unroll
            for (int jj = 0; jj < 8; jj++) r[jj] += a * ss[d * 33 + j0 + jj];
        }
        for (int s = 0; s <= smax; s++) {
            const float* kr = &kvs[s * 64 + dq0];
            float a0 = 0.f, a1 = 0.f, a2 = 0.f, a3 = 0.f;
#pragma unroll
            for (int d = 0; d < 16; d += 4) {
                a0 += qreg[d]     * kr[d];
                a1 += qreg[d + 1] * kr[d + 1];
                a2 += qreg[d + 2] * kr[d + 2];
                a3 += qreg[d + 3] * kr[d + 3];
            }
            float a = (a0 + a1) + (a2 + a3);
            a += __shfl_xor_sync(0xffffffffu, a, 1);
            a += __shfl_xor_sync(0xffffffffu, a, 2);
            if (s <= t) {
                const float* pr = &ps[s * 33 + j0];
#pragma unroll
                for (int jj = 0; jj < 8; jj++) r[jj] += a * pr[jj];
            }
        }
        float mx = -1e30f;
#pragma unroll
        for (int jj = 0; jj < 8; jj++) { r[jj] *= inv; mx = fmaxf(mx, r[jj]); }
        mx = fmaxf(mx, __shfl_xor_sync(0xffffffffu, mx, 1));
        mx = fmaxf(mx, __shfl_xor_sync(0xffffffffu, mx, 2));
        float sum = 0.f;
#pragma unroll
        for (int jj = 0; jj < 8; jj++) { r[jj] = expf(r[jj] - mx); sum += r[jj]; }
        sum += __shfl_xor_sync(0xffffffffu, sum, 1);
        sum += __shfl_xor_sync(0xffffffffu, sum, 2);
        float rs = 1.0f / sum;
#pragma unroll
        for (int jj = 0; jj < 8; jj++) ws[t * 33 + j0 + jj] = r[jj] * rs;
    }
    __syncwarp();

    // ---------------- pass 2 ----------------
    {
        const int d0 = sub * 16;
        const int jw0 = sub * 8;
        float wreg[32];
#pragma unroll
        for (int j = 0; j < 32; j++) wreg[j] = ws[t * 33 + j];

        float r[16];
#pragma unroll
        for (int dd = 0; dd < 16; dd++) r[dd] = 0.f;

#pragma unroll 8
        for (int j = 0; j < 32; j++) {
            float a = wreg[j];
            const float* sr = &ssT[j * 65 + d0];
#pragma unroll
            for (int dd = 0; dd < 16; dd++) r[dd] += a * sr[dd];
        }
        for (int s = 0; s <= smax; s++) {
            const float* pr = &ps[s * 33 + jw0];
            float a0 = 0.f, a1 = 0.f;
#pragma unroll
            for (int j = 0; j < 8; j += 2) {
                a0 += wreg[jw0 + j]     * pr[j];
                a1 += wreg[jw0 + j + 1] * pr[j + 1];
            }
            float a = a0 + a1;
            a += __shfl_xor_sync(0xffffffffu, a, 1);
            a += __shfl_xor_sync(0xffffffffu, a, 2);
            if (s <= t) {
                const float* kr = &kvs[s * 64 + d0];
#pragma unroll
                for (int dd = 0; dd < 16; dd++) r[dd] += a * kr[dd];
            }
        }
        const int b = bh >> 4, hh = bh & 15;
        const size_t ob = ((size_t)tgl * 2 + b) * 1024 + hh * 64 + d0;
#pragma unroll
        for (int dd = 0; dd < 16; dd++) {
            float v = r[dd] * inv;
            __half h = __float2half_rn(v);
            g_AThi[ob + dd] = h;
            g_ATlo[ob + dd] = __float2half_rn(v - __half2float(h));
        }
    }
}

// ---------------------------------------------------------------------------
extern "C" void kernel_launch(void* const* d_in, const int* in_sizes, int n_in,
                              void* d_out, int out_size)
{
    const float* query  = (const float*)d_in[0];
    const float* pquery = (const float*)d_in[1];
    const float* Wpq = (const float*)d_in[2];
    const float* bpq = (const float*)d_in[3];
    const float* Wq  = (const float*)d_in[4];
    const float* bq  = (const float*)d_in[5];
    const float* Wpc = (const float*)d_in[6];
    const float* bpc = (const float*)d_in[7];
    const float* Wc  = (const float*)d_in[8];
    const float* bc  = (const float*)d_in[9];
    const float* Wo  = (const float*)d_in[10];
    const float* bo  = (const float*)d_in[11];
    float* out = (float*)d_out;

    float *p_pq, *p_q, *p_kp, *p_kv;
    __half *p_Ahi, *p_Alo, *p_PQhi, *p_PQlo, *p_W4h;
    __half *p_WOhi, *p_WOlo, *p_AThi, *p_ATlo;
    cudaGetSymbolAddress((void**)&p_pq,   g_pq);
    cudaGetSymbolAddress((void**)&p_q,    g_q);
    cudaGetSymbolAddress((void**)&p_kp,   g_kp);
    cudaGetSymbolAddress((void**)&p_kv,   g_kv);
    cudaGetSymbolAddress((void**)&p_Ahi,  g_Ahi);
    cudaGetSymbolAddress((void**)&p_Alo,  g_Alo);
    cudaGetSymbolAddress((void**)&p_PQhi, g_PQhi);
    cudaGetSymbolAddress((void**)&p_PQlo, g_PQlo);
    cudaGetSymbolAddress((void**)&p_W4h,  g_W4h);
    cudaGetSymbolAddress((void**)&p_WOhi, g_WOhi);
    cudaGetSymbolAddress((void**)&p_WOlo, g_WOlo);
    cudaGetSymbolAddress((void**)&p_AThi, g_AThi);
    cudaGetSymbolAddress((void**)&p_ATlo, g_ATlo);

    const int GEMM_SMEM = 3 * 32768;   // 98304
    const int PL_SMEM = (64 * 65 + 32 * 65 + 64 * 64 + 64 * 32) * 4;
    const int FP_SMEM = (64 * 65 + 64 * 64 + 64 * 33 + 64 * 33 + 32 * 65 + 64 * 33) * 4;
    cudaFuncSetAttribute(gemm_mma<2>, cudaFuncAttributeMaxDynamicSharedMemorySize, GEMM_SMEM);
    cudaFuncSetAttribute(gemm_mma<3>, cudaFuncAttributeMaxDynamicSharedMemorySize, GEMM_SMEM);
    cudaFuncSetAttribute(pattn_local, cudaFuncAttributeMaxDynamicSharedMemorySize, PL_SMEM);
    cudaFuncSetAttribute(fused_pass,  cudaFuncAttributeMaxDynamicSharedMemorySize, FP_SMEM);

    // ---- launch 0: ALL conversions in one kernel ----
    CvtArgs ca;
    int acc = 0, n4;
    n4 = MROWS * E_DIM / 4;
    ca.s[0] = (const float4*)query;  ca.h[0] = (__half2*)p_Ahi;  ca.l[0] = (__half2*)p_Alo;  ca.mode[0] = 0; acc += n4; ca.end[0] = acc;
    n4 = 64 * E_DIM / 4;
    ca.s[1] = (const float4*)pquery; ca.h[1] = (__half2*)p_PQhi; ca.l[1] = (__half2*)p_PQlo; ca.mode[1] = 0; acc += n4; ca.end[1] = acc;
    n4 = NE / 4;
    ca.s[2] = (const float4*)Wq;  ca.h[2] = (__half2*)p_W4h;            ca.l[2] = nullptr; ca.mode[2] = 1; acc += n4; ca.end[2] = acc;
    ca.s[3] = (const float4*)Wpc; ca.h[3] = (__half2*)(p_W4h + NE);     ca.l[3] = nullptr; ca.mode[3] = 1; acc += n4; ca.end[3] = acc;
    ca.s[4] = (const float4*)Wc;  ca.h[4] = (__half2*)(p_W4h + 2 * NE); ca.l[4] = nullptr; ca.mode[4] = 1; acc += n4; ca.end[4] = acc;
    ca.s[5] = (const float4*)Wpq; ca.h[5] = (__half2*)(p_W4h + 3 * NE); ca.l[5] = nullptr; ca.mode[5] = 1; acc += n4; ca.end[5] = acc;
    ca.s[6] = (const float4*)Wo;  ca.h[6] = (__half2*)p_WOhi;           ca.l[6] = (__half2*)p_WOlo; ca.mode[6] = 0; acc += n4; ca.end[6] = acc;
    cvt_all<<<(acc + 255) / 256, 256>>>(ca);

    // ---- launch 1: q/kp/kv/pq projections (z = 0..3), 2-term fp16 ----
    gemm_mma<2><<<dim3(8, 32, 4), 256, GEMM_SMEM>>>(
        p_Ahi, p_Alo, p_PQhi, p_PQlo, p_W4h, nullptr,
        bq, bpc, bc, bpq,
        p_q, p_kp, p_kv, p_pq,
        SCALING, 1.0f, 1.0f, SCALING,
        MROWS, 64, 1, T_LEN, PLEN);

    // ---- launch 2: pattn + chunk-local states ----
    pattn_local<<<dim3(NCH, BH), 256, PL_SMEM>>>();

    // ---- launch 3: exclusive scan of chunk states (flat, 256 CTAs) ----
    scan_states<<<BH * 2048 / 256, 256>>>();

    // ---- launch 4: fused pass1 + softmax + pass2 ----
    fused_pass<<<dim3(NCH, BH), 256, FP_SMEM>>>();

    // ---- launch 5: output projection -> d_out (3-term fp16) ----
    gemm_mma<3><<<dim3(8, 32, 1), 256, GEMM_SMEM>>>(
        p_AThi, p_ATlo, p_AThi, p_ATlo, p_WOhi, p_WOlo,
        bo, bo, bo, bo,
        out, out, out, out,
        1.0f, 1.0f, 1.0f, 1.0f,
        MROWS, MROWS, 0, 0, 0);
}

// round 9
// speedup vs baseline: 3.5253x; 1.0905x over previous
#include <cuda_runtime.h>
#include <cuda_fp16.h>
#include <math.h>
#include <stdint.h>

#define T_LEN  2048
#define BSZ    2
#define E_DIM  1024
#define H_NUM  16
#define D_DIM  64
#define PLEN   32
#define BH     32
#define SCH    32               // state chunk
#define NSC    (T_LEN/SCH)      // 64
#define SCALING 0.125f
#define BETA    0.6931471805599453f

#define MROWS  (T_LEN*BSZ)      // 4096
#define NE     (E_DIM*E_DIM)

// ------------------------- scratch -----------------------------------------
__device__ float g_pq   [BH*PLEN*D_DIM];
__device__ float g_q    [BH*T_LEN*D_DIM];
__device__ float g_kp   [BH*T_LEN*D_DIM];
__device__ float g_kv   [BH*T_LEN*D_DIM];
__device__ float g_pattn[BH*T_LEN*PLEN];
__device__ float g_S    [BH*NSC*D_DIM*PLEN];

__device__ __half g_Ahi [MROWS*E_DIM];
__device__ __half g_Alo [MROWS*E_DIM];
__device__ __half g_PQhi[64*E_DIM];
__device__ __half g_PQlo[64*E_DIM];
__device__ __half g_W4h [4*NE];          // Wq, Wpc, Wc, Wpq (hi plane only)
__device__ __half g_WOh [NE];
__device__ __half g_AThi[MROWS*E_DIM];
__device__ __half g_ATlo[MROWS*E_DIM];

// ------------------------- helpers -----------------------------------------
__device__ __forceinline__ uint32_t smem_u32(const void* p) {
    uint32_t a;
    asm("{ .reg .u64 t; cvta.to.shared.u64 t, %1; cvt.u32.u64 %0, t; }"
        : "=r"(a) : "l"(p));
    return a;
}
__device__ __forceinline__ uint32_t sw128(uint32_t off) {
    return off ^ ((off >> 3) & 0x70);
}
__device__ __forceinline__ void ldsm_x4(uint32_t* r, uint32_t addr) {
    asm volatile("ldmatrix.sync.aligned.m8n8.x4.shared.b16 {%0,%1,%2,%3}, [%4];"
                 : "=r"(r[0]), "=r"(r[1]), "=r"(r[2]), "=r"(r[3]) : "r"(addr));
}
__device__ __forceinline__ void mma16816(float* c, const uint32_t* a, const uint32_t* b) {
    asm volatile("mma.sync.aligned.m16n8k16.row.col.f32.f16.f16.f32 "
                 "{%0,%1,%2,%3}, {%4,%5,%6,%7}, {%8,%9}, {%0,%1,%2,%3};"
                 : "+f"(c[0]), "+f"(c[1]), "+f"(c[2]), "+f"(c[3])
                 : "r"(a[0]), "r"(a[1]), "r"(a[2]), "r"(a[3]), "r"(b[0]), "r"(b[1]));
}
__device__ __forceinline__ void cp16(uint32_t dst, const void* src, int sz) {
    asm volatile("cp.async.cg.shared.global [%0], [%1], 16, %2;"
                 :: "r"(dst), "l"(src), "r"(sz));
}
__device__ __forceinline__ void cp_commit() {
    asm volatile("cp.async.commit_group;" ::: "memory");
}
__device__ __forceinline__ void cp_wait1() {
    asm volatile("cp.async.wait_group 1;" ::: "memory");
}
__device__ __forceinline__ void cp_wait0() {
    asm volatile("cp.async.wait_group 0;" ::: "memory");
}

// ------------------------- merged fp32 -> fp16 converter -------------------
#define NCVT 7
struct CvtArgs {
    const float4* s[NCVT];
    __half2*      h[NCVT];
    __half2*      l[NCVT];     // may be unused (mode 1)
    int           end[NCVT];
    int           mode[NCVT];  // 0 = hi+lo exact split, 1 = hi only
};

__global__ __launch_bounds__(256)
void cvt_all(CvtArgs A)
{
    int gi = blockIdx.x * 256 + threadIdx.x;
    int seg = 0;
    while (seg < NCVT && gi >= A.end[seg]) seg++;
    if (seg >= NCVT) return;
    int i = gi - (seg ? A.end[seg - 1] : 0);

    float4 v = A.s[seg][i];
    __half h0 = __float2half_rn(v.x);
    __half h1 = __float2half_rn(v.y);
    __half h2 = __float2half_rn(v.z);
    __half h3 = __float2half_rn(v.w);
    A.h[seg][2 * i]     = __half2(h0, h1);
    A.h[seg][2 * i + 1] = __half2(h2, h3);
    if (A.mode[seg] == 0) {
        __half l0 = __float2half_rn(v.x - __half2float(h0));
        __half l1 = __float2half_rn(v.y - __half2float(h1));
        __half l2 = __float2half_rn(v.z - __half2float(h2));
        __half l3 = __float2half_rn(v.w - __half2float(h3));
        A.l[seg][2 * i]     = __half2(l0, l1);
        A.l[seg][2 * i + 1] = __half2(l2, l3);
    }
}

// ------------------------- pipelined 2-term fp16 GEMM -----------------------
// C = ((Ahi + Alo) @ Wh^T + bias) * scale.  A exact fp16 split, W fp16-rounded.
// smem row = 128B: [A: hi 64B | lo 64B], [B: hi 64B | unused].
__device__ __forceinline__ void g_load_stage(
    uint32_t sb, int slot,
    const __half* Ahi, const __half* Alo, const __half* Bhi,
    int bm, int bn, int kb, int M, int tid)
{
    const uint32_t abase = sb + slot * 32768;
    const uint32_t bbase = abase + 16384;
    const int c  = tid & 7;
    const int r0 = tid >> 3;
    const int kc = kb + (c & 3) * 8;
    const __half* ap = (c & 4) ? Alo : Ahi;
    const bool blo = (c & 4);
#pragma unroll
    for (int ii = 0; ii < 4; ii++) {
        int r = r0 + ii * 32;
        uint32_t so = sw128((uint32_t)(r * 128 + c * 16));
        int m = bm + r;
        int mc = (m < M) ? m : (M - 1);
        cp16(abase + so, ap + (size_t)mc * E_DIM + kc, (m < M) ? 16 : 0);
        if (!blo)
            cp16(bbase + so, Bhi + (size_t)(bn + r) * E_DIM + kc, 16);
    }
}

__global__ __launch_bounds__(256, 2)
void gemm_mma(const __half* __restrict__ A0hi, const __half* __restrict__ A0lo,
              const __half* __restrict__ A3hi, const __half* __restrict__ A3lo,
              const __half* __restrict__ Whi,
              const float* b0, const float* b1, const float* b2, const float* b3,
              float* o0, float* o1, float* o2, float* o3,
              float s0, float s1, float s2, float s3,
              int M0, int M3, int mode, int Trows0, int Trows3)
{
    extern __shared__ char smem[];
    const uint32_t sb = smem_u32(smem);

    const int tid = threadIdx.x, wid = tid >> 5, lane = tid & 31;
    const int bm = blockIdx.y * 128, bn = blockIdx.x * 128;
    const int z = blockIdx.z;
    const int M     = (z == 3) ? M3 : M0;
    const int Trows = (z == 3) ? Trows3 : Trows0;
    if (bm >= M) return;
    const __half* Ahi = (z == 3) ? A3hi : A0hi;
    const __half* Alo = (z == 3) ? A3lo : A0lo;
    const __half* wh = Whi + (size_t)z * NE;
    const float* bias = (z == 0) ? b0 : ((z == 1) ? b1 : ((z == 2) ? b2 : b3));
    float* out        = (z == 0) ? o0 : ((z == 1) ? o1 : ((z == 2) ? o2 : o3));
    const float scale = (z == 0) ? s0 : ((z == 1) ? s1 : ((z == 2) ? s2 : s3));

    const int warpM = (wid >> 2) * 64;
    const int warpN = (wid & 3) * 32;
    const int li = lane >> 3, lr = lane & 7;

    float acc[4][4][4];
#pragma unroll
    for (int i = 0; i < 4; i++)
#pragma unroll
        for (int j = 0; j < 4; j++)
#pragma unroll
            for (int k = 0; k < 4; k++) acc[i][j][k] = 0.f;

    const int NK = E_DIM / 32;
    g_load_stage(sb, 0, Ahi, Alo, wh, bm, bn, 0, M, tid);
    cp_commit();
    g_load_stage(sb, 1, Ahi, Alo, wh, bm, bn, 32, M, tid);
    cp_commit();

    int slot = 0, next = 2;
    for (int ks = 0; ks < NK; ks++) {
        if (ks + 1 < NK) cp_wait1(); else cp_wait0();
        __syncthreads();
        if (ks + 2 < NK) {
            g_load_stage(sb, next, Ahi, Alo, wh, bm, bn, (ks + 2) * 32, M, tid);
            cp_commit();
            if (++next == 3) next = 0;
        }

        const uint32_t abase = sb + slot * 32768;
        const uint32_t bbase = abase + 16384;
        if (++slot == 3) slot = 0;
#pragma unroll
        for (int kk = 0; kk < 2; kk++) {
            uint32_t bh[2][4];
            const uint32_t kb2 = (uint32_t)(kk * 32 + (li & 1) * 16);
#pragma unroll
            for (int jn = 0; jn < 2; jn++) {
                uint32_t off = (uint32_t)((warpN + jn * 16 + (li >> 1) * 8 + lr) * 128) + kb2;
                ldsm_x4(bh[jn], bbase + sw128(off));
            }
            const uint32_t ka = (uint32_t)(kk * 32 + (li >> 1) * 16);
#pragma unroll
            for (int i = 0; i < 4; i++) {
                uint32_t ah[4], al[4];
                uint32_t off = (uint32_t)((warpM + i * 16 + (li & 1) * 8 + lr) * 128) + ka;
                ldsm_x4(ah, abase + sw128(off));
                ldsm_x4(al, abase + sw128(off + 64));
#pragma unroll
                for (int j = 0; j < 4; j++) {
                    const uint32_t* Bh = &bh[j >> 1][(j & 1) * 2];
                    mma16816(acc[i][j], ah, Bh);
                    mma16816(acc[i][j], al, Bh);
                }
            }
        }
    }

    // ---- epilogue (float2 stores) ----
    const int g = lane >> 2, tg = lane & 3;
#pragma unroll
    for (int i = 0; i < 4; i++) {
#pragma unroll
        for (int j = 0; j < 4; j++) {
            int n0 = bn + warpN + j * 8 + tg * 2;
            float bx = bias[n0], by = bias[n0 + 1];
#pragma unroll
            for (int half = 0; half < 2; half++) {
                int m = bm + warpM + i * 16 + g + half * 8;
                if (m >= M) continue;
                float2 v;
                v.x = (acc[i][j][half * 2 + 0] + bx) * scale;
                v.y = (acc[i][j][half * 2 + 1] + by) * scale;
                if (mode == 0) {
                    *(float2*)&out[(size_t)m * E_DIM + n0] = v;
                } else {
                    int t = m >> 1, b = m & 1;
                    int h = n0 >> 6, d = n0 & 63;
                    *(float2*)&out[(size_t)((b * 16 + h) * Trows + t) * 64 + d] = v;
                }
            }
        }
    }
}

// ------------- merged pattn (softplus) + TWO 32-row local states ------------
// grid (T_LEN/64, BH): block covers 64 rows = state chunks 2*bx, 2*bx+1.
__global__ __launch_bounds__(256, 2)
void pattn_local()
{
    const int bx = blockIdx.x, bh = blockIdx.y;
    extern __shared__ float sm[];
    float* kps = sm;                   // 64 x 65
    float* pqs = kps + 64 * 65;        // 32 x 65
    float* kvs = pqs + 32 * 65;        // 64 x 64
    float* ps  = kvs + 64 * 64;        // 64 x 32
    const size_t base = (size_t)bh * T_LEN + bx * 64;
    const int tid = threadIdx.x;

    for (int i = tid; i < 64 * 64; i += 256) {
        int s = i >> 6, d = i & 63;
        kps[s * 65 + d] = g_kp[(base + s) * 64 + d];
        kvs[i] = g_kv[(base + s) * 64 + d];
    }
    for (int i = tid; i < PLEN * 64; i += 256) {
        int p = i >> 6, d = i & 63;
        pqs[p * 65 + d] = g_pq[(size_t)bh * PLEN * D_DIM + i];
    }
    __syncthreads();

    {
        const int t  = tid >> 2;
        const int p0 = (tid & 3) * 8;
#pragma unroll
        for (int pp = 0; pp < 8; pp++) {
            int p = p0 + pp;
            float a0 = 0.f, a1 = 0.f, a2 = 0.f, a3 = 0.f;
#pragma unroll
            for (int d = 0; d < 64; d += 4) {
                a0 += kps[t * 65 + d]     * pqs[p * 65 + d];
                a1 += kps[t * 65 + d + 1] * pqs[p * 65 + d + 1];
                a2 += kps[t * 65 + d + 2] * pqs[p * 65 + d + 2];
                a3 += kps[t * 65 + d + 3] * pqs[p * 65 + d + 3];
            }
            float accv = (a0 + a1) + (a2 + a3);
            float zz = BETA * accv;
            float sp = (fmaxf(zz, 0.f) + log1pf(expf(-fabsf(zz)))) * (1.0f / BETA);
            ps[t * 32 + p] = sp;
            g_pattn[(base + t) * PLEN + p] = sp;
        }
    }
    __syncthreads();

    {
        const int d  = tid >> 2;
        const int j0 = (tid & 3) * 8;
        float acc0[8] = {0.f}, acc1[8] = {0.f};
        for (int s = 0; s < 32; s++) {
            float a = kvs[s * 64 + d];
#pragma unroll
            for (int jj = 0; jj < 8; jj++) acc0[jj] += a * ps[s * 32 + j0 + jj];
        }
        for (int s = 32; s < 64; s++) {
            float a = kvs[s * 64 + d];
#pragma unroll
            for (int jj = 0; jj < 8; jj++) acc1[jj] += a * ps[s * 32 + j0 + jj];
        }
        float* o0 = &g_S[((size_t)bh * NSC + 2 * bx)     * 2048];
        float* o1 = &g_S[((size_t)bh * NSC + 2 * bx + 1) * 2048];
#pragma unroll
        for (int jj = 0; jj < 8; jj++) {
            o0[d * 32 + j0 + jj] = acc0[jj];
            o1[d * 32 + j0 + jj] = acc1[jj];
        }
    }
}

// ------------------- exclusive prefix scan over 64 chunks ------------------
__global__ __launch_bounds__(256)
void scan_states()
{
    const int gi = blockIdx.x * 256 + threadIdx.x;   // (bh, e): 32 * 2048
    const int bh = gi >> 11;
    const int e  = gi & 2047;
    float run = 0.f;
    float* p = &g_S[(size_t)bh * NSC * 2048 + e];
    for (int c = 0; c < NSC; c++) {
        float v = p[c * 2048];
        p[c * 2048] = run;
        run += v;
    }
}

// ------------------- fused pass1 + softmax + pass2 (SCH=32, 2 chunks/blk) ---
__global__ __launch_bounds__(256, 2)
void fused_pass()
{
    const int bx = blockIdx.x, bh = blockIdx.y;   // bx covers chunks 2bx, 2bx+1
    extern __shared__ float sm[];
    float* qs  = sm;                 // 64 x 65
    float* kvs = qs  + 64 * 65;      // 64 x 64
    float* ps  = kvs + 64 * 64;      // 64 x 33
    float* ws  = ps  + 64 * 33;      // 64 x 33
    float* ss  = ws  + 64 * 33;      // 2 x 64 x 33   ([cid][d][j])
    float* ssT = ss  + 2 * 64 * 33;  // 2 x 32 x 65   ([cid][j][d])
    const size_t base = (size_t)bh * T_LEN + bx * 64;
    const int tid = threadIdx.x;

    for (int i = tid; i < 64 * 64; i += 256) {
        int s = i >> 6, d = i & 63;
        kvs[i] = g_kv[(base + s) * 64 + d];
        qs[s * 65 + d] = g_q[(base + s) * 64 + d];
    }
    for (int i = tid; i < 64 * 32; i += 256) {
        int s = i >> 5, j = i & 31;
        ps[s * 33 + j] = g_pattn[base * 32 + i];
    }
    for (int i = tid; i < 2 * 64 * 32; i += 256) {
        int ci  = i >> 11;
        int idx = i & 2047;
        int d = idx >> 5, j = idx & 31;
        float v = g_S[((size_t)bh * NSC + 2 * bx + ci) * 2048 + idx];
        ss [ci * (64 * 33) + d * 33 + j] = v;
        ssT[ci * (32 * 65) + j * 65 + d] = v;
    }
    __syncthreads();

    const int cid = tid >> 7;            // chunk within block (0/1)
    const int lt  = (tid >> 2) & 31;     // local row in chunk
    const int sub = tid & 3;
    const int row = cid * 32 + lt;       // row within block (0..63)
    const int tgl = bx * 64 + row;       // global t
    const float inv = 1.0f / (float)(tgl + 1);
    const int smax = lt | 7;             // uniform within warp
    const float* ssb  = ss  + cid * (64 * 33);
    const float* ssTb = ssT + cid * (32 * 65);
    const int srow0 = cid * 32;          // chunk-local s -> block row offset

    // ---------------- pass 1 ----------------
    {
        const int j0  = sub * 8;
        const int dq0 = sub * 16;
        float qreg[16];
#pragma unroll
        for (int d = 0; d < 16; d++) qreg[d] = qs[row * 65 + dq0 + d];

        float r[8];
#pragma unroll
        for (int jj = 0; jj < 8; jj++) r[jj] = 0.f;

        const float* qrow = &qs[row * 65];
#pragma unroll 8
        for (int d = 0; d < 64; d++) {
            float a = qrow[d];
#pragma unroll
            for (int jj = 0; jj < 8; jj++) r[jj] += a * ssb[d * 33 + j0 + jj];
        }
        for (int s = 0; s <= smax; s++) {
            const float* kr = &kvs[(srow0 + s) * 64 + dq0];
            float a0 = 0.f, a1 = 0.f, a2 = 0.f, a3 = 0.f;
#pragma unroll
            for (int d = 0; d < 16; d += 4) {
                a0 += qreg[d]     * kr[d];
                a1 += qreg[d + 1] * kr[d + 1];
                a2 += qreg[d + 2] * kr[d + 2];
                a3 += qreg[d + 3] * kr[d + 3];
            }
            float a = (a0 + a1) + (a2 + a3);
            a += __shfl_xor_sync(0xffffffffu, a, 1);
            a += __shfl_xor_sync(0xffffffffu, a, 2);
            if (s <= lt) {
                const float* pr = &ps[(srow0 + s) * 33 + j0];
#pragma unroll
                for (int jj = 0; jj < 8; jj++) r[jj] += a * pr[jj];
            }
        }
        float mx = -1e30f;
#pragma unroll
        for (int jj = 0; jj < 8; jj++) { r[jj] *= inv; mx = fmaxf(mx, r[jj]); }
        mx = fmaxf(mx, __shfl_xor_sync(0xffffffffu, mx, 1));
        mx = fmaxf(mx, __shfl_xor_sync(0xffffffffu, mx, 2));
        float sum = 0.f;
#pragma unroll
        for (int jj = 0; jj < 8; jj++) { r[jj] = expf(r[jj] - mx); sum += r[jj]; }
        sum += __shfl_xor_sync(0xffffffffu, sum, 1);
        sum += __shfl_xor_sync(0xffffffffu, sum, 2);
        float rs = 1.0f / sum;
#pragma unroll
        for (int jj = 0; jj < 8; jj++) ws[row * 33 + j0 + jj] = r[jj] * rs;
    }
    __syncwarp();

    // ---------------- pass 2 ----------------
    {
        const int d0 = sub * 16;
        const int jw0 = sub * 8;
        float wreg[32];
#pragma unroll
        for (int j = 0; j < 32; j++) wreg[j] = ws[row * 33 + j];

        float r[16];
#pragma unroll
        for (int dd = 0; dd < 16; dd++) r[dd] = 0.f;

#pragma unroll 8
        for (int j = 0; j < 32; j++) {
            float a = wreg[j];
            const float* sr = &ssTb[j * 65 + d0];
#pragma unroll
            for (int dd = 0; dd < 16; dd++) r[dd] += a * sr[dd];
        }
        for (int s = 0; s <= smax; s++) {
            const float* pr = &ps[(srow0 + s) * 33 + jw0];
            float a0 = 0.f, a1 = 0.f;
#pragma unroll
            for (int j = 0; j < 8; j += 2) {
                a0 += wreg[jw0 + j]     * pr[j];
                a1 += wreg[jw0 + j + 1] * pr[j + 1];
            }
            float a = a0 + a1;
            a += __shfl_xor_sync(0xffffffffu, a, 1);
            a += __shfl_xor_sync(0xffffffffu, a, 2);
            if (s <= lt) {
                const float* kr = &kvs[(srow0 + s) * 64 + d0];
#pragma unroll
                for (int dd = 0; dd < 16; dd++) r[dd] += a * kr[dd];
            }
        }
        const int b = bh >> 4, hh = bh & 15;
        const size_t ob = ((size_t)tgl * 2 + b) * 1024 + hh * 64 + d0;
#pragma unroll
        for (int dd = 0; dd < 16; dd++) {
            float v = r[dd] * inv;
            __half h = __float2half_rn(v);
            g_AThi[ob + dd] = h;
            g_ATlo[ob + dd] = __float2half_rn(v - __half2float(h));
        }
    }
}

// ---------------------------------------------------------------------------
extern "C" void kernel_launch(void* const* d_in, const int* in_sizes, int n_in,
                              void* d_out, int out_size)
{
    const float* query  = (const float*)d_in[0];
    const float* pquery = (const float*)d_in[1];
    const float* Wpq = (const float*)d_in[2];
    const float* bpq = (const float*)d_in[3];
    const float* Wq  = (const float*)d_in[4];
    const float* bq  = (const float*)d_in[5];
    const float* Wpc = (const float*)d_in[6];
    const float* bpc = (const float*)d_in[7];
    const float* Wc  = (const float*)d_in[8];
    const float* bc  = (const float*)d_in[9];
    const float* Wo  = (const float*)d_in[10];
    const float* bo  = (const float*)d_in[11];
    float* out = (float*)d_out;

    float *p_pq, *p_q, *p_kp, *p_kv;
    __half *p_Ahi, *p_Alo, *p_PQhi, *p_PQlo, *p_W4h, *p_WOh, *p_AThi, *p_ATlo;
    cudaGetSymbolAddress((void**)&p_pq,   g_pq);
    cudaGetSymbolAddress((void**)&p_q,    g_q);
    cudaGetSymbolAddress((void**)&p_kp,   g_kp);
    cudaGetSymbolAddress((void**)&p_kv,   g_kv);
    cudaGetSymbolAddress((void**)&p_Ahi,  g_Ahi);
    cudaGetSymbolAddress((void**)&p_Alo,  g_Alo);
    cudaGetSymbolAddress((void**)&p_PQhi, g_PQhi);
    cudaGetSymbolAddress((void**)&p_PQlo, g_PQlo);
    cudaGetSymbolAddress((void**)&p_W4h,  g_W4h);
    cudaGetSymbolAddress((void**)&p_WOh,  g_WOh);
    cudaGetSymbolAddress((void**)&p_AThi, g_AThi);
    cudaGetSymbolAddress((void**)&p_ATlo, g_ATlo);

    const int GEMM_SMEM = 3 * 32768;
    const int PL_SMEM = (64 * 65 + 32 * 65 + 64 * 64 + 64 * 32) * 4;
    const int FP_SMEM = (64 * 65 + 64 * 64 + 64 * 33 + 64 * 33 + 2 * 64 * 33 + 2 * 32 * 65) * 4;
    cudaFuncSetAttribute(gemm_mma,    cudaFuncAttributeMaxDynamicSharedMemorySize, GEMM_SMEM);
    cudaFuncSetAttribute(pattn_local, cudaFuncAttributeMaxDynamicSharedMemorySize, PL_SMEM);
    cudaFuncSetAttribute(fused_pass,  cudaFuncAttributeMaxDynamicSharedMemorySize, FP_SMEM);

    // ---- launch 0: ALL conversions ----
    CvtArgs ca;
    int acc = 0, n4;
    n4 = MROWS * E_DIM / 4;
    ca.s[0] = (const float4*)query;  ca.h[0] = (__half2*)p_Ahi;  ca.l[0] = (__half2*)p_Alo;  ca.mode[0] = 0; acc += n4; ca.end[0] = acc;
    n4 = 64 * E_DIM / 4;
    ca.s[1] = (const float4*)pquery; ca.h[1] = (__half2*)p_PQhi; ca.l[1] = (__half2*)p_PQlo; ca.mode[1] = 0; acc += n4; ca.end[1] = acc;
    n4 = NE / 4;
    ca.s[2] = (const float4*)Wq;  ca.h[2] = (__half2*)p_W4h;            ca.l[2] = nullptr; ca.mode[2] = 1; acc += n4; ca.end[2] = acc;
    ca.s[3] = (const float4*)Wpc; ca.h[3] = (__half2*)(p_W4h + NE);     ca.l[3] = nullptr; ca.mode[3] = 1; acc += n4; ca.end[3] = acc;
    ca.s[4] = (const float4*)Wc;  ca.h[4] = (__half2*)(p_W4h + 2 * NE); ca.l[4] = nullptr; ca.mode[4] = 1; acc += n4; ca.end[4] = acc;
    ca.s[5] = (const float4*)Wpq; ca.h[5] = (__half2*)(p_W4h + 3 * NE); ca.l[5] = nullptr; ca.mode[5] = 1; acc += n4; ca.end[5] = acc;
    ca.s[6] = (const float4*)Wo;  ca.h[6] = (__half2*)p_WOh;            ca.l[6] = nullptr; ca.mode[6] = 1; acc += n4; ca.end[6] = acc;
    cvt_all<<<(acc + 255) / 256, 256>>>(ca);

    // ---- launch 1: q/kp/kv/pq projections (z = 0..3) ----
    gemm_mma<<<dim3(8, 32, 4), 256, GEMM_SMEM>>>(
        p_Ahi, p_Alo, p_PQhi, p_PQlo, p_W4h,
        bq, bpc, bc, bpq,
        p_q, p_kp, p_kv, p_pq,
        SCALING, 1.0f, 1.0f, SCALING,
        MROWS, 64, 1, T_LEN, PLEN);

    // ---- launch 2: pattn + two 32-row local states per block ----
    pattn_local<<<dim3(T_LEN / 64, BH), 256, PL_SMEM>>>();

    // ---- launch 3: exclusive scan over 64 chunks ----
    scan_states<<<BH * 2048 / 256, 256>>>();

    // ---- launch 4: fused pass1 + softmax + pass2 ----
    fused_pass<<<dim3(T_LEN / 64, BH), 256, FP_SMEM>>>();

    // ---- launch 5: output projection -> d_out (2-term fp16) ----
    gemm_mma<<<dim3(8, 32, 1), 256, GEMM_SMEM>>>(
        p_AThi, p_ATlo, p_AThi, p_ATlo, p_WOh,
        bo, bo, bo, bo,
        out, out, out, out,
        1.0f, 1.0f, 1.0f, 1.0f,
        MROWS, MROWS, 0, 0, 0);
}

// round 10
// speedup vs baseline: 4.7376x; 1.3439x over previous
#include <cuda_runtime.h>
#include <cuda_fp16.h>
#include <math.h>
#include <stdint.h>

#define T_LEN  2048
#define BSZ    2
#define E_DIM  1024
#define H_NUM  16
#define D_DIM  64
#define PLEN   32
#define BH     32
#define SCH    32               // state chunk
#define NSC    (T_LEN/SCH)      // 64
#define SCALING 0.125f
#define BETA    0.6931471805599453f

#define MROWS  (T_LEN*BSZ)      // 4096
#define NE     (E_DIM*E_DIM)

// ------------------------- scratch -----------------------------------------
__device__ float g_pq   [BH*PLEN*D_DIM];
__device__ float g_q    [BH*T_LEN*D_DIM];
__device__ float g_kp   [BH*T_LEN*D_DIM];
__device__ float g_kv   [BH*T_LEN*D_DIM];
__device__ float g_pattn[BH*T_LEN*PLEN];
__device__ float g_S    [BH*NSC*D_DIM*PLEN];

__device__ __half g_Ah  [MROWS*E_DIM];
__device__ __half g_PQh [64*E_DIM];
__device__ __half g_W4h [4*NE];          // Wq, Wpc, Wc, Wpq
__device__ __half g_WOh [NE];
__device__ __half g_ATh [MROWS*E_DIM];

// ------------------------- helpers -----------------------------------------
__device__ __forceinline__ uint32_t smem_u32(const void* p) {
    uint32_t a;
    asm("{ .reg .u64 t; cvta.to.shared.u64 t, %1; cvt.u32.u64 %0, t; }"
        : "=r"(a) : "l"(p));
    return a;
}
__device__ __forceinline__ uint32_t sw128(uint32_t off) {
    return off ^ ((off >> 3) & 0x70);
}
__device__ __forceinline__ void ldsm_x4(uint32_t* r, uint32_t addr) {
    asm volatile("ldmatrix.sync.aligned.m8n8.x4.shared.b16 {%0,%1,%2,%3}, [%4];"
                 : "=r"(r[0]), "=r"(r[1]), "=r"(r[2]), "=r"(r[3]) : "r"(addr));
}
__device__ __forceinline__ void mma16816(float* c, const uint32_t* a, const uint32_t* b) {
    asm volatile("mma.sync.aligned.m16n8k16.row.col.f32.f16.f16.f32 "
                 "{%0,%1,%2,%3}, {%4,%5,%6,%7}, {%8,%9}, {%0,%1,%2,%3};"
                 : "+f"(c[0]), "+f"(c[1]), "+f"(c[2]), "+f"(c[3])
                 : "r"(a[0]), "r"(a[1]), "r"(a[2]), "r"(a[3]), "r"(b[0]), "r"(b[1]));
}
__device__ __forceinline__ void cp16(uint32_t dst, const void* src, int sz) {
    asm volatile("cp.async.cg.shared.global [%0], [%1], 16, %2;"
                 :: "r"(dst), "l"(src), "r"(sz));
}
__device__ __forceinline__ void cp_commit() {
    asm volatile("cp.async.commit_group;" ::: "memory");
}
__device__ __forceinline__ void cp_wait1() {
    asm volatile("cp.async.wait_group 1;" ::: "memory");
}
__device__ __forceinline__ void cp_wait0() {
    asm volatile("cp.async.wait_group 0;" ::: "memory");
}

// ------------------------- merged fp32 -> fp16 converter -------------------
#define NCVT 7
struct CvtArgs {
    const float4* s[NCVT];
    __half2*      h[NCVT];
    int           end[NCVT];
};

__global__ __launch_bounds__(256)
void cvt_all(CvtArgs A)
{
    int gi = blockIdx.x * 256 + threadIdx.x;
    int seg = 0;
    while (seg < NCVT && gi >= A.end[seg]) seg++;
    if (seg >= NCVT) return;
    int i = gi - (seg ? A.end[seg - 1] : 0);

    float4 v = A.s[seg][i];
    A.h[seg][2 * i]     = __half2(__float2half_rn(v.x), __float2half_rn(v.y));
    A.h[seg][2 * i + 1] = __half2(__float2half_rn(v.z), __float2half_rn(v.w));
}

// ------------------------- pipelined fp16 GEMM ------------------------------
// C = (A @ W^T + bias) * scale, pure fp16 operands, fp32 accum.
// smem row = 128B = 64 fp16 = one k-tile; stage = A(16KB) + B(16KB).
__device__ __forceinline__ void g_load_stage(
    uint32_t sb, int slot,
    const __half* Ah, const __half* Bh,
    int bm, int bn, int kb, int M, int tid)
{
    const uint32_t abase = sb + slot * 32768;
    const uint32_t bbase = abase + 16384;
    const int c  = tid & 7;           // 16B column
    const int r0 = tid >> 3;          // rows 0..31, step 32
    const int kc = kb + c * 8;        // element column (8 fp16 per 16B)
#pragma unroll
    for (int ii = 0; ii < 4; ii++) {
        int r = r0 + ii * 32;
        uint32_t so = sw128((uint32_t)(r * 128 + c * 16));
        int m = bm + r;
        int mc = (m < M) ? m : (M - 1);
        cp16(abase + so, Ah + (size_t)mc * E_DIM + kc, (m < M) ? 16 : 0);
        cp16(bbase + so, Bh + (size_t)(bn + r) * E_DIM + kc, 16);
    }
}

__global__ __launch_bounds__(256, 2)
void gemm_mma(const __half* __restrict__ A0, const __half* __restrict__ A3,
              const __half* __restrict__ W,
              const float* b0, const float* b1, const float* b2, const float* b3,
              float* o0, float* o1, float* o2, float* o3,
              float s0, float s1, float s2, float s3,
              int M0, int M3, int mode, int Trows0, int Trows3)
{
    extern __shared__ char smem[];
    const uint32_t sb = smem_u32(smem);

    const int tid = threadIdx.x, wid = tid >> 5, lane = tid & 31;
    const int bm = blockIdx.y * 128, bn = blockIdx.x * 128;
    const int z = blockIdx.z;
    const int M     = (z == 3) ? M3 : M0;
    const int Trows = (z == 3) ? Trows3 : Trows0;
    if (bm >= M) return;
    const __half* Ah = (z == 3) ? A3 : A0;
    const __half* wh = W + (size_t)z * NE;
    const float* bias = (z == 0) ? b0 : ((z == 1) ? b1 : ((z == 2) ? b2 : b3));
    float* out        = (z == 0) ? o0 : ((z == 1) ? o1 : ((z == 2) ? o2 : o3));
    const float scale = (z == 0) ? s0 : ((z == 1) ? s1 : ((z == 2) ? s2 : s3));

    const int warpM = (wid >> 2) * 64;
    const int warpN = (wid & 3) * 32;
    const int li = lane >> 3, lr = lane & 7;

    float acc[4][4][4];
#pragma unroll
    for (int i = 0; i < 4; i++)
#pragma unroll
        for (int j = 0; j < 4; j++)
#pragma unroll
            for (int k = 0; k < 4; k++) acc[i][j][k] = 0.f;

    const int NK = E_DIM / 64;   // 16 k-iters of 64
    g_load_stage(sb, 0, Ah, wh, bm, bn, 0, M, tid);
    cp_commit();
    g_load_stage(sb, 1, Ah, wh, bm, bn, 64, M, tid);
    cp_commit();

    int slot = 0, next = 2;
    for (int ks = 0; ks < NK; ks++) {
        if (ks + 1 < NK) cp_wait1(); else cp_wait0();
        __syncthreads();
        if (ks + 2 < NK) {
            g_load_stage(sb, next, Ah, wh, bm, bn, (ks + 2) * 64, M, tid);
            cp_commit();
            if (++next == 3) next = 0;
        }

        const uint32_t abase = sb + slot * 32768;
        const uint32_t bbase = abase + 16384;
        if (++slot == 3) slot = 0;
#pragma unroll
        for (int kk = 0; kk < 4; kk++) {
            uint32_t bfr[2][4];
            const uint32_t kb2 = (uint32_t)(kk * 32 + (li & 1) * 16);
#pragma unroll
            for (int jn = 0; jn < 2; jn++) {
                uint32_t off = (uint32_t)((warpN + jn * 16 + (li >> 1) * 8 + lr) * 128) + kb2;
                ldsm_x4(bfr[jn], bbase + sw128(off));
            }
            const uint32_t ka = (uint32_t)(kk * 32 + (li >> 1) * 16);
#pragma unroll
            for (int i = 0; i < 4; i++) {
                uint32_t ah[4];
                uint32_t off = (uint32_t)((warpM + i * 16 + (li & 1) * 8 + lr) * 128) + ka;
                ldsm_x4(ah, abase + sw128(off));
#pragma unroll
                for (int j = 0; j < 4; j++)
                    mma16816(acc[i][j], ah, &bfr[j >> 1][(j & 1) * 2]);
            }
        }
    }

    // ---- epilogue (float2 stores) ----
    const int g = lane >> 2, tg = lane & 3;
#pragma unroll
    for (int i = 0; i < 4; i++) {
#pragma unroll
        for (int j = 0; j < 4; j++) {
            int n0 = bn + warpN + j * 8 + tg * 2;
            float bx = bias[n0], by = bias[n0 + 1];
#pragma unroll
            for (int half = 0; half < 2; half++) {
                int m = bm + warpM + i * 16 + g + half * 8;
                if (m >= M) continue;
                float2 v;
                v.x = (acc[i][j][half * 2 + 0] + bx) * scale;
                v.y = (acc[i][j][half * 2 + 1] + by) * scale;
                if (mode == 0) {
                    *(float2*)&out[(size_t)m * E_DIM + n0] = v;
                } else {
                    int t = m >> 1, b = m & 1;
                    int h = n0 >> 6, d = n0 & 63;
                    *(float2*)&out[(size_t)((b * 16 + h) * Trows + t) * 64 + d] = v;
                }
            }
        }
    }
}

// ------------- merged pattn (softplus) + TWO 32-row local states ------------
__global__ __launch_bounds__(256, 2)
void pattn_local()
{
    const int bx = blockIdx.x, bh = blockIdx.y;
    extern __shared__ float sm[];
    float* kps = sm;                   // 64 x 65
    float* pqs = kps + 64 * 65;        // 32 x 65
    float* kvs = pqs + 32 * 65;        // 64 x 64
    float* ps  = kvs + 64 * 64;        // 64 x 32
    const size_t base = (size_t)bh * T_LEN + bx * 64;
    const int tid = threadIdx.x;

    for (int i = tid; i < 64 * 64; i += 256) {
        int s = i >> 6, d = i & 63;
        kps[s * 65 + d] = g_kp[(base + s) * 64 + d];
        kvs[i] = g_kv[(base + s) * 64 + d];
    }
    for (int i = tid; i < PLEN * 64; i += 256) {
        int p = i >> 6, d = i & 63;
        pqs[p * 65 + d] = g_pq[(size_t)bh * PLEN * D_DIM + i];
    }
    __syncthreads();

    {
        const int t  = tid >> 2;
        const int p0 = (tid & 3) * 8;
#pragma unroll
        for (int pp = 0; pp < 8; pp++) {
            int p = p0 + pp;
            float a0 = 0.f, a1 = 0.f, a2 = 0.f, a3 = 0.f;
#pragma unroll
            for (int d = 0; d < 64; d += 4) {
                a0 += kps[t * 65 + d]     * pqs[p * 65 + d];
                a1 += kps[t * 65 + d + 1] * pqs[p * 65 + d + 1];
                a2 += kps[t * 65 + d + 2] * pqs[p * 65 + d + 2];
                a3 += kps[t * 65 + d + 3] * pqs[p * 65 + d + 3];
            }
            float accv = (a0 + a1) + (a2 + a3);
            float zz = BETA * accv;
            float sp = (fmaxf(zz, 0.f) + log1pf(expf(-fabsf(zz)))) * (1.0f / BETA);
            ps[t * 32 + p] = sp;
            g_pattn[(base + t) * PLEN + p] = sp;
        }
    }
    __syncthreads();

    {
        const int d  = tid >> 2;
        const int j0 = (tid & 3) * 8;
        float acc0[8] = {0.f}, acc1[8] = {0.f};
        for (int s = 0; s < 32; s++) {
            float a = kvs[s * 64 + d];
#pragma unroll
            for (int jj = 0; jj < 8; jj++) acc0[jj] += a * ps[s * 32 + j0 + jj];
        }
        for (int s = 32; s < 64; s++) {
            float a = kvs[s * 64 + d];
#pragma unroll
            for (int jj = 0; jj < 8; jj++) acc1[jj] += a * ps[s * 32 + j0 + jj];
        }
        float* o0 = &g_S[((size_t)bh * NSC + 2 * bx)     * 2048];
        float* o1 = &g_S[((size_t)bh * NSC + 2 * bx + 1) * 2048];
#pragma unroll
        for (int jj = 0; jj < 8; jj++) {
            o0[d * 32 + j0 + jj] = acc0[jj];
            o1[d * 32 + j0 + jj] = acc1[jj];
        }
    }
}

// ------------------- exclusive prefix scan over 64 chunks ------------------
__global__ __launch_bounds__(256)
void scan_states()
{
    const int gi = blockIdx.x * 256 + threadIdx.x;
    const int bh = gi >> 11;
    const int e  = gi & 2047;
    float run = 0.f;
    float* p = &g_S[(size_t)bh * NSC * 2048 + e];
    for (int c = 0; c < NSC; c++) {
        float v = p[c * 2048];
        p[c * 2048] = run;
        run += v;
    }
}

// ------------------- fused pass1 + softmax + pass2 (SCH=32, 2 chunks/blk) ---
__global__ __launch_bounds__(256, 2)
void fused_pass()
{
    const int bx = blockIdx.x, bh = blockIdx.y;
    extern __shared__ float sm[];
    float* qs  = sm;                 // 64 x 65
    float* kvs = qs  + 64 * 65;      // 64 x 64
    float* ps  = kvs + 64 * 64;      // 64 x 33
    float* ws  = ps  + 64 * 33;      // 64 x 33
    float* ss  = ws  + 64 * 33;      // 2 x 64 x 33
    float* ssT = ss  + 2 * 64 * 33;  // 2 x 32 x 65
    const size_t base = (size_t)bh * T_LEN + bx * 64;
    const int tid = threadIdx.x;

    for (int i = tid; i < 64 * 64; i += 256) {
        int s = i >> 6, d = i & 63;
        kvs[i] = g_kv[(base + s) * 64 + d];
        qs[s * 65 + d] = g_q[(base + s) * 64 + d];
    }
    for (int i = tid; i < 64 * 32; i += 256) {
        int s = i >> 5, j = i & 31;
        ps[s * 33 + j] = g_pattn[base * 32 + i];
    }
    for (int i = tid; i < 2 * 64 * 32; i += 256) {
        int ci  = i >> 11;
        int idx = i & 2047;
        int d = idx >> 5, j = idx & 31;
        float v = g_S[((size_t)bh * NSC + 2 * bx + ci) * 2048 + idx];
        ss [ci * (64 * 33) + d * 33 + j] = v;
        ssT[ci * (32 * 65) + j * 65 + d] = v;
    }
    __syncthreads();

    const int cid = tid >> 7;
    const int lt  = (tid >> 2) & 31;
    const int sub = tid & 3;
    const int row = cid * 32 + lt;
    const int tgl = bx * 64 + row;
    const float inv = 1.0f / (float)(tgl + 1);
    const int smax = lt | 7;
    const float* ssb  = ss  + cid * (64 * 33);
    const float* ssTb = ssT + cid * (32 * 65);
    const int srow0 = cid * 32;

    // ---------------- pass 1 ----------------
    {
        const int j0  = sub * 8;
        const int dq0 = sub * 16;
        float qreg[16];
#pragma unroll
        for (int d = 0; d < 16; d++) qreg[d] = qs[row * 65 + dq0 + d];

        float r[8];
#pragma unroll
        for (int jj = 0; jj < 8; jj++) r[jj] = 0.f;

        const float* qrow = &qs[row * 65];
#pragma unroll 8
        for (int d = 0; d < 64; d++) {
            float a = qrow[d];
#pragma unroll
            for (int jj = 0; jj < 8; jj++) r[jj] += a * ssb[d * 33 + j0 + jj];
        }
        for (int s = 0; s <= smax; s++) {
            const float* kr = &kvs[(srow0 + s) * 64 + dq0];
            float a0 = 0.f, a1 = 0.f, a2 = 0.f, a3 = 0.f;
#pragma unroll
            for (int d = 0; d < 16; d += 4) {
                a0 += qreg[d]     * kr[d];
                a1 += qreg[d + 1] * kr[d + 1];
                a2 += qreg[d + 2] * kr[d + 2];
                a3 += qreg[d + 3] * kr[d + 3];
            }
            float a = (a0 + a1) + (a2 + a3);
            a += __shfl_xor_sync(0xffffffffu, a, 1);
            a += __shfl_xor_sync(0xffffffffu, a, 2);
            if (s <= lt) {
                const float* pr = &ps[(srow0 + s) * 33 + j0];
#pragma unroll
                for (int jj = 0; jj < 8; jj++) r[jj] += a * pr[jj];
            }
        }
        float mx = -1e30f;
#pragma unroll
        for (int jj = 0; jj < 8; jj++) { r[jj] *= inv; mx = fmaxf(mx, r[jj]); }
        mx = fmaxf(mx, __shfl_xor_sync(0xffffffffu, mx, 1));
        mx = fmaxf(mx, __shfl_xor_sync(0xffffffffu, mx, 2));
        float sum = 0.f;
#pragma unroll
        for (int jj = 0; jj < 8; jj++) { r[jj] = expf(r[jj] - mx); sum += r[jj]; }
        sum += __shfl_xor_sync(0xffffffffu, sum, 1);
        sum += __shfl_xor_sync(0xffffffffu, sum, 2);
        float rs = 1.0f / sum;
#pragma unroll
        for (int jj = 0; jj < 8; jj++) ws[row * 33 + j0 + jj] = r[jj] * rs;
    }
    __syncwarp();

    // ---------------- pass 2 ----------------
    {
        const int d0 = sub * 16;
        const int jw0 = sub * 8;
        float wreg[32];
#pragma unroll
        for (int j = 0; j < 32; j++) wreg[j] = ws[row * 33 + j];

        float r[16];
#pragma unroll
        for (int dd = 0; dd < 16; dd++) r[dd] = 0.f;

#pragma unroll 8
        for (int j = 0; j < 32; j++) {
            float a = wreg[j];
            const float* sr = &ssTb[j * 65 + d0];
#pragma unroll
            for (int dd = 0; dd < 16; dd++) r[dd] += a * sr[dd];
        }
        for (int s = 0; s <= smax; s++) {
            const float* pr = &ps[(srow0 + s) * 33 + jw0];
            float a0 = 0.f, a1 = 0.f;
#pragma unroll
            for (int j = 0; j < 8; j += 2) {
                a0 += wreg[jw0 + j]     * pr[j];
                a1 += wreg[jw0 + j + 1] * pr[j + 1];
            }
            float a = a0 + a1;
            a += __shfl_xor_sync(0xffffffffu, a, 1);
            a += __shfl_xor_sync(0xffffffffu, a, 2);
            if (s <= lt) {
                const float* kr = &kvs[(srow0 + s) * 64 + d0];
#pragma unroll
                for (int dd = 0; dd < 16; dd++) r[dd] += a * kr[dd];
            }
        }
        const int b = bh >> 4, hh = bh & 15;
        const size_t ob = ((size_t)tgl * 2 + b) * 1024 + hh * 64 + d0;
#pragma unroll
        for (int dd = 0; dd < 16; dd++)
            g_ATh[ob + dd] = __float2half_rn(r[dd] * inv);
    }
}

// ---------------------------------------------------------------------------
extern "C" void kernel_launch(void* const* d_in, const int* in_sizes, int n_in,
                              void* d_out, int out_size)
{
    const float* query  = (const float*)d_in[0];
    const float* pquery = (const float*)d_in[1];
    const float* Wpq = (const float*)d_in[2];
    const float* bpq = (const float*)d_in[3];
    const float* Wq  = (const float*)d_in[4];
    const float* bq  = (const float*)d_in[5];
    const float* Wpc = (const float*)d_in[6];
    const float* bpc = (const float*)d_in[7];
    const float* Wc  = (const float*)d_in[8];
    const float* bc  = (const float*)d_in[9];
    const float* Wo  = (const float*)d_in[10];
    const float* bo  = (const float*)d_in[11];
    float* out = (float*)d_out;

    float *p_pq, *p_q, *p_kp, *p_kv;
    __half *p_Ah, *p_PQh, *p_W4h, *p_WOh, *p_ATh;
    cudaGetSymbolAddress((void**)&p_pq,  g_pq);
    cudaGetSymbolAddress((void**)&p_q,   g_q);
    cudaGetSymbolAddress((void**)&p_kp,  g_kp);
    cudaGetSymbolAddress((void**)&p_kv,  g_kv);
    cudaGetSymbolAddress((void**)&p_Ah,  g_Ah);
    cudaGetSymbolAddress((void**)&p_PQh, g_PQh);
    cudaGetSymbolAddress((void**)&p_W4h, g_W4h);
    cudaGetSymbolAddress((void**)&p_WOh, g_WOh);
    cudaGetSymbolAddress((void**)&p_ATh, g_ATh);

    const int GEMM_SMEM = 3 * 32768;
    const int PL_SMEM = (64 * 65 + 32 * 65 + 64 * 64 + 64 * 32) * 4;
    const int FP_SMEM = (64 * 65 + 64 * 64 + 64 * 33 + 64 * 33 + 2 * 64 * 33 + 2 * 32 * 65) * 4;
    cudaFuncSetAttribute(gemm_mma,    cudaFuncAttributeMaxDynamicSharedMemorySize, GEMM_SMEM);
    cudaFuncSetAttribute(pattn_local, cudaFuncAttributeMaxDynamicSharedMemorySize, PL_SMEM);
    cudaFuncSetAttribute(fused_pass,  cudaFuncAttributeMaxDynamicSharedMemorySize, FP_SMEM);

    // ---- launch 0: ALL conversions (hi-plane only) ----
    CvtArgs ca;
    int acc = 0, n4;
    n4 = MROWS * E_DIM / 4;
    ca.s[0] = (const float4*)query;  ca.h[0] = (__half2*)p_Ah;  acc += n4; ca.end[0] = acc;
    n4 = 64 * E_DIM / 4;
    ca.s[1] = (const float4*)pquery; ca.h[1] = (__half2*)p_PQh; acc += n4; ca.end[1] = acc;
    n4 = NE / 4;
    ca.s[2] = (const float4*)Wq;  ca.h[2] = (__half2*)p_W4h;            acc += n4; ca.end[2] = acc;
    ca.s[3] = (const float4*)Wpc; ca.h[3] = (__half2*)(p_W4h + NE);     acc += n4; ca.end[3] = acc;
    ca.s[4] = (const float4*)Wc;  ca.h[4] = (__half2*)(p_W4h + 2 * NE); acc += n4; ca.end[4] = acc;
    ca.s[5] = (const float4*)Wpq; ca.h[5] = (__half2*)(p_W4h + 3 * NE); acc += n4; ca.end[5] = acc;
    ca.s[6] = (const float4*)Wo;  ca.h[6] = (__half2*)p_WOh;            acc += n4; ca.end[6] = acc;
    cvt_all<<<(acc + 255) / 256, 256>>>(ca);

    // ---- launch 1: q/kp/kv/pq projections (z = 0..3) ----
    gemm_mma<<<dim3(8, 32, 4), 256, GEMM_SMEM>>>(
        p_Ah, p_PQh, p_W4h,
        bq, bpc, bc, bpq,
        p_q, p_kp, p_kv, p_pq,
        SCALING, 1.0f, 1.0f, SCALING,
        MROWS, 64, 1, T_LEN, PLEN);

    // ---- launch 2: pattn + two 32-row local states per block ----
    pattn_local<<<dim3(T_LEN / 64, BH), 256, PL_SMEM>>>();

    // ---- launch 3: exclusive scan over 64 chunks ----
    scan_states<<<BH * 2048 / 256, 256>>>();

    // ---- launch 4: fused pass1 + softmax + pass2 ----
    fused_pass<<<dim3(T_LEN / 64, BH), 256, FP_SMEM>>>();

    // ---- launch 5: output projection -> d_out ----
    gemm_mma<<<dim3(8, 32, 1), 256, GEMM_SMEM>>>(
        p_ATh, p_ATh, p_WOh,
        bo, bo, bo, bo,
        out, out, out, out,
        1.0f, 1.0f, 1.0f, 1.0f,
        MROWS, MROWS, 0, 0, 0);
}